// round 11
// baseline (speedup 1.0000x reference)
#include <cuda_runtime.h>
#include <math.h>

#define Nn 1024
#define C1 384
#define C2 128
#define Hh 12
#define FEATD 2112
#define NCHd 384
#define PW 1152

// ---------------- scratch (device globals; no runtime allocation) ----------------
static __device__ float g_P[Nn * PW];               // projections (1024x1152)
static __device__ float g_qpt[Nn * Hh * 12];        // global q points (n,h,p*3+i)
static __device__ float g_kpt[Nn * Hh * 12];
static __device__ float g_vpt[Nn * Hh * 24];
static __device__ float g_qn[Nn * Hh];              // |q_pts|^2 per (n,h)
static __device__ float g_kn[Nn * Hh];
static __device__ float g_bufA[(size_t)Hh * Nn * Nn]; // (h,q,k): cheap logits, then attn
static __device__ float g_out6[Nn * Hh * 40];       // [v_scalar(16) | point(24)] per (q,h)
static __device__ float g_feat[Nn * FEATD];         // assembled feature rows

// packed fp32x2 FMA: d0 += a0*b0 ; d1 += a1*b1
__device__ __forceinline__ void ffma2(float& d0, float& d1, float a0, float a1,
                                      float b0, float b1) {
    asm("{\n\t"
        ".reg .b64 ra, rb, rc;\n\t"
        "mov.b64 ra, {%2, %3};\n\t"
        "mov.b64 rb, {%4, %5};\n\t"
        "mov.b64 rc, {%0, %1};\n\t"
        "fma.rn.f32x2 rc, ra, rb, rc;\n\t"
        "mov.b64 {%0, %1}, rc;\n\t"
        "}"
        : "+f"(d0), "+f"(d1)
        : "f"(a0), "f"(a1), "f"(b0), "f"(b1));
}

// source of the assembled projection matrix column `col`, row `c`
__device__ __forceinline__ float wsrc(const float* __restrict__ wqp, const float* __restrict__ wkp,
                                      const float* __restrict__ wvp, const float* __restrict__ wqs,
                                      const float* __restrict__ wks, const float* __restrict__ wvs,
                                      int c, int col) {
    if (col < 144)  return wqp[c * 144 + col];
    if (col < 288)  return wkp[c * 144 + col - 144];
    if (col < 576)  return wvp[c * 288 + col - 288];
    if (col < 768)  return wqs[c * 192 + col - 576];
    if (col < 960)  return wks[c * 192 + col - 768];
    return wvs[c * 192 + col - 960];
}

// ---------------- K1: projection GEMM 1024x1152x384 (weights assembled on the fly) ----------------
__global__ __launch_bounds__(256) void k_proj(const float* __restrict__ A,
                                              const float* __restrict__ wqp, const float* __restrict__ wkp,
                                              const float* __restrict__ wvp, const float* __restrict__ wqs,
                                              const float* __restrict__ wks, const float* __restrict__ wvs,
                                              const float* __restrict__ bqp, const float* __restrict__ bkp,
                                              const float* __restrict__ bvp) {
    __shared__ __align__(16) float As[16 * 64];
    __shared__ __align__(16) float Bs[16 * 64];
    int n0 = blockIdx.x * 64, m0 = blockIdx.y * 64;
    int t = threadIdx.x;
    int tx = t & 15, ty = t >> 4;
    float acc[4][4] = {};
    for (int kc = 0; kc < C1; kc += 16) {
#pragma unroll
        for (int r = 0; r < 4; r++) {
            int idx = t + r * 256;
            As[(idx & 15) * 64 + (idx >> 4)] = A[(m0 + (idx >> 4)) * C1 + kc + (idx & 15)];
            Bs[(idx >> 6) * 64 + (idx & 63)] =
                wsrc(wqp, wkp, wvp, wqs, wks, wvs, kc + (idx >> 6), n0 + (idx & 63));
        }
        __syncthreads();
#pragma unroll
        for (int kk = 0; kk < 16; kk++) {
            float4 a4 = *(const float4*)(As + kk * 64 + ty * 4);
            float4 b4 = *(const float4*)(Bs + kk * 64 + tx * 4);
            ffma2(acc[0][0], acc[0][1], a4.x, a4.x, b4.x, b4.y);
            ffma2(acc[0][2], acc[0][3], a4.x, a4.x, b4.z, b4.w);
            ffma2(acc[1][0], acc[1][1], a4.y, a4.y, b4.x, b4.y);
            ffma2(acc[1][2], acc[1][3], a4.y, a4.y, b4.z, b4.w);
            ffma2(acc[2][0], acc[2][1], a4.z, a4.z, b4.x, b4.y);
            ffma2(acc[2][2], acc[2][3], a4.z, a4.z, b4.z, b4.w);
            ffma2(acc[3][0], acc[3][1], a4.w, a4.w, b4.x, b4.y);
            ffma2(acc[3][2], acc[3][3], a4.w, a4.w, b4.z, b4.w);
        }
        __syncthreads();
    }
#pragma unroll
    for (int i = 0; i < 4; i++) {
        int m = m0 + ty * 4 + i;
#pragma unroll
        for (int j = 0; j < 4; j++) {
            int n = n0 + tx * 4 + j;
            float b = 0.f;
            if (n < 144)      b = bqp[n];
            else if (n < 288) b = bkp[n - 144];
            else if (n < 576) b = bvp[n - 288];
            float s = (n >= 576 && n < 768) ? 0.25f : 1.f;   // q_scalar * sqrt(1/16)
            g_P[m * PW + n] = acc[i][j] * s + b;
        }
    }
}

// ---------------- K2: rigid transform + point norms ----------------
__global__ void k_rotate(const float* __restrict__ rot, const float* __restrict__ trans) {
    int n = blockIdx.x;
    int t = threadIdx.x;
    __shared__ float R[9], T[3];
    if (t < 9) R[t] = rot[n * 9 + t];
    if (t < 3) T[t] = trans[n * 3 + t];
    __syncthreads();
    if (t < 192) {
        float l0, l1, l2;
        float* dst;
        if (t < 48) {
            int h = t >> 2, p = t & 3;
            const float* src = &g_P[n * PW + h * 12];
            l0 = src[p]; l1 = src[4 + p]; l2 = src[8 + p];
            dst = &g_qpt[(n * 12 + h) * 12 + p * 3];
        } else if (t < 96) {
            int u = t - 48; int h = u >> 2, p = u & 3;
            const float* src = &g_P[n * PW + 144 + h * 12];
            l0 = src[p]; l1 = src[4 + p]; l2 = src[8 + p];
            dst = &g_kpt[(n * 12 + h) * 12 + p * 3];
        } else {
            int u = t - 96; int h = u >> 3, p = u & 7;
            const float* src = &g_P[n * PW + 288 + h * 24];
            l0 = src[p]; l1 = src[8 + p]; l2 = src[16 + p];
            dst = &g_vpt[(n * 12 + h) * 24 + p * 3];
        }
        dst[0] = R[0] * l0 + R[1] * l1 + R[2] * l2 + T[0];
        dst[1] = R[3] * l0 + R[4] * l1 + R[5] * l2 + T[1];
        dst[2] = R[6] * l0 + R[7] * l1 + R[8] * l2 + T[2];
    }
    __syncthreads();
    if (t < 24) {
        int h = t % 12;
        const float* p = (t < 12) ? &g_qpt[(n * 12 + h) * 12] : &g_kpt[(n * 12 + h) * 12];
        float s = 0.f;
#pragma unroll
        for (int d = 0; d < 12; d++) s += p[d] * p[d];
        if (t < 12) g_qn[n * 12 + h] = s;
        else        g_kn[n * 12 + h] = s;
    }
}

// ---------------- K3: cheap logits (scalar QK + point + b2d) -> (h,q,k), 128x64 tiles ----------------
__global__ __launch_bounds__(256) void k_cheap(const float* __restrict__ b2d,
                                               const float* __restrict__ rawpw) {
    int k0 = blockIdx.x * 64, q0 = blockIdx.y * 128, h = blockIdx.z;
    __shared__ __align__(16) float qf[28 * 128];   // [c][r]
    __shared__ __align__(16) float kf[28 * 64];
    __shared__ float qn_[128], kn_[64];
    int t = threadIdx.x;
    float x = rawpw[h];
    float sp = (x > 20.f) ? x : log1pf(expf(x));
    float pw = sqrtf(1.f / 18.f) * sp;             // point_var = 4*9/2 = 18
    for (int u = t; u < 1024; u += 256) {
        int r = u >> 3, g = u & 7;
        if (g < 4) {
            float4 v = *(const float4*)(&g_P[(size_t)(q0 + r) * PW + 576 + h * 16 + g * 4]);
            qf[(g * 4 + 0) * 128 + r] = v.x; qf[(g * 4 + 1) * 128 + r] = v.y;
            qf[(g * 4 + 2) * 128 + r] = v.z; qf[(g * 4 + 3) * 128 + r] = v.w;
        } else if (g < 7) {
            int pc = 16 + (g - 4) * 4;
            float4 v = *(const float4*)(&g_qpt[(((size_t)(q0 + r)) * 12 + h) * 12 + (g - 4) * 4]);
            qf[(pc + 0) * 128 + r] = v.x; qf[(pc + 1) * 128 + r] = v.y;
            qf[(pc + 2) * 128 + r] = v.z; qf[(pc + 3) * 128 + r] = v.w;
        }
    }
    for (int u = t; u < 512; u += 256) {
        int r = u >> 3, g = u & 7;
        if (g < 4) {
            float4 w = *(const float4*)(&g_P[(size_t)(k0 + r) * PW + 768 + h * 16 + g * 4]);
            kf[(g * 4 + 0) * 64 + r] = w.x; kf[(g * 4 + 1) * 64 + r] = w.y;
            kf[(g * 4 + 2) * 64 + r] = w.z; kf[(g * 4 + 3) * 64 + r] = w.w;
        } else if (g < 7) {
            int pc = 16 + (g - 4) * 4;
            float4 w = *(const float4*)(&g_kpt[(((size_t)(k0 + r)) * 12 + h) * 12 + (g - 4) * 4]);
            kf[(pc + 0) * 64 + r] = pw * w.x; kf[(pc + 1) * 64 + r] = pw * w.y;
            kf[(pc + 2) * 64 + r] = pw * w.z; kf[(pc + 3) * 64 + r] = pw * w.w;
        }
    }
    if (t < 128)           qn_[t] = 0.5f * pw * g_qn[(q0 + t) * 12 + h];
    else if (t < 192)      kn_[t - 128] = 0.5f * pw * g_kn[(k0 + t - 128) * 12 + h];
    __syncthreads();
    int tx = t & 15, ty = t >> 4;
    float acc[8][4] = {};
#pragma unroll
    for (int c = 0; c < 28; c++) {
        float4 aA = *(const float4*)(qf + c * 128 + ty * 8);
        float4 aB = *(const float4*)(qf + c * 128 + ty * 8 + 4);
        float4 b4 = *(const float4*)(kf + c * 64 + tx * 4);
        ffma2(acc[0][0], acc[0][1], aA.x, aA.x, b4.x, b4.y);
        ffma2(acc[0][2], acc[0][3], aA.x, aA.x, b4.z, b4.w);
        ffma2(acc[1][0], acc[1][1], aA.y, aA.y, b4.x, b4.y);
        ffma2(acc[1][2], acc[1][3], aA.y, aA.y, b4.z, b4.w);
        ffma2(acc[2][0], acc[2][1], aA.z, aA.z, b4.x, b4.y);
        ffma2(acc[2][2], acc[2][3], aA.z, aA.z, b4.z, b4.w);
        ffma2(acc[3][0], acc[3][1], aA.w, aA.w, b4.x, b4.y);
        ffma2(acc[3][2], acc[3][3], aA.w, aA.w, b4.z, b4.w);
        ffma2(acc[4][0], acc[4][1], aB.x, aB.x, b4.x, b4.y);
        ffma2(acc[4][2], acc[4][3], aB.x, aB.x, b4.z, b4.w);
        ffma2(acc[5][0], acc[5][1], aB.y, aB.y, b4.x, b4.y);
        ffma2(acc[5][2], acc[5][3], aB.y, aB.y, b4.z, b4.w);
        ffma2(acc[6][0], acc[6][1], aB.z, aB.z, b4.x, b4.y);
        ffma2(acc[6][2], acc[6][3], aB.z, aB.z, b4.z, b4.w);
        ffma2(acc[7][0], acc[7][1], aB.w, aB.w, b4.x, b4.y);
        ffma2(acc[7][2], acc[7][3], aB.w, aB.w, b4.z, b4.w);
    }
    float bb = b2d[h];
#pragma unroll
    for (int i = 0; i < 8; i++) {
        int q = q0 + ty * 8 + i;
#pragma unroll
        for (int j = 0; j < 4; j++) {
            int k = k0 + tx * 4 + j;
            g_bufA[((size_t)h << 20) + (size_t)q * 1024 + k] =
                acc[i][j] - qn_[ty * 8 + i] - kn_[tx * 4 + j] + bb;
        }
    }
}

// ---------------- K4: fused inputs_2d projection + cheap-add + mask + softmax ----------------
// one block per q; 512 threads; thread t owns k in {t, t+512}; attn -> g_bufA (h,q,k)
// inputs_2d rows streamed directly from global (no smem staging) to keep occupancy high.
__global__ __launch_bounds__(512, 2) void k_logits(const float* __restrict__ in2d,
                                                   const float* __restrict__ w2d,
                                                   const float* __restrict__ mask) {
    __shared__ __align__(16) float ws[1536];   // full w2d (128 x 12)
    __shared__ float red[192];                 // 16 warps x 12
    int q = blockIdx.x, t = threadIdx.x;
    for (int i = t; i < 1536; i += 512) ws[i] = w2d[i];
    __syncthreads();
    float acc[2][12];
#pragma unroll
    for (int s = 0; s < 2; s++)
#pragma unroll
        for (int h = 0; h < 12; h++) acc[s][h] = 0.f;
    const float* r0 = in2d + (size_t)q * 131072 + (size_t)t * 128;
    const float* r1 = r0 + 512 * 128;
#pragma unroll 4
    for (int c4 = 0; c4 < 32; c4++) {
        float4 a0 = *(const float4*)(r0 + c4 * 4);
        float4 a1 = *(const float4*)(r1 + c4 * 4);
#pragma unroll
        for (int cc = 0; cc < 4; cc++) {
            const float* wb = ws + (c4 * 4 + cc) * 12;
            float4 b0 = *(const float4*)(wb);
            float4 b1 = *(const float4*)(wb + 4);
            float4 b2 = *(const float4*)(wb + 8);
            float av0 = (cc == 0) ? a0.x : (cc == 1) ? a0.y : (cc == 2) ? a0.z : a0.w;
            float av1 = (cc == 0) ? a1.x : (cc == 1) ? a1.y : (cc == 2) ? a1.z : a1.w;
            ffma2(acc[0][0],  acc[0][1],  av0, av0, b0.x, b0.y);
            ffma2(acc[0][2],  acc[0][3],  av0, av0, b0.z, b0.w);
            ffma2(acc[0][4],  acc[0][5],  av0, av0, b1.x, b1.y);
            ffma2(acc[0][6],  acc[0][7],  av0, av0, b1.z, b1.w);
            ffma2(acc[0][8],  acc[0][9],  av0, av0, b2.x, b2.y);
            ffma2(acc[0][10], acc[0][11], av0, av0, b2.z, b2.w);
            ffma2(acc[1][0],  acc[1][1],  av1, av1, b0.x, b0.y);
            ffma2(acc[1][2],  acc[1][3],  av1, av1, b0.z, b0.w);
            ffma2(acc[1][4],  acc[1][5],  av1, av1, b1.x, b1.y);
            ffma2(acc[1][6],  acc[1][7],  av1, av1, b1.z, b1.w);
            ffma2(acc[1][8],  acc[1][9],  av1, av1, b2.x, b2.y);
            ffma2(acc[1][10], acc[1][11], av1, av1, b2.z, b2.w);
        }
    }
    // ---- epilogue: add cheap, mask, scale ----
    const float scale = 0.57735026918962576f;
    float mq = mask[q];
    float pen0 = -1e5f * (1.f - mq * mask[t]);
    float pen1 = -1e5f * (1.f - mq * mask[t + 512]);
#pragma unroll
    for (int h = 0; h < 12; h++) {
        size_t off = ((size_t)h << 20) + ((size_t)q << 10) + t;
        acc[0][h] = (acc[0][h] + g_bufA[off] + pen0) * scale;
        acc[1][h] = (acc[1][h] + g_bufA[off + 512] + pen1) * scale;
    }
    // ---- softmax over k (block-wide per h) ----
    int w = t >> 5, lane = t & 31;
#pragma unroll
    for (int h = 0; h < 12; h++) {
        float m = fmaxf(acc[0][h], acc[1][h]);
#pragma unroll
        for (int s = 16; s; s >>= 1) m = fmaxf(m, __shfl_xor_sync(0xffffffffu, m, s));
        if (lane == 0) red[w * 12 + h] = m;
    }
    __syncthreads();
    float hm[12];
#pragma unroll
    for (int h = 0; h < 12; h++) {
        float m = red[h];
#pragma unroll
        for (int w2 = 1; w2 < 16; w2++) m = fmaxf(m, red[w2 * 12 + h]);
        hm[h] = m;
    }
    __syncthreads();
#pragma unroll
    for (int h = 0; h < 12; h++) {
        acc[0][h] = __expf(acc[0][h] - hm[h]);
        acc[1][h] = __expf(acc[1][h] - hm[h]);
        float s0 = acc[0][h] + acc[1][h];
#pragma unroll
        for (int s = 16; s; s >>= 1) s0 += __shfl_xor_sync(0xffffffffu, s0, s);
        if (lane == 0) red[w * 12 + h] = s0;
    }
    __syncthreads();
#pragma unroll
    for (int h = 0; h < 12; h++) {
        float tot = red[h];
#pragma unroll
        for (int w2 = 1; w2 < 16; w2++) tot += red[w2 * 12 + h];
        float inv = 1.f / tot;
        size_t off = ((size_t)h << 20) + ((size_t)q << 10) + t;
        g_bufA[off]       = acc[0][h] * inv;
        g_bufA[off + 512] = acc[1][h] * inv;
    }
}

// ---------------- K5: AV (scalar + point values), per-head GEMM ----------------
__global__ __launch_bounds__(256) void k_av() {
    __shared__ __align__(16) float As[64 * 64];   // [kk][r]
    __shared__ float Bs[64 * 48];
    int h = blockIdx.y;
    int q0 = blockIdx.x * 64;
    int t = threadIdx.x;
    int tx = t & 15, ty = t >> 4;
    float acc[4][3] = {};
    for (int k0 = 0; k0 < 1024; k0 += 64) {
        const float* ab = g_bufA + ((size_t)h << 20) + (size_t)q0 * 1024 + k0;
        for (int idx = t; idx < 1024; idx += 256) {
            int r = idx >> 4, c4 = (idx & 15) * 4;
            float4 v = *(const float4*)(ab + (size_t)r * 1024 + c4);
            As[(c4 + 0) * 64 + r] = v.x; As[(c4 + 1) * 64 + r] = v.y;
            As[(c4 + 2) * 64 + r] = v.z; As[(c4 + 3) * 64 + r] = v.w;
        }
        for (int idx = t; idx < 64 * 48; idx += 256) {
            int kk = idx / 48, col = idx - kk * 48;
            int k = k0 + kk;
            float v = 0.f;
            if (col < 16)       v = g_P[(size_t)k * 1152 + 960 + h * 16 + col];
            else if (col < 40)  v = g_vpt[((size_t)k * 12 + h) * 24 + (col - 16)];
            Bs[kk * 48 + col] = v;
        }
        __syncthreads();
#pragma unroll 8
        for (int kk = 0; kk < 64; kk++) {
            float4 a4 = *(const float4*)(As + kk * 64 + ty * 4);
            float b0 = Bs[kk * 48 + tx * 3 + 0];
            float b1 = Bs[kk * 48 + tx * 3 + 1];
            float b2 = Bs[kk * 48 + tx * 3 + 2];
            ffma2(acc[0][0], acc[1][0], a4.x, a4.y, b0, b0);
            ffma2(acc[2][0], acc[3][0], a4.z, a4.w, b0, b0);
            ffma2(acc[0][1], acc[1][1], a4.x, a4.y, b1, b1);
            ffma2(acc[2][1], acc[3][1], a4.z, a4.w, b1, b1);
            ffma2(acc[0][2], acc[1][2], a4.x, a4.y, b2, b2);
            ffma2(acc[2][2], acc[3][2], a4.z, a4.w, b2, b2);
        }
        __syncthreads();
    }
#pragma unroll
    for (int i = 0; i < 4; i++) {
        int q = q0 + ty * 4 + i;
#pragma unroll
        for (int j = 0; j < 3; j++) {
            int col = tx * 3 + j;
            if (col < 40) g_out6[((size_t)q * 12 + h) * 40 + col] = acc[i][j];
        }
    }
}

// ---------------- K6: res_2d per q (second in2d pass) ----------------
// 256 threads = 64 c-pairs x 4 k-slices; dynamic smem 12288 floats (attn planes)
__global__ __launch_bounds__(256) void k_final(const float* __restrict__ in2d) {
    extern __shared__ float sa[];   // [h][1024]
    int q = blockIdx.x;
    int t = threadIdx.x;
#pragma unroll
    for (int h = 0; h < 12; h++) {
        float4 v = *(const float4*)(g_bufA + ((size_t)h << 20) + ((size_t)q << 10) + t * 4);
        *(float4*)(sa + h * 1024 + t * 4) = v;
    }
    __syncthreads();
    int cp = t & 63, ks = t >> 6;
    float aX[12], aY[12];
#pragma unroll
    for (int u = 0; u < 12; u++) { aX[u] = 0.f; aY[u] = 0.f; }
    const float* base = in2d + (size_t)q * 131072 + cp * 2;
    int kbase = ks * 256;
    for (int kt = 0; kt < 64; kt++) {
        int k0 = kbase + kt * 4;
        float2 v0 = *(const float2*)(base + (size_t)(k0 + 0) * 128);
        float2 v1 = *(const float2*)(base + (size_t)(k0 + 1) * 128);
        float2 v2 = *(const float2*)(base + (size_t)(k0 + 2) * 128);
        float2 v3 = *(const float2*)(base + (size_t)(k0 + 3) * 128);
#pragma unroll
        for (int u = 0; u < 6; u++) {
            float4 a0 = *(const float4*)(sa + (2 * u) * 1024 + k0);
            float4 a1 = *(const float4*)(sa + (2 * u + 1) * 1024 + k0);
            ffma2(aX[2 * u], aX[2 * u + 1], a0.x, a1.x, v0.x, v0.x);
            ffma2(aY[2 * u], aY[2 * u + 1], a0.x, a1.x, v0.y, v0.y);
            ffma2(aX[2 * u], aX[2 * u + 1], a0.y, a1.y, v1.x, v1.x);
            ffma2(aY[2 * u], aY[2 * u + 1], a0.y, a1.y, v1.y, v1.y);
            ffma2(aX[2 * u], aX[2 * u + 1], a0.z, a1.z, v2.x, v2.x);
            ffma2(aY[2 * u], aY[2 * u + 1], a0.z, a1.z, v2.y, v2.y);
            ffma2(aX[2 * u], aX[2 * u + 1], a0.w, a1.w, v3.x, v3.x);
            ffma2(aY[2 * u], aY[2 * u + 1], a0.w, a1.w, v3.y, v3.y);
        }
    }
    __syncthreads();   // everyone done reading attn from sa
    if (ks != 0) {
        float* d = sa + (size_t)((ks - 1) * 64 + cp) * 24;
#pragma unroll
        for (int u = 0; u < 12; u++) { d[u] = aX[u]; d[12 + u] = aY[u]; }
    }
    __syncthreads();
    if (ks == 0) {
#pragma unroll
        for (int s = 0; s < 3; s++) {
            const float* d = sa + (size_t)(s * 64 + cp) * 24;
#pragma unroll
            for (int u = 0; u < 12; u++) { aX[u] += d[u]; aY[u] += d[12 + u]; }
        }
        float* f = g_feat + (size_t)q * 2112 + 576;
#pragma unroll
        for (int hh = 0; hh < 12; hh++) {
            f[hh * 128 + 2 * cp]     = aX[hh];
            f[hh * 128 + 2 * cp + 1] = aY[hh];
        }
    }
}

// ---------------- K7: inverse rigid, norms, feature assembly ----------------
__global__ void k_post(const float* __restrict__ rot, const float* __restrict__ trans) {
    int q = blockIdx.x;
    int t = threadIdx.x;   // 288
    float* f = g_feat + (size_t)q * 2112;
    const float* o6 = g_out6 + (size_t)q * 12 * 40;
    if (t < 96) {
        int h = t >> 3, p = t & 7;
        const float* g = o6 + h * 40 + 16 + p * 3;
        float g0 = g[0] - trans[q * 3 + 0];
        float g1 = g[1] - trans[q * 3 + 1];
        float g2 = g[2] - trans[q * 3 + 2];
        const float* R = rot + q * 9;
        float l0 = R[0] * g0 + R[3] * g1 + R[6] * g2;
        float l1 = R[1] * g0 + R[4] * g1 + R[7] * g2;
        float l2 = R[2] * g0 + R[5] * g1 + R[8] * g2;
        int idx = h * 8 + p;
        f[192 + idx] = l0;
        f[288 + idx] = l1;
        f[384 + idx] = l2;
        f[480 + idx] = sqrtf(fmaxf(l0 * l0 + l1 * l1 + l2 * l2, 1e-16f));
    } else if (t < 288) {
        int idx = t - 96;           // 0..191
        int h = idx >> 4, s = idx & 15;
        f[idx] = o6[h * 40 + s];
    }
}

// ---------------- K8: output GEMM 1024x384x2112 (32x64 tiles) ----------------
__global__ __launch_bounds__(256) void k_out(const float* __restrict__ wout,
                                             const float* __restrict__ bout,
                                             float* __restrict__ out) {
    __shared__ __align__(16) float As[16 * 32];
    __shared__ __align__(16) float Bs[16 * 64];
    int n0 = blockIdx.x * 64, m0 = blockIdx.y * 32;
    int t = threadIdx.x;
    int tx = t & 15, ty = t >> 4;
    float acc[2][4] = {};
    for (int kc = 0; kc < FEATD; kc += 16) {
#pragma unroll
        for (int r = 0; r < 2; r++) {
            int idx = t + r * 256;
            As[(idx & 15) * 32 + (idx >> 4)] =
                g_feat[(size_t)(m0 + (idx >> 4)) * FEATD + kc + (idx & 15)];
        }
#pragma unroll
        for (int r = 0; r < 4; r++) {
            int idx = t + r * 256;
            Bs[(idx >> 6) * 64 + (idx & 63)] =
                wout[(size_t)(kc + (idx >> 6)) * NCHd + n0 + (idx & 63)];
        }
        __syncthreads();
#pragma unroll
        for (int kk = 0; kk < 16; kk++) {
            float2 a2 = *(const float2*)(As + kk * 32 + ty * 2);
            float4 b4 = *(const float4*)(Bs + kk * 64 + tx * 4);
            ffma2(acc[0][0], acc[0][1], a2.x, a2.x, b4.x, b4.y);
            ffma2(acc[0][2], acc[0][3], a2.x, a2.x, b4.z, b4.w);
            ffma2(acc[1][0], acc[1][1], a2.y, a2.y, b4.x, b4.y);
            ffma2(acc[1][2], acc[1][3], a2.y, a2.y, b4.z, b4.w);
        }
        __syncthreads();
    }
#pragma unroll
    for (int i = 0; i < 2; i++) {
        int m = m0 + ty * 2 + i;
#pragma unroll
        for (int j = 0; j < 4; j++) {
            int n = n0 + tx * 4 + j;
            out[(size_t)m * NCHd + n] = acc[i][j] + bout[n];
        }
    }
}

// ---------------- launch ----------------
extern "C" void kernel_launch(void* const* d_in, const int* in_sizes, int n_in,
                              void* d_out, int out_size) {
    const float* inputs_1d = (const float*)d_in[0];
    const float* inputs_2d = (const float*)d_in[1];
    const float* mask      = (const float*)d_in[2];
    const float* rot       = (const float*)d_in[3];
    const float* trans     = (const float*)d_in[4];
    const float* rawpw     = (const float*)d_in[5];
    const float* wq_point  = (const float*)d_in[6];
    const float* bq_point  = (const float*)d_in[7];
    const float* wk_point  = (const float*)d_in[8];
    const float* bk_point  = (const float*)d_in[9];
    const float* wv_point  = (const float*)d_in[10];
    const float* bv_point  = (const float*)d_in[11];
    const float* wq_scalar = (const float*)d_in[12];
    const float* wk_scalar = (const float*)d_in[13];
    const float* wv_scalar = (const float*)d_in[14];
    const float* w2d       = (const float*)d_in[15];
    const float* b2d       = (const float*)d_in[16];
    const float* wout      = (const float*)d_in[17];
    const float* bout      = (const float*)d_in[18];
    float* out = (float*)d_out;

    const int smem_final = 12288 * 4;   // 49152 B
    cudaFuncSetAttribute(k_final, cudaFuncAttributeMaxDynamicSharedMemorySize, smem_final);

    k_proj<<<dim3(PW / 64, Nn / 64), 256>>>(inputs_1d, wq_point, wk_point, wv_point,
                                            wq_scalar, wk_scalar, wv_scalar,
                                            bq_point, bk_point, bv_point);
    k_rotate<<<Nn, 256>>>(rot, trans);
    k_cheap<<<dim3(16, 8, 12), 256>>>(b2d, rawpw);
    k_logits<<<Nn, 512>>>(inputs_2d, w2d, mask);
    k_av<<<dim3(16, 12), 256>>>();
    k_final<<<Nn, 256, smem_final>>>(inputs_2d);
    k_post<<<Nn, 288>>>(rot, trans);
    k_out<<<dim3(NCHd / 64, Nn / 32), 256>>>(wout, bout, out);
}

// round 12
// speedup vs baseline: 1.4947x; 1.4947x over previous
#include <cuda_runtime.h>
#include <math.h>

#define Nn 1024
#define C1 384
#define C2 128
#define Hh 12
#define FEATD 2112
#define NCHd 384
#define PW 1152
#define LPAD 20

// ---------------- scratch (device globals; no runtime allocation) ----------------
static __device__ float g_P[Nn * PW];               // projections (1024x1152)
static __device__ float g_qpt[Nn * Hh * 12];        // global q points (n,h,p*3+i)
static __device__ float g_kpt[Nn * Hh * 12];
static __device__ float g_vpt[Nn * Hh * 24];
static __device__ float g_qn[Nn * Hh];              // |q_pts|^2 per (n,h)
static __device__ float g_kn[Nn * Hh];
static __device__ float g_bufA[(size_t)Hh * Nn * Nn]; // (h,q,k): cheap logits, then attn
static __device__ float g_out6[Nn * Hh * 40];       // [v_scalar(16) | point(24)] per (q,h)
static __device__ float g_feat[Nn * FEATD];         // assembled feature rows

// packed fp32x2 FMA: d0 += a0*b0 ; d1 += a1*b1
__device__ __forceinline__ void ffma2(float& d0, float& d1, float a0, float a1,
                                      float b0, float b1) {
    asm("{\n\t"
        ".reg .b64 ra, rb, rc;\n\t"
        "mov.b64 ra, {%2, %3};\n\t"
        "mov.b64 rb, {%4, %5};\n\t"
        "mov.b64 rc, {%0, %1};\n\t"
        "fma.rn.f32x2 rc, ra, rb, rc;\n\t"
        "mov.b64 {%0, %1}, rc;\n\t"
        "}"
        : "+f"(d0), "+f"(d1)
        : "f"(a0), "f"(a1), "f"(b0), "f"(b1));
}

// source of the assembled projection matrix column `col`, row `c`
__device__ __forceinline__ float wsrc(const float* __restrict__ wqp, const float* __restrict__ wkp,
                                      const float* __restrict__ wvp, const float* __restrict__ wqs,
                                      const float* __restrict__ wks, const float* __restrict__ wvs,
                                      int c, int col) {
    if (col < 144)  return wqp[c * 144 + col];
    if (col < 288)  return wkp[c * 144 + col - 144];
    if (col < 576)  return wvp[c * 288 + col - 288];
    if (col < 768)  return wqs[c * 192 + col - 576];
    if (col < 960)  return wks[c * 192 + col - 768];
    return wvs[c * 192 + col - 960];
}

// ---------------- K1: projection GEMM 1024x1152x384 (weights assembled on the fly) ----------------
__global__ __launch_bounds__(256) void k_proj(const float* __restrict__ A,
                                              const float* __restrict__ wqp, const float* __restrict__ wkp,
                                              const float* __restrict__ wvp, const float* __restrict__ wqs,
                                              const float* __restrict__ wks, const float* __restrict__ wvs,
                                              const float* __restrict__ bqp, const float* __restrict__ bkp,
                                              const float* __restrict__ bvp) {
    __shared__ __align__(16) float As[16 * 64];
    __shared__ __align__(16) float Bs[16 * 64];
    int n0 = blockIdx.x * 64, m0 = blockIdx.y * 64;
    int t = threadIdx.x;
    int tx = t & 15, ty = t >> 4;
    float acc[4][4] = {};
    for (int kc = 0; kc < C1; kc += 16) {
#pragma unroll
        for (int r = 0; r < 4; r++) {
            int idx = t + r * 256;
            As[(idx & 15) * 64 + (idx >> 4)] = A[(m0 + (idx >> 4)) * C1 + kc + (idx & 15)];
            Bs[(idx >> 6) * 64 + (idx & 63)] =
                wsrc(wqp, wkp, wvp, wqs, wks, wvs, kc + (idx >> 6), n0 + (idx & 63));
        }
        __syncthreads();
#pragma unroll
        for (int kk = 0; kk < 16; kk++) {
            float4 a4 = *(const float4*)(As + kk * 64 + ty * 4);
            float4 b4 = *(const float4*)(Bs + kk * 64 + tx * 4);
            ffma2(acc[0][0], acc[0][1], a4.x, a4.x, b4.x, b4.y);
            ffma2(acc[0][2], acc[0][3], a4.x, a4.x, b4.z, b4.w);
            ffma2(acc[1][0], acc[1][1], a4.y, a4.y, b4.x, b4.y);
            ffma2(acc[1][2], acc[1][3], a4.y, a4.y, b4.z, b4.w);
            ffma2(acc[2][0], acc[2][1], a4.z, a4.z, b4.x, b4.y);
            ffma2(acc[2][2], acc[2][3], a4.z, a4.z, b4.z, b4.w);
            ffma2(acc[3][0], acc[3][1], a4.w, a4.w, b4.x, b4.y);
            ffma2(acc[3][2], acc[3][3], a4.w, a4.w, b4.z, b4.w);
        }
        __syncthreads();
    }
#pragma unroll
    for (int i = 0; i < 4; i++) {
        int m = m0 + ty * 4 + i;
#pragma unroll
        for (int j = 0; j < 4; j++) {
            int n = n0 + tx * 4 + j;
            float b = 0.f;
            if (n < 144)      b = bqp[n];
            else if (n < 288) b = bkp[n - 144];
            else if (n < 576) b = bvp[n - 288];
            float s = (n >= 576 && n < 768) ? 0.25f : 1.f;   // q_scalar * sqrt(1/16)
            g_P[m * PW + n] = acc[i][j] * s + b;
        }
    }
}

// ---------------- K2: rigid transform + point norms ----------------
__global__ void k_rotate(const float* __restrict__ rot, const float* __restrict__ trans) {
    int n = blockIdx.x;
    int t = threadIdx.x;
    __shared__ float R[9], T[3];
    if (t < 9) R[t] = rot[n * 9 + t];
    if (t < 3) T[t] = trans[n * 3 + t];
    __syncthreads();
    if (t < 192) {
        float l0, l1, l2;
        float* dst;
        if (t < 48) {
            int h = t >> 2, p = t & 3;
            const float* src = &g_P[n * PW + h * 12];
            l0 = src[p]; l1 = src[4 + p]; l2 = src[8 + p];
            dst = &g_qpt[(n * 12 + h) * 12 + p * 3];
        } else if (t < 96) {
            int u = t - 48; int h = u >> 2, p = u & 3;
            const float* src = &g_P[n * PW + 144 + h * 12];
            l0 = src[p]; l1 = src[4 + p]; l2 = src[8 + p];
            dst = &g_kpt[(n * 12 + h) * 12 + p * 3];
        } else {
            int u = t - 96; int h = u >> 3, p = u & 7;
            const float* src = &g_P[n * PW + 288 + h * 24];
            l0 = src[p]; l1 = src[8 + p]; l2 = src[16 + p];
            dst = &g_vpt[(n * 12 + h) * 24 + p * 3];
        }
        dst[0] = R[0] * l0 + R[1] * l1 + R[2] * l2 + T[0];
        dst[1] = R[3] * l0 + R[4] * l1 + R[5] * l2 + T[1];
        dst[2] = R[6] * l0 + R[7] * l1 + R[8] * l2 + T[2];
    }
    __syncthreads();
    if (t < 24) {
        int h = t % 12;
        const float* p = (t < 12) ? &g_qpt[(n * 12 + h) * 12] : &g_kpt[(n * 12 + h) * 12];
        float s = 0.f;
#pragma unroll
        for (int d = 0; d < 12; d++) s += p[d] * p[d];
        if (t < 12) g_qn[n * 12 + h] = s;
        else        g_kn[n * 12 + h] = s;
    }
}

// ---------------- K3: cheap logits (scalar QK + point + b2d) -> (h,q,k), 128x64 tiles ----------------
__global__ __launch_bounds__(256) void k_cheap(const float* __restrict__ b2d,
                                               const float* __restrict__ rawpw) {
    int k0 = blockIdx.x * 64, q0 = blockIdx.y * 128, h = blockIdx.z;
    __shared__ __align__(16) float qf[28 * 128];   // [c][r]
    __shared__ __align__(16) float kf[28 * 64];
    __shared__ float qn_[128], kn_[64];
    int t = threadIdx.x;
    float x = rawpw[h];
    float sp = (x > 20.f) ? x : log1pf(expf(x));
    float pw = sqrtf(1.f / 18.f) * sp;             // point_var = 4*9/2 = 18
    for (int u = t; u < 1024; u += 256) {
        int r = u >> 3, g = u & 7;
        if (g < 4) {
            float4 v = *(const float4*)(&g_P[(size_t)(q0 + r) * PW + 576 + h * 16 + g * 4]);
            qf[(g * 4 + 0) * 128 + r] = v.x; qf[(g * 4 + 1) * 128 + r] = v.y;
            qf[(g * 4 + 2) * 128 + r] = v.z; qf[(g * 4 + 3) * 128 + r] = v.w;
        } else if (g < 7) {
            int pc = 16 + (g - 4) * 4;
            float4 v = *(const float4*)(&g_qpt[(((size_t)(q0 + r)) * 12 + h) * 12 + (g - 4) * 4]);
            qf[(pc + 0) * 128 + r] = v.x; qf[(pc + 1) * 128 + r] = v.y;
            qf[(pc + 2) * 128 + r] = v.z; qf[(pc + 3) * 128 + r] = v.w;
        }
    }
    for (int u = t; u < 512; u += 256) {
        int r = u >> 3, g = u & 7;
        if (g < 4) {
            float4 w = *(const float4*)(&g_P[(size_t)(k0 + r) * PW + 768 + h * 16 + g * 4]);
            kf[(g * 4 + 0) * 64 + r] = w.x; kf[(g * 4 + 1) * 64 + r] = w.y;
            kf[(g * 4 + 2) * 64 + r] = w.z; kf[(g * 4 + 3) * 64 + r] = w.w;
        } else if (g < 7) {
            int pc = 16 + (g - 4) * 4;
            float4 w = *(const float4*)(&g_kpt[(((size_t)(k0 + r)) * 12 + h) * 12 + (g - 4) * 4]);
            kf[(pc + 0) * 64 + r] = pw * w.x; kf[(pc + 1) * 64 + r] = pw * w.y;
            kf[(pc + 2) * 64 + r] = pw * w.z; kf[(pc + 3) * 64 + r] = pw * w.w;
        }
    }
    if (t < 128)           qn_[t] = 0.5f * pw * g_qn[(q0 + t) * 12 + h];
    else if (t < 192)      kn_[t - 128] = 0.5f * pw * g_kn[(k0 + t - 128) * 12 + h];
    __syncthreads();
    int tx = t & 15, ty = t >> 4;
    float acc[8][4] = {};
#pragma unroll
    for (int c = 0; c < 28; c++) {
        float4 aA = *(const float4*)(qf + c * 128 + ty * 8);
        float4 aB = *(const float4*)(qf + c * 128 + ty * 8 + 4);
        float4 b4 = *(const float4*)(kf + c * 64 + tx * 4);
        ffma2(acc[0][0], acc[0][1], aA.x, aA.x, b4.x, b4.y);
        ffma2(acc[0][2], acc[0][3], aA.x, aA.x, b4.z, b4.w);
        ffma2(acc[1][0], acc[1][1], aA.y, aA.y, b4.x, b4.y);
        ffma2(acc[1][2], acc[1][3], aA.y, aA.y, b4.z, b4.w);
        ffma2(acc[2][0], acc[2][1], aA.z, aA.z, b4.x, b4.y);
        ffma2(acc[2][2], acc[2][3], aA.z, aA.z, b4.z, b4.w);
        ffma2(acc[3][0], acc[3][1], aA.w, aA.w, b4.x, b4.y);
        ffma2(acc[3][2], acc[3][3], aA.w, aA.w, b4.z, b4.w);
        ffma2(acc[4][0], acc[4][1], aB.x, aB.x, b4.x, b4.y);
        ffma2(acc[4][2], acc[4][3], aB.x, aB.x, b4.z, b4.w);
        ffma2(acc[5][0], acc[5][1], aB.y, aB.y, b4.x, b4.y);
        ffma2(acc[5][2], acc[5][3], aB.y, aB.y, b4.z, b4.w);
        ffma2(acc[6][0], acc[6][1], aB.z, aB.z, b4.x, b4.y);
        ffma2(acc[6][2], acc[6][3], aB.z, aB.z, b4.z, b4.w);
        ffma2(acc[7][0], acc[7][1], aB.w, aB.w, b4.x, b4.y);
        ffma2(acc[7][2], acc[7][3], aB.w, aB.w, b4.z, b4.w);
    }
    float bb = b2d[h];
#pragma unroll
    for (int i = 0; i < 8; i++) {
        int q = q0 + ty * 8 + i;
#pragma unroll
        for (int j = 0; j < 4; j++) {
            int k = k0 + tx * 4 + j;
            g_bufA[((size_t)h << 20) + (size_t)q * 1024 + k] =
                acc[i][j] - qn_[ty * 8 + i] - kn_[tx * 4 + j] + bb;
        }
    }
}

// ---------------- K4: fused inputs_2d projection + cheap-add + mask + softmax ----------------
// one block per q; 512 threads, 2 CTAs/SM; thread t owns k in {t, t+512}.
// inputs_2d staged through padded smem: coalesced LDG + conflict-free LDS.128.
__global__ __launch_bounds__(512, 2) void k_logits(const float* __restrict__ in2d,
                                                   const float* __restrict__ w2d,
                                                   const float* __restrict__ mask) {
    extern __shared__ float dsm[];
    float* s2d = dsm;                 // [1024][LPAD]
    float* ws  = dsm + 1024 * LPAD;   // 192 floats (w2d chunk); reused as red[192]
    int q = blockIdx.x, t = threadIdx.x;
    float acc[2][12];
#pragma unroll
    for (int s = 0; s < 2; s++)
#pragma unroll
        for (int h = 0; h < 12; h++) acc[s][h] = 0.f;
    const float* inrow = in2d + (size_t)q * 131072;
    for (int c0 = 0; c0 < 128; c0 += 16) {
        if (t < 192) ws[t] = w2d[c0 * 12 + t];
#pragma unroll
        for (int it = 0; it < 8; it++) {
            int idx = t + it * 512;
            int row = idx >> 2, cq = (idx & 3) * 4;
            float4 v = *(const float4*)(inrow + row * 128 + c0 + cq);
            *(float4*)(s2d + row * LPAD + cq) = v;
        }
        __syncthreads();
#pragma unroll
        for (int c4 = 0; c4 < 4; c4++) {
            float4 a0 = *(const float4*)(s2d + (size_t)t * LPAD + c4 * 4);
            float4 a1 = *(const float4*)(s2d + (size_t)(t + 512) * LPAD + c4 * 4);
#pragma unroll
            for (int cc = 0; cc < 4; cc++) {
                const float* wb = ws + (c4 * 4 + cc) * 12;
                float4 b0 = *(const float4*)(wb);
                float4 b1 = *(const float4*)(wb + 4);
                float4 b2 = *(const float4*)(wb + 8);
                float av0 = (cc == 0) ? a0.x : (cc == 1) ? a0.y : (cc == 2) ? a0.z : a0.w;
                float av1 = (cc == 0) ? a1.x : (cc == 1) ? a1.y : (cc == 2) ? a1.z : a1.w;
                ffma2(acc[0][0],  acc[0][1],  av0, av0, b0.x, b0.y);
                ffma2(acc[0][2],  acc[0][3],  av0, av0, b0.z, b0.w);
                ffma2(acc[0][4],  acc[0][5],  av0, av0, b1.x, b1.y);
                ffma2(acc[0][6],  acc[0][7],  av0, av0, b1.z, b1.w);
                ffma2(acc[0][8],  acc[0][9],  av0, av0, b2.x, b2.y);
                ffma2(acc[0][10], acc[0][11], av0, av0, b2.z, b2.w);
                ffma2(acc[1][0],  acc[1][1],  av1, av1, b0.x, b0.y);
                ffma2(acc[1][2],  acc[1][3],  av1, av1, b0.z, b0.w);
                ffma2(acc[1][4],  acc[1][5],  av1, av1, b1.x, b1.y);
                ffma2(acc[1][6],  acc[1][7],  av1, av1, b1.z, b1.w);
                ffma2(acc[1][8],  acc[1][9],  av1, av1, b2.x, b2.y);
                ffma2(acc[1][10], acc[1][11], av1, av1, b2.z, b2.w);
            }
        }
        __syncthreads();
    }
    // ---- epilogue: add cheap, mask, scale ----
    float* red = ws;
    const float scale = 0.57735026918962576f;
    float mq = mask[q];
    float pen0 = -1e5f * (1.f - mq * mask[t]);
    float pen1 = -1e5f * (1.f - mq * mask[t + 512]);
#pragma unroll
    for (int h = 0; h < 12; h++) {
        size_t off = ((size_t)h << 20) + ((size_t)q << 10) + t;
        acc[0][h] = (acc[0][h] + g_bufA[off] + pen0) * scale;
        acc[1][h] = (acc[1][h] + g_bufA[off + 512] + pen1) * scale;
    }
    // ---- softmax over k (block-wide per h) ----
    int w = t >> 5, lane = t & 31;
#pragma unroll
    for (int h = 0; h < 12; h++) {
        float m = fmaxf(acc[0][h], acc[1][h]);
#pragma unroll
        for (int s = 16; s; s >>= 1) m = fmaxf(m, __shfl_xor_sync(0xffffffffu, m, s));
        if (lane == 0) red[w * 12 + h] = m;
    }
    __syncthreads();
    float hm[12];
#pragma unroll
    for (int h = 0; h < 12; h++) {
        float m = red[h];
#pragma unroll
        for (int w2 = 1; w2 < 16; w2++) m = fmaxf(m, red[w2 * 12 + h]);
        hm[h] = m;
    }
    __syncthreads();
#pragma unroll
    for (int h = 0; h < 12; h++) {
        acc[0][h] = __expf(acc[0][h] - hm[h]);
        acc[1][h] = __expf(acc[1][h] - hm[h]);
        float s0 = acc[0][h] + acc[1][h];
#pragma unroll
        for (int s = 16; s; s >>= 1) s0 += __shfl_xor_sync(0xffffffffu, s0, s);
        if (lane == 0) red[w * 12 + h] = s0;
    }
    __syncthreads();
#pragma unroll
    for (int h = 0; h < 12; h++) {
        float tot = red[h];
#pragma unroll
        for (int w2 = 1; w2 < 16; w2++) tot += red[w2 * 12 + h];
        float inv = 1.f / tot;
        size_t off = ((size_t)h << 20) + ((size_t)q << 10) + t;
        g_bufA[off]       = acc[0][h] * inv;
        g_bufA[off + 512] = acc[1][h] * inv;
    }
}

// ---------------- K5: AV (scalar + point values), per-head GEMM ----------------
__global__ __launch_bounds__(256) void k_av() {
    __shared__ __align__(16) float As[64 * 64];   // [kk][r]
    __shared__ float Bs[64 * 48];
    int h = blockIdx.y;
    int q0 = blockIdx.x * 64;
    int t = threadIdx.x;
    int tx = t & 15, ty = t >> 4;
    float acc[4][3] = {};
    for (int k0 = 0; k0 < 1024; k0 += 64) {
        const float* ab = g_bufA + ((size_t)h << 20) + (size_t)q0 * 1024 + k0;
        for (int idx = t; idx < 1024; idx += 256) {
            int r = idx >> 4, c4 = (idx & 15) * 4;
            float4 v = *(const float4*)(ab + (size_t)r * 1024 + c4);
            As[(c4 + 0) * 64 + r] = v.x; As[(c4 + 1) * 64 + r] = v.y;
            As[(c4 + 2) * 64 + r] = v.z; As[(c4 + 3) * 64 + r] = v.w;
        }
        for (int idx = t; idx < 64 * 48; idx += 256) {
            int kk = idx / 48, col = idx - kk * 48;
            int k = k0 + kk;
            float v = 0.f;
            if (col < 16)       v = g_P[(size_t)k * 1152 + 960 + h * 16 + col];
            else if (col < 40)  v = g_vpt[((size_t)k * 12 + h) * 24 + (col - 16)];
            Bs[kk * 48 + col] = v;
        }
        __syncthreads();
#pragma unroll 8
        for (int kk = 0; kk < 64; kk++) {
            float4 a4 = *(const float4*)(As + kk * 64 + ty * 4);
            float b0 = Bs[kk * 48 + tx * 3 + 0];
            float b1 = Bs[kk * 48 + tx * 3 + 1];
            float b2 = Bs[kk * 48 + tx * 3 + 2];
            ffma2(acc[0][0], acc[1][0], a4.x, a4.y, b0, b0);
            ffma2(acc[2][0], acc[3][0], a4.z, a4.w, b0, b0);
            ffma2(acc[0][1], acc[1][1], a4.x, a4.y, b1, b1);
            ffma2(acc[2][1], acc[3][1], a4.z, a4.w, b1, b1);
            ffma2(acc[0][2], acc[1][2], a4.x, a4.y, b2, b2);
            ffma2(acc[2][2], acc[3][2], a4.z, a4.w, b2, b2);
        }
        __syncthreads();
    }
#pragma unroll
    for (int i = 0; i < 4; i++) {
        int q = q0 + ty * 4 + i;
#pragma unroll
        for (int j = 0; j < 3; j++) {
            int col = tx * 3 + j;
            if (col < 40) g_out6[((size_t)q * 12 + h) * 40 + col] = acc[i][j];
        }
    }
}

// ---------------- K6: res_2d per q (second in2d pass) ----------------
// 256 threads = 64 c-pairs x 4 k-slices; dynamic smem 12288 floats (attn planes)
__global__ __launch_bounds__(256) void k_final(const float* __restrict__ in2d) {
    extern __shared__ float sa[];   // [h][1024]
    int q = blockIdx.x;
    int t = threadIdx.x;
#pragma unroll
    for (int h = 0; h < 12; h++) {
        float4 v = *(const float4*)(g_bufA + ((size_t)h << 20) + ((size_t)q << 10) + t * 4);
        *(float4*)(sa + h * 1024 + t * 4) = v;
    }
    __syncthreads();
    int cp = t & 63, ks = t >> 6;
    float aX[12], aY[12];
#pragma unroll
    for (int u = 0; u < 12; u++) { aX[u] = 0.f; aY[u] = 0.f; }
    const float* base = in2d + (size_t)q * 131072 + cp * 2;
    int kbase = ks * 256;
    for (int kt = 0; kt < 64; kt++) {
        int k0 = kbase + kt * 4;
        float2 v0 = *(const float2*)(base + (size_t)(k0 + 0) * 128);
        float2 v1 = *(const float2*)(base + (size_t)(k0 + 1) * 128);
        float2 v2 = *(const float2*)(base + (size_t)(k0 + 2) * 128);
        float2 v3 = *(const float2*)(base + (size_t)(k0 + 3) * 128);
#pragma unroll
        for (int u = 0; u < 6; u++) {
            float4 a0 = *(const float4*)(sa + (2 * u) * 1024 + k0);
            float4 a1 = *(const float4*)(sa + (2 * u + 1) * 1024 + k0);
            ffma2(aX[2 * u], aX[2 * u + 1], a0.x, a1.x, v0.x, v0.x);
            ffma2(aY[2 * u], aY[2 * u + 1], a0.x, a1.x, v0.y, v0.y);
            ffma2(aX[2 * u], aX[2 * u + 1], a0.y, a1.y, v1.x, v1.x);
            ffma2(aY[2 * u], aY[2 * u + 1], a0.y, a1.y, v1.y, v1.y);
            ffma2(aX[2 * u], aX[2 * u + 1], a0.z, a1.z, v2.x, v2.x);
            ffma2(aY[2 * u], aY[2 * u + 1], a0.z, a1.z, v2.y, v2.y);
            ffma2(aX[2 * u], aX[2 * u + 1], a0.w, a1.w, v3.x, v3.x);
            ffma2(aY[2 * u], aY[2 * u + 1], a0.w, a1.w, v3.y, v3.y);
        }
    }
    __syncthreads();   // everyone done reading attn from sa
    if (ks != 0) {
        float* d = sa + (size_t)((ks - 1) * 64 + cp) * 24;
#pragma unroll
        for (int u = 0; u < 12; u++) { d[u] = aX[u]; d[12 + u] = aY[u]; }
    }
    __syncthreads();
    if (ks == 0) {
#pragma unroll
        for (int s = 0; s < 3; s++) {
            const float* d = sa + (size_t)(s * 64 + cp) * 24;
#pragma unroll
            for (int u = 0; u < 12; u++) { aX[u] += d[u]; aY[u] += d[12 + u]; }
        }
        float* f = g_feat + (size_t)q * 2112 + 576;
#pragma unroll
        for (int hh = 0; hh < 12; hh++) {
            f[hh * 128 + 2 * cp]     = aX[hh];
            f[hh * 128 + 2 * cp + 1] = aY[hh];
        }
    }
}

// ---------------- K7: inverse rigid, norms, feature assembly ----------------
__global__ void k_post(const float* __restrict__ rot, const float* __restrict__ trans) {
    int q = blockIdx.x;
    int t = threadIdx.x;   // 288
    float* f = g_feat + (size_t)q * 2112;
    const float* o6 = g_out6 + (size_t)q * 12 * 40;
    if (t < 96) {
        int h = t >> 3, p = t & 7;
        const float* g = o6 + h * 40 + 16 + p * 3;
        float g0 = g[0] - trans[q * 3 + 0];
        float g1 = g[1] - trans[q * 3 + 1];
        float g2 = g[2] - trans[q * 3 + 2];
        const float* R = rot + q * 9;
        float l0 = R[0] * g0 + R[3] * g1 + R[6] * g2;
        float l1 = R[1] * g0 + R[4] * g1 + R[7] * g2;
        float l2 = R[2] * g0 + R[5] * g1 + R[8] * g2;
        int idx = h * 8 + p;
        f[192 + idx] = l0;
        f[288 + idx] = l1;
        f[384 + idx] = l2;
        f[480 + idx] = sqrtf(fmaxf(l0 * l0 + l1 * l1 + l2 * l2, 1e-16f));
    } else if (t < 288) {
        int idx = t - 96;           // 0..191
        int h = idx >> 4, s = idx & 15;
        f[idx] = o6[h * 40 + s];
    }
}

// ---------------- K8: output GEMM 1024x384x2112 (32x64 tiles) ----------------
__global__ __launch_bounds__(256) void k_out(const float* __restrict__ wout,
                                             const float* __restrict__ bout,
                                             float* __restrict__ out) {
    __shared__ __align__(16) float As[16 * 32];
    __shared__ __align__(16) float Bs[16 * 64];
    int n0 = blockIdx.x * 64, m0 = blockIdx.y * 32;
    int t = threadIdx.x;
    int tx = t & 15, ty = t >> 4;
    float acc[2][4] = {};
    for (int kc = 0; kc < FEATD; kc += 16) {
#pragma unroll
        for (int r = 0; r < 2; r++) {
            int idx = t + r * 256;
            As[(idx & 15) * 32 + (idx >> 4)] =
                g_feat[(size_t)(m0 + (idx >> 4)) * FEATD + kc + (idx & 15)];
        }
#pragma unroll
        for (int r = 0; r < 4; r++) {
            int idx = t + r * 256;
            Bs[(idx >> 6) * 64 + (idx & 63)] =
                wout[(size_t)(kc + (idx >> 6)) * NCHd + n0 + (idx & 63)];
        }
        __syncthreads();
#pragma unroll
        for (int kk = 0; kk < 16; kk++) {
            float2 a2 = *(const float2*)(As + kk * 32 + ty * 2);
            float4 b4 = *(const float4*)(Bs + kk * 64 + tx * 4);
            ffma2(acc[0][0], acc[0][1], a2.x, a2.x, b4.x, b4.y);
            ffma2(acc[0][2], acc[0][3], a2.x, a2.x, b4.z, b4.w);
            ffma2(acc[1][0], acc[1][1], a2.y, a2.y, b4.x, b4.y);
            ffma2(acc[1][2], acc[1][3], a2.y, a2.y, b4.z, b4.w);
        }
        __syncthreads();
    }
#pragma unroll
    for (int i = 0; i < 2; i++) {
        int m = m0 + ty * 2 + i;
#pragma unroll
        for (int j = 0; j < 4; j++) {
            int n = n0 + tx * 4 + j;
            out[(size_t)m * NCHd + n] = acc[i][j] + bout[n];
        }
    }
}

// ---------------- launch ----------------
extern "C" void kernel_launch(void* const* d_in, const int* in_sizes, int n_in,
                              void* d_out, int out_size) {
    const float* inputs_1d = (const float*)d_in[0];
    const float* inputs_2d = (const float*)d_in[1];
    const float* mask      = (const float*)d_in[2];
    const float* rot       = (const float*)d_in[3];
    const float* trans     = (const float*)d_in[4];
    const float* rawpw     = (const float*)d_in[5];
    const float* wq_point  = (const float*)d_in[6];
    const float* bq_point  = (const float*)d_in[7];
    const float* wk_point  = (const float*)d_in[8];
    const float* bk_point  = (const float*)d_in[9];
    const float* wv_point  = (const float*)d_in[10];
    const float* bv_point  = (const float*)d_in[11];
    const float* wq_scalar = (const float*)d_in[12];
    const float* wk_scalar = (const float*)d_in[13];
    const float* wv_scalar = (const float*)d_in[14];
    const float* w2d       = (const float*)d_in[15];
    const float* b2d       = (const float*)d_in[16];
    const float* wout      = (const float*)d_in[17];
    const float* bout      = (const float*)d_in[18];
    float* out = (float*)d_out;

    const int smem_logits = (1024 * LPAD + 192) * 4;   // 82688 B
    const int smem_final  = 12288 * 4;                 // 49152 B
    cudaFuncSetAttribute(k_logits, cudaFuncAttributeMaxDynamicSharedMemorySize, smem_logits);
    cudaFuncSetAttribute(k_final,  cudaFuncAttributeMaxDynamicSharedMemorySize, smem_final);

    k_proj<<<dim3(PW / 64, Nn / 64), 256>>>(inputs_1d, wq_point, wk_point, wv_point,
                                            wq_scalar, wk_scalar, wv_scalar,
                                            bq_point, bk_point, bv_point);
    k_rotate<<<Nn, 256>>>(rot, trans);
    k_cheap<<<dim3(16, 8, 12), 256>>>(b2d, rawpw);
    k_logits<<<Nn, 512, smem_logits>>>(inputs_2d, w2d, mask);
    k_av<<<dim3(16, 12), 256>>>();
    k_final<<<Nn, 256, smem_final>>>(inputs_2d);
    k_post<<<Nn, 288>>>(rot, trans);
    k_out<<<dim3(NCHd / 64, Nn / 32), 256>>>(wout, bout, out);
}

// round 13
// speedup vs baseline: 1.5798x; 1.0570x over previous
#include <cuda_runtime.h>
#include <math.h>

#define Nn 1024
#define C1 384
#define C2 128
#define Hh 12
#define FEATD 2112
#define NCHd 384
#define PW 1152

// ---------------- scratch (device globals; no runtime allocation) ----------------
static __device__ float g_P[Nn * PW];               // projections (1024x1152)
static __device__ float g_qpt[Nn * Hh * 12];        // global q points (n,h,p*3+i)
static __device__ float g_kpt[Nn * Hh * 12];
static __device__ float g_vpt[Nn * Hh * 24];
static __device__ float g_qn[Nn * Hh];              // |q_pts|^2 per (n,h)
static __device__ float g_kn[Nn * Hh];
static __device__ float g_bufA[(size_t)Hh * Nn * Nn]; // (h,q,k): cheap logits, then attn
static __device__ float g_out6[Nn * Hh * 40];       // [v_scalar(16) | point(24)] per (q,h)
static __device__ float g_feat[Nn * FEATD];         // assembled feature rows

// packed fp32x2 FMA: d0 += a0*b0 ; d1 += a1*b1
__device__ __forceinline__ void ffma2(float& d0, float& d1, float a0, float a1,
                                      float b0, float b1) {
    asm("{\n\t"
        ".reg .b64 ra, rb, rc;\n\t"
        "mov.b64 ra, {%2, %3};\n\t"
        "mov.b64 rb, {%4, %5};\n\t"
        "mov.b64 rc, {%0, %1};\n\t"
        "fma.rn.f32x2 rc, ra, rb, rc;\n\t"
        "mov.b64 {%0, %1}, rc;\n\t"
        "}"
        : "+f"(d0), "+f"(d1)
        : "f"(a0), "f"(a1), "f"(b0), "f"(b1));
}

// source of the assembled projection matrix column `col`, row `c`
__device__ __forceinline__ float wsrc(const float* __restrict__ wqp, const float* __restrict__ wkp,
                                      const float* __restrict__ wvp, const float* __restrict__ wqs,
                                      const float* __restrict__ wks, const float* __restrict__ wvs,
                                      int c, int col) {
    if (col < 144)  return wqp[c * 144 + col];
    if (col < 288)  return wkp[c * 144 + col - 144];
    if (col < 576)  return wvp[c * 288 + col - 288];
    if (col < 768)  return wqs[c * 192 + col - 576];
    if (col < 960)  return wks[c * 192 + col - 768];
    return wvs[c * 192 + col - 960];
}

// ---------------- K1: projection GEMM 1024x1152x384 (weights assembled on the fly) ----------------
__global__ __launch_bounds__(256) void k_proj(const float* __restrict__ A,
                                              const float* __restrict__ wqp, const float* __restrict__ wkp,
                                              const float* __restrict__ wvp, const float* __restrict__ wqs,
                                              const float* __restrict__ wks, const float* __restrict__ wvs,
                                              const float* __restrict__ bqp, const float* __restrict__ bkp,
                                              const float* __restrict__ bvp) {
    __shared__ __align__(16) float As[16 * 64];
    __shared__ __align__(16) float Bs[16 * 64];
    int n0 = blockIdx.x * 64, m0 = blockIdx.y * 64;
    int t = threadIdx.x;
    int tx = t & 15, ty = t >> 4;
    float acc[4][4] = {};
    for (int kc = 0; kc < C1; kc += 16) {
#pragma unroll
        for (int r = 0; r < 4; r++) {
            int idx = t + r * 256;
            As[(idx & 15) * 64 + (idx >> 4)] = A[(m0 + (idx >> 4)) * C1 + kc + (idx & 15)];
            Bs[(idx >> 6) * 64 + (idx & 63)] =
                wsrc(wqp, wkp, wvp, wqs, wks, wvs, kc + (idx >> 6), n0 + (idx & 63));
        }
        __syncthreads();
#pragma unroll
        for (int kk = 0; kk < 16; kk++) {
            float4 a4 = *(const float4*)(As + kk * 64 + ty * 4);
            float4 b4 = *(const float4*)(Bs + kk * 64 + tx * 4);
            ffma2(acc[0][0], acc[0][1], a4.x, a4.x, b4.x, b4.y);
            ffma2(acc[0][2], acc[0][3], a4.x, a4.x, b4.z, b4.w);
            ffma2(acc[1][0], acc[1][1], a4.y, a4.y, b4.x, b4.y);
            ffma2(acc[1][2], acc[1][3], a4.y, a4.y, b4.z, b4.w);
            ffma2(acc[2][0], acc[2][1], a4.z, a4.z, b4.x, b4.y);
            ffma2(acc[2][2], acc[2][3], a4.z, a4.z, b4.z, b4.w);
            ffma2(acc[3][0], acc[3][1], a4.w, a4.w, b4.x, b4.y);
            ffma2(acc[3][2], acc[3][3], a4.w, a4.w, b4.z, b4.w);
        }
        __syncthreads();
    }
#pragma unroll
    for (int i = 0; i < 4; i++) {
        int m = m0 + ty * 4 + i;
#pragma unroll
        for (int j = 0; j < 4; j++) {
            int n = n0 + tx * 4 + j;
            float b = 0.f;
            if (n < 144)      b = bqp[n];
            else if (n < 288) b = bkp[n - 144];
            else if (n < 576) b = bvp[n - 288];
            float s = (n >= 576 && n < 768) ? 0.25f : 1.f;   // q_scalar * sqrt(1/16)
            g_P[m * PW + n] = acc[i][j] * s + b;
        }
    }
}

// ---------------- K2: rigid transform + point norms ----------------
__global__ void k_rotate(const float* __restrict__ rot, const float* __restrict__ trans) {
    int n = blockIdx.x;
    int t = threadIdx.x;
    __shared__ float R[9], T[3];
    if (t < 9) R[t] = rot[n * 9 + t];
    if (t < 3) T[t] = trans[n * 3 + t];
    __syncthreads();
    if (t < 192) {
        float l0, l1, l2;
        float* dst;
        if (t < 48) {
            int h = t >> 2, p = t & 3;
            const float* src = &g_P[n * PW + h * 12];
            l0 = src[p]; l1 = src[4 + p]; l2 = src[8 + p];
            dst = &g_qpt[(n * 12 + h) * 12 + p * 3];
        } else if (t < 96) {
            int u = t - 48; int h = u >> 2, p = u & 3;
            const float* src = &g_P[n * PW + 144 + h * 12];
            l0 = src[p]; l1 = src[4 + p]; l2 = src[8 + p];
            dst = &g_kpt[(n * 12 + h) * 12 + p * 3];
        } else {
            int u = t - 96; int h = u >> 3, p = u & 7;
            const float* src = &g_P[n * PW + 288 + h * 24];
            l0 = src[p]; l1 = src[8 + p]; l2 = src[16 + p];
            dst = &g_vpt[(n * 12 + h) * 24 + p * 3];
        }
        dst[0] = R[0] * l0 + R[1] * l1 + R[2] * l2 + T[0];
        dst[1] = R[3] * l0 + R[4] * l1 + R[5] * l2 + T[1];
        dst[2] = R[6] * l0 + R[7] * l1 + R[8] * l2 + T[2];
    }
    __syncthreads();
    if (t < 24) {
        int h = t % 12;
        const float* p = (t < 12) ? &g_qpt[(n * 12 + h) * 12] : &g_kpt[(n * 12 + h) * 12];
        float s = 0.f;
#pragma unroll
        for (int d = 0; d < 12; d++) s += p[d] * p[d];
        if (t < 12) g_qn[n * 12 + h] = s;
        else        g_kn[n * 12 + h] = s;
    }
}

// ---------------- K3: cheap logits (scalar QK + point + b2d) -> (h,q,k), 64x64 tiles ----------------
__global__ __launch_bounds__(256) void k_cheap(const float* __restrict__ b2d,
                                               const float* __restrict__ rawpw) {
    int k0 = blockIdx.x * 64, q0 = blockIdx.y * 64, h = blockIdx.z;
    __shared__ __align__(16) float qf[28 * 64];   // [c][r]
    __shared__ __align__(16) float kf[28 * 64];
    __shared__ float qn_[64], kn_[64];
    int t = threadIdx.x;
    float x = rawpw[h];
    float sp = (x > 20.f) ? x : log1pf(expf(x));
    float pw = sqrtf(1.f / 18.f) * sp;             // point_var = 4*9/2 = 18
    // fill: 64 rows x 8 groups (g==7 unused); g<4: scalar float4, g in 4..6: point float4
    for (int u = t; u < 512; u += 256) {
        int r = u >> 3, g = u & 7;
        if (g < 4) {
            float4 v = *(const float4*)(&g_P[(size_t)(q0 + r) * PW + 576 + h * 16 + g * 4]);
            qf[(g * 4 + 0) * 64 + r] = v.x; qf[(g * 4 + 1) * 64 + r] = v.y;
            qf[(g * 4 + 2) * 64 + r] = v.z; qf[(g * 4 + 3) * 64 + r] = v.w;
            float4 w = *(const float4*)(&g_P[(size_t)(k0 + r) * PW + 768 + h * 16 + g * 4]);
            kf[(g * 4 + 0) * 64 + r] = w.x; kf[(g * 4 + 1) * 64 + r] = w.y;
            kf[(g * 4 + 2) * 64 + r] = w.z; kf[(g * 4 + 3) * 64 + r] = w.w;
        } else if (g < 7) {
            int pc = 16 + (g - 4) * 4;
            float4 v = *(const float4*)(&g_qpt[(((size_t)(q0 + r)) * 12 + h) * 12 + (g - 4) * 4]);
            qf[(pc + 0) * 64 + r] = v.x; qf[(pc + 1) * 64 + r] = v.y;
            qf[(pc + 2) * 64 + r] = v.z; qf[(pc + 3) * 64 + r] = v.w;
            float4 w = *(const float4*)(&g_kpt[(((size_t)(k0 + r)) * 12 + h) * 12 + (g - 4) * 4]);
            kf[(pc + 0) * 64 + r] = pw * w.x; kf[(pc + 1) * 64 + r] = pw * w.y;
            kf[(pc + 2) * 64 + r] = pw * w.z; kf[(pc + 3) * 64 + r] = pw * w.w;
        }
    }
    if (t < 64)            qn_[t] = 0.5f * pw * g_qn[(q0 + t) * 12 + h];
    else if (t < 128)      kn_[t - 64] = 0.5f * pw * g_kn[(k0 + t - 64) * 12 + h];
    __syncthreads();
    int tx = t & 15, ty = t >> 4;
    float acc[4][4] = {};
#pragma unroll
    for (int c = 0; c < 28; c++) {
        float4 a4 = *(const float4*)(qf + c * 64 + ty * 4);
        float4 b4 = *(const float4*)(kf + c * 64 + tx * 4);
        ffma2(acc[0][0], acc[0][1], a4.x, a4.x, b4.x, b4.y);
        ffma2(acc[0][2], acc[0][3], a4.x, a4.x, b4.z, b4.w);
        ffma2(acc[1][0], acc[1][1], a4.y, a4.y, b4.x, b4.y);
        ffma2(acc[1][2], acc[1][3], a4.y, a4.y, b4.z, b4.w);
        ffma2(acc[2][0], acc[2][1], a4.z, a4.z, b4.x, b4.y);
        ffma2(acc[2][2], acc[2][3], a4.z, a4.z, b4.z, b4.w);
        ffma2(acc[3][0], acc[3][1], a4.w, a4.w, b4.x, b4.y);
        ffma2(acc[3][2], acc[3][3], a4.w, a4.w, b4.z, b4.w);
    }
    float bb = b2d[h];
#pragma unroll
    for (int i = 0; i < 4; i++) {
        int q = q0 + ty * 4 + i;
#pragma unroll
        for (int j = 0; j < 4; j++) {
            int k = k0 + tx * 4 + j;
            g_bufA[((size_t)h << 20) + (size_t)q * 1024 + k] =
                acc[i][j] - qn_[ty * 4 + i] - kn_[tx * 4 + j] + bb;
        }
    }
}

// ---------------- K4: fused inputs_2d projection + cheap-add + mask + softmax ----------------
// one block per q; 256 threads (2 CTAs/SM), thread t owns k in {t, t+256, t+512, t+768}.
// inputs_2d staged via row-pair interleaved smem: addr = 40*(k>>1) + 4*(k&1) + 8*c4.
// Both the fill STS.128 and compute LDS.128 are bank-conflict-free in this layout.
__global__ __launch_bounds__(256, 2) void k_logits(const float* __restrict__ in2d,
                                                   const float* __restrict__ w2d,
                                                   const float* __restrict__ mask) {
    extern __shared__ float dsm[];
    float* s2d = dsm;                 // 512 row-pairs * 40 floats = 20480
    float* ws  = dsm + 20480;         // 192 floats (w2d chunk); reused as red[96]
    int q = blockIdx.x, t = threadIdx.x;
    float acc[4][12];
#pragma unroll
    for (int s = 0; s < 4; s++)
#pragma unroll
        for (int h = 0; h < 12; h++) acc[s][h] = 0.f;
    int kb[4];
#pragma unroll
    for (int s = 0; s < 4; s++) {
        int k = t + s * 256;
        kb[s] = 40 * (k >> 1) + 4 * (k & 1);
    }
    const float* inrow = in2d + (size_t)q * 131072;
    for (int c0 = 0; c0 < 128; c0 += 16) {
        if (t < 192) ws[t] = w2d[c0 * 12 + t];
#pragma unroll
        for (int it = 0; it < 16; it++) {
            int idx = t + it * 256;
            int row = idx >> 2, cq = idx & 3;
            float4 v = *(const float4*)(inrow + row * 128 + c0 + cq * 4);
            *(float4*)(s2d + 40 * (row >> 1) + 4 * (row & 1) + 8 * cq) = v;
        }
        __syncthreads();
#pragma unroll
        for (int c4 = 0; c4 < 4; c4++) {
            float4 a[4];
#pragma unroll
            for (int s = 0; s < 4; s++)
                a[s] = *(const float4*)(s2d + kb[s] + 8 * c4);
#pragma unroll
            for (int cc = 0; cc < 4; cc++) {
                const float* wb = ws + (c4 * 4 + cc) * 12;
                float4 b0 = *(const float4*)(wb);
                float4 b1 = *(const float4*)(wb + 4);
                float4 b2 = *(const float4*)(wb + 8);
#pragma unroll
                for (int s = 0; s < 4; s++) {
                    float av = (cc == 0) ? a[s].x : (cc == 1) ? a[s].y
                             : (cc == 2) ? a[s].z : a[s].w;
                    ffma2(acc[s][0],  acc[s][1],  av, av, b0.x, b0.y);
                    ffma2(acc[s][2],  acc[s][3],  av, av, b0.z, b0.w);
                    ffma2(acc[s][4],  acc[s][5],  av, av, b1.x, b1.y);
                    ffma2(acc[s][6],  acc[s][7],  av, av, b1.z, b1.w);
                    ffma2(acc[s][8],  acc[s][9],  av, av, b2.x, b2.y);
                    ffma2(acc[s][10], acc[s][11], av, av, b2.z, b2.w);
                }
            }
        }
        __syncthreads();
    }
    // ---- epilogue: add cheap, mask, scale ----
    float* red = ws;
    const float scale = 0.57735026918962576f;
    float mq = mask[q];
    float pen[4];
#pragma unroll
    for (int s = 0; s < 4; s++) pen[s] = -1e5f * (1.f - mq * mask[t + s * 256]);
#pragma unroll
    for (int h = 0; h < 12; h++) {
        size_t off = ((size_t)h << 20) + ((size_t)q << 10) + t;
#pragma unroll
        for (int s = 0; s < 4; s++) {
            float ch = g_bufA[off + s * 256];
            acc[s][h] = (acc[s][h] + ch + pen[s]) * scale;
        }
    }
    // ---- softmax over k (block-wide per h) ----
    int w = t >> 5, lane = t & 31;
#pragma unroll
    for (int h = 0; h < 12; h++) {
        float m = fmaxf(fmaxf(acc[0][h], acc[1][h]), fmaxf(acc[2][h], acc[3][h]));
#pragma unroll
        for (int s = 16; s; s >>= 1) m = fmaxf(m, __shfl_xor_sync(0xffffffffu, m, s));
        if (lane == 0) red[w * 12 + h] = m;
    }
    __syncthreads();
    float hm[12];
#pragma unroll
    for (int h = 0; h < 12; h++) {
        float m = red[h];
#pragma unroll
        for (int w2 = 1; w2 < 8; w2++) m = fmaxf(m, red[w2 * 12 + h]);
        hm[h] = m;
    }
    __syncthreads();
#pragma unroll
    for (int h = 0; h < 12; h++) {
        float s0 = 0.f;
#pragma unroll
        for (int s = 0; s < 4; s++) {
            acc[s][h] = __expf(acc[s][h] - hm[h]);
            s0 += acc[s][h];
        }
#pragma unroll
        for (int s = 16; s; s >>= 1) s0 += __shfl_xor_sync(0xffffffffu, s0, s);
        if (lane == 0) red[w * 12 + h] = s0;
    }
    __syncthreads();
#pragma unroll
    for (int h = 0; h < 12; h++) {
        float tot = red[h];
#pragma unroll
        for (int w2 = 1; w2 < 8; w2++) tot += red[w2 * 12 + h];
        float inv = 1.f / tot;
        size_t off = ((size_t)h << 20) + ((size_t)q << 10) + t;
#pragma unroll
        for (int s = 0; s < 4; s++) g_bufA[off + s * 256] = acc[s][h] * inv;
    }
}

// ---------------- K5: AV (scalar + point values), per-head GEMM ----------------
__global__ __launch_bounds__(256) void k_av() {
    __shared__ __align__(16) float As[64 * 64];   // [kk][r]
    __shared__ float Bs[64 * 48];
    int h = blockIdx.y;
    int q0 = blockIdx.x * 64;
    int t = threadIdx.x;
    int tx = t & 15, ty = t >> 4;
    float acc[4][3] = {};
    for (int k0 = 0; k0 < 1024; k0 += 64) {
        const float* ab = g_bufA + ((size_t)h << 20) + (size_t)q0 * 1024 + k0;
        for (int idx = t; idx < 1024; idx += 256) {
            int r = idx >> 4, c4 = (idx & 15) * 4;
            float4 v = *(const float4*)(ab + (size_t)r * 1024 + c4);
            As[(c4 + 0) * 64 + r] = v.x; As[(c4 + 1) * 64 + r] = v.y;
            As[(c4 + 2) * 64 + r] = v.z; As[(c4 + 3) * 64 + r] = v.w;
        }
        for (int idx = t; idx < 64 * 48; idx += 256) {
            int kk = idx / 48, col = idx - kk * 48;
            int k = k0 + kk;
            float v = 0.f;
            if (col < 16)       v = g_P[(size_t)k * 1152 + 960 + h * 16 + col];
            else if (col < 40)  v = g_vpt[((size_t)k * 12 + h) * 24 + (col - 16)];
            Bs[kk * 48 + col] = v;
        }
        __syncthreads();
#pragma unroll 8
        for (int kk = 0; kk < 64; kk++) {
            float4 a4 = *(const float4*)(As + kk * 64 + ty * 4);
            float b0 = Bs[kk * 48 + tx * 3 + 0];
            float b1 = Bs[kk * 48 + tx * 3 + 1];
            float b2 = Bs[kk * 48 + tx * 3 + 2];
            ffma2(acc[0][0], acc[1][0], a4.x, a4.y, b0, b0);
            ffma2(acc[2][0], acc[3][0], a4.z, a4.w, b0, b0);
            ffma2(acc[0][1], acc[1][1], a4.x, a4.y, b1, b1);
            ffma2(acc[2][1], acc[3][1], a4.z, a4.w, b1, b1);
            ffma2(acc[0][2], acc[1][2], a4.x, a4.y, b2, b2);
            ffma2(acc[2][2], acc[3][2], a4.z, a4.w, b2, b2);
        }
        __syncthreads();
    }
#pragma unroll
    for (int i = 0; i < 4; i++) {
        int q = q0 + ty * 4 + i;
#pragma unroll
        for (int j = 0; j < 3; j++) {
            int col = tx * 3 + j;
            if (col < 40) g_out6[((size_t)q * 12 + h) * 40 + col] = acc[i][j];
        }
    }
}

// ---------------- K6: res_2d per q (second in2d pass) ----------------
// 256 threads = 64 c-pairs x 4 k-slices; dynamic smem 12288 floats (attn planes)
__global__ __launch_bounds__(256) void k_final(const float* __restrict__ in2d) {
    extern __shared__ float sa[];   // [h][1024]
    int q = blockIdx.x;
    int t = threadIdx.x;
#pragma unroll
    for (int h = 0; h < 12; h++) {
        float4 v = *(const float4*)(g_bufA + ((size_t)h << 20) + ((size_t)q << 10) + t * 4);
        *(float4*)(sa + h * 1024 + t * 4) = v;
    }
    __syncthreads();
    int cp = t & 63, ks = t >> 6;
    float aX[12], aY[12];
#pragma unroll
    for (int u = 0; u < 12; u++) { aX[u] = 0.f; aY[u] = 0.f; }
    const float* base = in2d + (size_t)q * 131072 + cp * 2;
    int kbase = ks * 256;
#pragma unroll 2
    for (int kt = 0; kt < 64; kt++) {
        int k0 = kbase + kt * 4;
        float2 v0 = *(const float2*)(base + (size_t)(k0 + 0) * 128);
        float2 v1 = *(const float2*)(base + (size_t)(k0 + 1) * 128);
        float2 v2 = *(const float2*)(base + (size_t)(k0 + 2) * 128);
        float2 v3 = *(const float2*)(base + (size_t)(k0 + 3) * 128);
#pragma unroll
        for (int u = 0; u < 6; u++) {
            float4 a0 = *(const float4*)(sa + (2 * u) * 1024 + k0);
            float4 a1 = *(const float4*)(sa + (2 * u + 1) * 1024 + k0);
            ffma2(aX[2 * u], aX[2 * u + 1], a0.x, a1.x, v0.x, v0.x);
            ffma2(aY[2 * u], aY[2 * u + 1], a0.x, a1.x, v0.y, v0.y);
            ffma2(aX[2 * u], aX[2 * u + 1], a0.y, a1.y, v1.x, v1.x);
            ffma2(aY[2 * u], aY[2 * u + 1], a0.y, a1.y, v1.y, v1.y);
            ffma2(aX[2 * u], aX[2 * u + 1], a0.z, a1.z, v2.x, v2.x);
            ffma2(aY[2 * u], aY[2 * u + 1], a0.z, a1.z, v2.y, v2.y);
            ffma2(aX[2 * u], aX[2 * u + 1], a0.w, a1.w, v3.x, v3.x);
            ffma2(aY[2 * u], aY[2 * u + 1], a0.w, a1.w, v3.y, v3.y);
        }
    }
    __syncthreads();   // everyone done reading attn from sa
    if (ks != 0) {
        float* d = sa + (size_t)((ks - 1) * 64 + cp) * 24;
#pragma unroll
        for (int u = 0; u < 12; u++) { d[u] = aX[u]; d[12 + u] = aY[u]; }
    }
    __syncthreads();
    if (ks == 0) {
#pragma unroll
        for (int s = 0; s < 3; s++) {
            const float* d = sa + (size_t)(s * 64 + cp) * 24;
#pragma unroll
            for (int u = 0; u < 12; u++) { aX[u] += d[u]; aY[u] += d[12 + u]; }
        }
        float* f = g_feat + (size_t)q * 2112 + 576;
#pragma unroll
        for (int hh = 0; hh < 12; hh++) {
            f[hh * 128 + 2 * cp]     = aX[hh];
            f[hh * 128 + 2 * cp + 1] = aY[hh];
        }
    }
}

// ---------------- K7: inverse rigid, norms, feature assembly ----------------
__global__ void k_post(const float* __restrict__ rot, const float* __restrict__ trans) {
    int q = blockIdx.x;
    int t = threadIdx.x;   // 288
    float* f = g_feat + (size_t)q * 2112;
    const float* o6 = g_out6 + (size_t)q * 12 * 40;
    if (t < 96) {
        int h = t >> 3, p = t & 7;
        const float* g = o6 + h * 40 + 16 + p * 3;
        float g0 = g[0] - trans[q * 3 + 0];
        float g1 = g[1] - trans[q * 3 + 1];
        float g2 = g[2] - trans[q * 3 + 2];
        const float* R = rot + q * 9;
        float l0 = R[0] * g0 + R[3] * g1 + R[6] * g2;
        float l1 = R[1] * g0 + R[4] * g1 + R[7] * g2;
        float l2 = R[2] * g0 + R[5] * g1 + R[8] * g2;
        int idx = h * 8 + p;
        f[192 + idx] = l0;
        f[288 + idx] = l1;
        f[384 + idx] = l2;
        f[480 + idx] = sqrtf(fmaxf(l0 * l0 + l1 * l1 + l2 * l2, 1e-16f));
    } else if (t < 288) {
        int idx = t - 96;           // 0..191
        int h = idx >> 4, s = idx & 15;
        f[idx] = o6[h * 40 + s];
    }
}

// ---------------- K8: output GEMM 1024x384x2112 (32x64 tiles) ----------------
__global__ __launch_bounds__(256) void k_out(const float* __restrict__ wout,
                                             const float* __restrict__ bout,
                                             float* __restrict__ out) {
    __shared__ __align__(16) float As[16 * 32];
    __shared__ __align__(16) float Bs[16 * 64];
    int n0 = blockIdx.x * 64, m0 = blockIdx.y * 32;
    int t = threadIdx.x;
    int tx = t & 15, ty = t >> 4;
    float acc[2][4] = {};
    for (int kc = 0; kc < FEATD; kc += 16) {
#pragma unroll
        for (int r = 0; r < 2; r++) {
            int idx = t + r * 256;
            As[(idx & 15) * 32 + (idx >> 4)] =
                g_feat[(size_t)(m0 + (idx >> 4)) * FEATD + kc + (idx & 15)];
        }
#pragma unroll
        for (int r = 0; r < 4; r++) {
            int idx = t + r * 256;
            Bs[(idx >> 6) * 64 + (idx & 63)] =
                wout[(size_t)(kc + (idx >> 6)) * NCHd + n0 + (idx & 63)];
        }
        __syncthreads();
#pragma unroll
        for (int kk = 0; kk < 16; kk++) {
            float2 a2 = *(const float2*)(As + kk * 32 + ty * 2);
            float4 b4 = *(const float4*)(Bs + kk * 64 + tx * 4);
            ffma2(acc[0][0], acc[0][1], a2.x, a2.x, b4.x, b4.y);
            ffma2(acc[0][2], acc[0][3], a2.x, a2.x, b4.z, b4.w);
            ffma2(acc[1][0], acc[1][1], a2.y, a2.y, b4.x, b4.y);
            ffma2(acc[1][2], acc[1][3], a2.y, a2.y, b4.z, b4.w);
        }
        __syncthreads();
    }
#pragma unroll
    for (int i = 0; i < 2; i++) {
        int m = m0 + ty * 2 + i;
#pragma unroll
        for (int j = 0; j < 4; j++) {
            int n = n0 + tx * 4 + j;
            out[(size_t)m * NCHd + n] = acc[i][j] + bout[n];
        }
    }
}

// ---------------- launch ----------------
extern "C" void kernel_launch(void* const* d_in, const int* in_sizes, int n_in,
                              void* d_out, int out_size) {
    const float* inputs_1d = (const float*)d_in[0];
    const float* inputs_2d = (const float*)d_in[1];
    const float* mask      = (const float*)d_in[2];
    const float* rot       = (const float*)d_in[3];
    const float* trans     = (const float*)d_in[4];
    const float* rawpw     = (const float*)d_in[5];
    const float* wq_point  = (const float*)d_in[6];
    const float* bq_point  = (const float*)d_in[7];
    const float* wk_point  = (const float*)d_in[8];
    const float* bk_point  = (const float*)d_in[9];
    const float* wv_point  = (const float*)d_in[10];
    const float* bv_point  = (const float*)d_in[11];
    const float* wq_scalar = (const float*)d_in[12];
    const float* wk_scalar = (const float*)d_in[13];
    const float* wv_scalar = (const float*)d_in[14];
    const float* w2d       = (const float*)d_in[15];
    const float* b2d       = (const float*)d_in[16];
    const float* wout      = (const float*)d_in[17];
    const float* bout      = (const float*)d_in[18];
    float* out = (float*)d_out;

    const int smem_logits = (20480 + 192) * 4;   // 82688 B
    const int smem_final  = 12288 * 4;           // 49152 B
    cudaFuncSetAttribute(k_logits, cudaFuncAttributeMaxDynamicSharedMemorySize, smem_logits);
    cudaFuncSetAttribute(k_final,  cudaFuncAttributeMaxDynamicSharedMemorySize, smem_final);

    k_proj<<<dim3(PW / 64, Nn / 64), 256>>>(inputs_1d, wq_point, wk_point, wv_point,
                                            wq_scalar, wk_scalar, wv_scalar,
                                            bq_point, bk_point, bv_point);
    k_rotate<<<Nn, 256>>>(rot, trans);
    k_cheap<<<dim3(16, 16, 12), 256>>>(b2d, rawpw);
    k_logits<<<Nn, 256, smem_logits>>>(inputs_2d, w2d, mask);
    k_av<<<dim3(16, 12), 256>>>();
    k_final<<<Nn, 256, smem_final>>>(inputs_2d);
    k_post<<<Nn, 288>>>(rot, trans);
    k_out<<<dim3(NCHd / 64, Nn / 32), 256>>>(wout, bout, out);
}

// round 14
// speedup vs baseline: 1.6134x; 1.0213x over previous
#include <cuda_runtime.h>
#include <math.h>

#define Nn 1024
#define C1 384
#define C2 128
#define Hh 12
#define FEATD 2112
#define NCHd 384
#define PW 1152

// ---------------- scratch (device globals; no runtime allocation) ----------------
static __device__ float g_P[Nn * PW];               // projections (1024x1152)
static __device__ float g_qpt[Nn * Hh * 12];        // global q points (n,h,p*3+i)
static __device__ float g_kpt[Nn * Hh * 12];
static __device__ float g_vpt[Nn * Hh * 24];
static __device__ float g_qn[Nn * Hh];              // |q_pts|^2 per (n,h)
static __device__ float g_kn[Nn * Hh];
static __device__ float g_bufA[(size_t)Hh * Nn * Nn]; // (h,q,k): cheap logits, then attn
static __device__ float g_out6[Nn * Hh * 40];       // [v_scalar(16) | point(24)] per (q,h)
static __device__ float g_feat[Nn * FEATD];         // assembled feature rows

// packed fp32x2 FMA: d0 += a0*b0 ; d1 += a1*b1
__device__ __forceinline__ void ffma2(float& d0, float& d1, float a0, float a1,
                                      float b0, float b1) {
    asm("{\n\t"
        ".reg .b64 ra, rb, rc;\n\t"
        "mov.b64 ra, {%2, %3};\n\t"
        "mov.b64 rb, {%4, %5};\n\t"
        "mov.b64 rc, {%0, %1};\n\t"
        "fma.rn.f32x2 rc, ra, rb, rc;\n\t"
        "mov.b64 {%0, %1}, rc;\n\t"
        "}"
        : "+f"(d0), "+f"(d1)
        : "f"(a0), "f"(a1), "f"(b0), "f"(b1));
}

// source of the assembled projection matrix column `col`, row `c`
__device__ __forceinline__ float wsrc(const float* __restrict__ wqp, const float* __restrict__ wkp,
                                      const float* __restrict__ wvp, const float* __restrict__ wqs,
                                      const float* __restrict__ wks, const float* __restrict__ wvs,
                                      int c, int col) {
    if (col < 144)  return wqp[c * 144 + col];
    if (col < 288)  return wkp[c * 144 + col - 144];
    if (col < 576)  return wvp[c * 288 + col - 288];
    if (col < 768)  return wqs[c * 192 + col - 576];
    if (col < 960)  return wks[c * 192 + col - 768];
    return wvs[c * 192 + col - 960];
}

// ---------------- K1: projection GEMM 1024x1152x384 (weights assembled on the fly) ----------------
__global__ __launch_bounds__(256) void k_proj(const float* __restrict__ A,
                                              const float* __restrict__ wqp, const float* __restrict__ wkp,
                                              const float* __restrict__ wvp, const float* __restrict__ wqs,
                                              const float* __restrict__ wks, const float* __restrict__ wvs,
                                              const float* __restrict__ bqp, const float* __restrict__ bkp,
                                              const float* __restrict__ bvp) {
    __shared__ __align__(16) float As[16 * 64];
    __shared__ __align__(16) float Bs[16 * 64];
    int n0 = blockIdx.x * 64, m0 = blockIdx.y * 64;
    int t = threadIdx.x;
    int tx = t & 15, ty = t >> 4;
    float acc[4][4] = {};
    for (int kc = 0; kc < C1; kc += 16) {
#pragma unroll
        for (int r = 0; r < 4; r++) {
            int idx = t + r * 256;
            As[(idx & 15) * 64 + (idx >> 4)] = A[(m0 + (idx >> 4)) * C1 + kc + (idx & 15)];
            Bs[(idx >> 6) * 64 + (idx & 63)] =
                wsrc(wqp, wkp, wvp, wqs, wks, wvs, kc + (idx >> 6), n0 + (idx & 63));
        }
        __syncthreads();
#pragma unroll
        for (int kk = 0; kk < 16; kk++) {
            float4 a4 = *(const float4*)(As + kk * 64 + ty * 4);
            float4 b4 = *(const float4*)(Bs + kk * 64 + tx * 4);
            ffma2(acc[0][0], acc[0][1], a4.x, a4.x, b4.x, b4.y);
            ffma2(acc[0][2], acc[0][3], a4.x, a4.x, b4.z, b4.w);
            ffma2(acc[1][0], acc[1][1], a4.y, a4.y, b4.x, b4.y);
            ffma2(acc[1][2], acc[1][3], a4.y, a4.y, b4.z, b4.w);
            ffma2(acc[2][0], acc[2][1], a4.z, a4.z, b4.x, b4.y);
            ffma2(acc[2][2], acc[2][3], a4.z, a4.z, b4.z, b4.w);
            ffma2(acc[3][0], acc[3][1], a4.w, a4.w, b4.x, b4.y);
            ffma2(acc[3][2], acc[3][3], a4.w, a4.w, b4.z, b4.w);
        }
        __syncthreads();
    }
#pragma unroll
    for (int i = 0; i < 4; i++) {
        int m = m0 + ty * 4 + i;
#pragma unroll
        for (int j = 0; j < 4; j++) {
            int n = n0 + tx * 4 + j;
            float b = 0.f;
            if (n < 144)      b = bqp[n];
            else if (n < 288) b = bkp[n - 144];
            else if (n < 576) b = bvp[n - 288];
            float s = (n >= 576 && n < 768) ? 0.25f : 1.f;   // q_scalar * sqrt(1/16)
            g_P[m * PW + n] = acc[i][j] * s + b;
        }
    }
}

// ---------------- K2: rigid transform + point norms ----------------
__global__ void k_rotate(const float* __restrict__ rot, const float* __restrict__ trans) {
    int n = blockIdx.x;
    int t = threadIdx.x;
    __shared__ float R[9], T[3];
    if (t < 9) R[t] = rot[n * 9 + t];
    if (t < 3) T[t] = trans[n * 3 + t];
    __syncthreads();
    if (t < 192) {
        float l0, l1, l2;
        float* dst;
        if (t < 48) {
            int h = t >> 2, p = t & 3;
            const float* src = &g_P[n * PW + h * 12];
            l0 = src[p]; l1 = src[4 + p]; l2 = src[8 + p];
            dst = &g_qpt[(n * 12 + h) * 12 + p * 3];
        } else if (t < 96) {
            int u = t - 48; int h = u >> 2, p = u & 3;
            const float* src = &g_P[n * PW + 144 + h * 12];
            l0 = src[p]; l1 = src[4 + p]; l2 = src[8 + p];
            dst = &g_kpt[(n * 12 + h) * 12 + p * 3];
        } else {
            int u = t - 96; int h = u >> 3, p = u & 7;
            const float* src = &g_P[n * PW + 288 + h * 24];
            l0 = src[p]; l1 = src[8 + p]; l2 = src[16 + p];
            dst = &g_vpt[(n * 12 + h) * 24 + p * 3];
        }
        dst[0] = R[0] * l0 + R[1] * l1 + R[2] * l2 + T[0];
        dst[1] = R[3] * l0 + R[4] * l1 + R[5] * l2 + T[1];
        dst[2] = R[6] * l0 + R[7] * l1 + R[8] * l2 + T[2];
    }
    __syncthreads();
    if (t < 24) {
        int h = t % 12;
        const float* p = (t < 12) ? &g_qpt[(n * 12 + h) * 12] : &g_kpt[(n * 12 + h) * 12];
        float s = 0.f;
#pragma unroll
        for (int d = 0; d < 12; d++) s += p[d] * p[d];
        if (t < 12) g_qn[n * 12 + h] = s;
        else        g_kn[n * 12 + h] = s;
    }
}

// ---------------- K3: cheap logits (scalar QK + point + b2d) -> (h,q,k), 64x64 tiles ----------------
__global__ __launch_bounds__(256) void k_cheap(const float* __restrict__ b2d,
                                               const float* __restrict__ rawpw) {
    int k0 = blockIdx.x * 64, q0 = blockIdx.y * 64, h = blockIdx.z;
    __shared__ __align__(16) float qf[28 * 64];   // [c][r]
    __shared__ __align__(16) float kf[28 * 64];
    __shared__ float qn_[64], kn_[64];
    int t = threadIdx.x;
    float x = rawpw[h];
    float sp = (x > 20.f) ? x : log1pf(expf(x));
    float pw = sqrtf(1.f / 18.f) * sp;             // point_var = 4*9/2 = 18
    for (int u = t; u < 512; u += 256) {
        int r = u >> 3, g = u & 7;
        if (g < 4) {
            float4 v = *(const float4*)(&g_P[(size_t)(q0 + r) * PW + 576 + h * 16 + g * 4]);
            qf[(g * 4 + 0) * 64 + r] = v.x; qf[(g * 4 + 1) * 64 + r] = v.y;
            qf[(g * 4 + 2) * 64 + r] = v.z; qf[(g * 4 + 3) * 64 + r] = v.w;
            float4 w = *(const float4*)(&g_P[(size_t)(k0 + r) * PW + 768 + h * 16 + g * 4]);
            kf[(g * 4 + 0) * 64 + r] = w.x; kf[(g * 4 + 1) * 64 + r] = w.y;
            kf[(g * 4 + 2) * 64 + r] = w.z; kf[(g * 4 + 3) * 64 + r] = w.w;
        } else if (g < 7) {
            int pc = 16 + (g - 4) * 4;
            float4 v = *(const float4*)(&g_qpt[(((size_t)(q0 + r)) * 12 + h) * 12 + (g - 4) * 4]);
            qf[(pc + 0) * 64 + r] = v.x; qf[(pc + 1) * 64 + r] = v.y;
            qf[(pc + 2) * 64 + r] = v.z; qf[(pc + 3) * 64 + r] = v.w;
            float4 w = *(const float4*)(&g_kpt[(((size_t)(k0 + r)) * 12 + h) * 12 + (g - 4) * 4]);
            kf[(pc + 0) * 64 + r] = pw * w.x; kf[(pc + 1) * 64 + r] = pw * w.y;
            kf[(pc + 2) * 64 + r] = pw * w.z; kf[(pc + 3) * 64 + r] = pw * w.w;
        }
    }
    if (t < 64)            qn_[t] = 0.5f * pw * g_qn[(q0 + t) * 12 + h];
    else if (t < 128)      kn_[t - 64] = 0.5f * pw * g_kn[(k0 + t - 64) * 12 + h];
    __syncthreads();
    int tx = t & 15, ty = t >> 4;
    float acc[4][4] = {};
#pragma unroll
    for (int c = 0; c < 28; c++) {
        float4 a4 = *(const float4*)(qf + c * 64 + ty * 4);
        float4 b4 = *(const float4*)(kf + c * 64 + tx * 4);
        ffma2(acc[0][0], acc[0][1], a4.x, a4.x, b4.x, b4.y);
        ffma2(acc[0][2], acc[0][3], a4.x, a4.x, b4.z, b4.w);
        ffma2(acc[1][0], acc[1][1], a4.y, a4.y, b4.x, b4.y);
        ffma2(acc[1][2], acc[1][3], a4.y, a4.y, b4.z, b4.w);
        ffma2(acc[2][0], acc[2][1], a4.z, a4.z, b4.x, b4.y);
        ffma2(acc[2][2], acc[2][3], a4.z, a4.z, b4.z, b4.w);
        ffma2(acc[3][0], acc[3][1], a4.w, a4.w, b4.x, b4.y);
        ffma2(acc[3][2], acc[3][3], a4.w, a4.w, b4.z, b4.w);
    }
    float bb = b2d[h];
#pragma unroll
    for (int i = 0; i < 4; i++) {
        int q = q0 + ty * 4 + i;
#pragma unroll
        for (int j = 0; j < 4; j++) {
            int k = k0 + tx * 4 + j;
            g_bufA[((size_t)h << 20) + (size_t)q * 1024 + k] =
                acc[i][j] - qn_[ty * 4 + i] - kn_[tx * 4 + j] + bb;
        }
    }
}

// ---------------- K4: fused in2d projection + cheap + softmax + res_2d ----------------
// one block per q; 256 threads (2 CTAs/SM), thread t owns k in {t, t+256, t+512, t+768}.
// Pass 1: logits via row-pair interleaved smem staging (bank-conflict-free).
// Pass 2: res_2d re-reads the SAME in2d row (L2-resident) with attn staged in smem.
__global__ __launch_bounds__(256, 2) void k_attn2d(const float* __restrict__ in2d,
                                                   const float* __restrict__ w2d,
                                                   const float* __restrict__ mask) {
    extern __shared__ float dsm[];
    float* s2d = dsm;                 // 20480 floats; pass2: [0,12288) attn planes, [12288,16896) partials
    float* ws  = dsm + 20480;         // 192 floats (w2d chunk); reused as red[96]
    int q = blockIdx.x, t = threadIdx.x;
    float acc[4][12];
#pragma unroll
    for (int s = 0; s < 4; s++)
#pragma unroll
        for (int h = 0; h < 12; h++) acc[s][h] = 0.f;
    int kb[4];
#pragma unroll
    for (int s = 0; s < 4; s++) {
        int k = t + s * 256;
        kb[s] = 40 * (k >> 1) + 4 * (k & 1);
    }
    const float* inrow = in2d + (size_t)q * 131072;
    for (int c0 = 0; c0 < 128; c0 += 16) {
        if (t < 192) ws[t] = w2d[c0 * 12 + t];
#pragma unroll
        for (int it = 0; it < 16; it++) {
            int idx = t + it * 256;
            int row = idx >> 2, cq = idx & 3;
            float4 v = *(const float4*)(inrow + row * 128 + c0 + cq * 4);
            *(float4*)(s2d + 40 * (row >> 1) + 4 * (row & 1) + 8 * cq) = v;
        }
        __syncthreads();
#pragma unroll
        for (int c4 = 0; c4 < 4; c4++) {
            float4 a[4];
#pragma unroll
            for (int s = 0; s < 4; s++)
                a[s] = *(const float4*)(s2d + kb[s] + 8 * c4);
#pragma unroll
            for (int cc = 0; cc < 4; cc++) {
                const float* wb = ws + (c4 * 4 + cc) * 12;
                float4 b0 = *(const float4*)(wb);
                float4 b1 = *(const float4*)(wb + 4);
                float4 b2 = *(const float4*)(wb + 8);
#pragma unroll
                for (int s = 0; s < 4; s++) {
                    float av = (cc == 0) ? a[s].x : (cc == 1) ? a[s].y
                             : (cc == 2) ? a[s].z : a[s].w;
                    ffma2(acc[s][0],  acc[s][1],  av, av, b0.x, b0.y);
                    ffma2(acc[s][2],  acc[s][3],  av, av, b0.z, b0.w);
                    ffma2(acc[s][4],  acc[s][5],  av, av, b1.x, b1.y);
                    ffma2(acc[s][6],  acc[s][7],  av, av, b1.z, b1.w);
                    ffma2(acc[s][8],  acc[s][9],  av, av, b2.x, b2.y);
                    ffma2(acc[s][10], acc[s][11], av, av, b2.z, b2.w);
                }
            }
        }
        __syncthreads();
    }
    // ---- epilogue: add cheap, mask, scale ----
    float* red = ws;
    const float scale = 0.57735026918962576f;
    float mq = mask[q];
    float pen[4];
#pragma unroll
    for (int s = 0; s < 4; s++) pen[s] = -1e5f * (1.f - mq * mask[t + s * 256]);
#pragma unroll
    for (int h = 0; h < 12; h++) {
        size_t off = ((size_t)h << 20) + ((size_t)q << 10) + t;
#pragma unroll
        for (int s = 0; s < 4; s++) {
            float ch = g_bufA[off + s * 256];
            acc[s][h] = (acc[s][h] + ch + pen[s]) * scale;
        }
    }
    // ---- softmax over k (block-wide per h) ----
    int w = t >> 5, lane = t & 31;
#pragma unroll
    for (int h = 0; h < 12; h++) {
        float m = fmaxf(fmaxf(acc[0][h], acc[1][h]), fmaxf(acc[2][h], acc[3][h]));
#pragma unroll
        for (int s = 16; s; s >>= 1) m = fmaxf(m, __shfl_xor_sync(0xffffffffu, m, s));
        if (lane == 0) red[w * 12 + h] = m;
    }
    __syncthreads();
    float hm[12];
#pragma unroll
    for (int h = 0; h < 12; h++) {
        float m = red[h];
#pragma unroll
        for (int w2 = 1; w2 < 8; w2++) m = fmaxf(m, red[w2 * 12 + h]);
        hm[h] = m;
    }
    __syncthreads();
#pragma unroll
    for (int h = 0; h < 12; h++) {
        float s0 = 0.f;
#pragma unroll
        for (int s = 0; s < 4; s++) {
            acc[s][h] = __expf(acc[s][h] - hm[h]);
            s0 += acc[s][h];
        }
#pragma unroll
        for (int s = 16; s; s >>= 1) s0 += __shfl_xor_sync(0xffffffffu, s0, s);
        if (lane == 0) red[w * 12 + h] = s0;
    }
    __syncthreads();
    // normalize; write attn to g_bufA (for AV kernel) and to smem planes [h][1024]
#pragma unroll
    for (int h = 0; h < 12; h++) {
        float tot = red[h];
#pragma unroll
        for (int w2 = 1; w2 < 8; w2++) tot += red[w2 * 12 + h];
        float inv = 1.f / tot;
        size_t off = ((size_t)h << 20) + ((size_t)q << 10) + t;
#pragma unroll
        for (int s = 0; s < 4; s++) {
            float a = acc[s][h] * inv;
            g_bufA[off + s * 256] = a;
            s2d[h * 1024 + t + s * 256] = a;
        }
    }
    __syncthreads();
    // ---- pass 2: res_2d, re-reading the same in2d row (L2-hot) ----
    {
        int cp = t & 63, ks = t >> 6;
        float aX[12], aY[12];
#pragma unroll
        for (int u = 0; u < 12; u++) { aX[u] = 0.f; aY[u] = 0.f; }
        const float* base = inrow + cp * 2;
        int kbase = ks * 256;
#pragma unroll 2
        for (int kt = 0; kt < 64; kt++) {
            int k0 = kbase + kt * 4;
            float2 v0 = *(const float2*)(base + (size_t)(k0 + 0) * 128);
            float2 v1 = *(const float2*)(base + (size_t)(k0 + 1) * 128);
            float2 v2 = *(const float2*)(base + (size_t)(k0 + 2) * 128);
            float2 v3 = *(const float2*)(base + (size_t)(k0 + 3) * 128);
#pragma unroll
            for (int u = 0; u < 6; u++) {
                float4 a0 = *(const float4*)(s2d + (2 * u) * 1024 + k0);
                float4 a1 = *(const float4*)(s2d + (2 * u + 1) * 1024 + k0);
                ffma2(aX[2 * u], aX[2 * u + 1], a0.x, a1.x, v0.x, v0.x);
                ffma2(aY[2 * u], aY[2 * u + 1], a0.x, a1.x, v0.y, v0.y);
                ffma2(aX[2 * u], aX[2 * u + 1], a0.y, a1.y, v1.x, v1.x);
                ffma2(aY[2 * u], aY[2 * u + 1], a0.y, a1.y, v1.y, v1.y);
                ffma2(aX[2 * u], aX[2 * u + 1], a0.z, a1.z, v2.x, v2.x);
                ffma2(aY[2 * u], aY[2 * u + 1], a0.z, a1.z, v2.y, v2.y);
                ffma2(aX[2 * u], aX[2 * u + 1], a0.w, a1.w, v3.x, v3.x);
                ffma2(aY[2 * u], aY[2 * u + 1], a0.w, a1.w, v3.y, v3.y);
            }
        }
        __syncthreads();   // everyone done reading attn planes
        float* part = s2d + 12288;
        if (ks != 0) {
            float* d = part + (size_t)((ks - 1) * 64 + cp) * 24;
#pragma unroll
            for (int u = 0; u < 12; u++) { d[u] = aX[u]; d[12 + u] = aY[u]; }
        }
        __syncthreads();
        if (ks == 0) {
#pragma unroll
            for (int s = 0; s < 3; s++) {
                const float* d = part + (size_t)(s * 64 + cp) * 24;
#pragma unroll
                for (int u = 0; u < 12; u++) { aX[u] += d[u]; aY[u] += d[12 + u]; }
            }
            float* f = g_feat + (size_t)q * 2112 + 576;
#pragma unroll
            for (int hh = 0; hh < 12; hh++) {
                f[hh * 128 + 2 * cp]     = aX[hh];
                f[hh * 128 + 2 * cp + 1] = aY[hh];
            }
        }
    }
}

// ---------------- K5: AV (scalar + point values), per-head GEMM ----------------
__global__ __launch_bounds__(256) void k_av() {
    __shared__ __align__(16) float As[64 * 64];   // [kk][r]
    __shared__ float Bs[64 * 48];
    int h = blockIdx.y;
    int q0 = blockIdx.x * 64;
    int t = threadIdx.x;
    int tx = t & 15, ty = t >> 4;
    float acc[4][3] = {};
    for (int k0 = 0; k0 < 1024; k0 += 64) {
        const float* ab = g_bufA + ((size_t)h << 20) + (size_t)q0 * 1024 + k0;
        for (int idx = t; idx < 1024; idx += 256) {
            int r = idx >> 4, c4 = (idx & 15) * 4;
            float4 v = *(const float4*)(ab + (size_t)r * 1024 + c4);
            As[(c4 + 0) * 64 + r] = v.x; As[(c4 + 1) * 64 + r] = v.y;
            As[(c4 + 2) * 64 + r] = v.z; As[(c4 + 3) * 64 + r] = v.w;
        }
        for (int idx = t; idx < 64 * 48; idx += 256) {
            int kk = idx / 48, col = idx - kk * 48;
            int k = k0 + kk;
            float v = 0.f;
            if (col < 16)       v = g_P[(size_t)k * 1152 + 960 + h * 16 + col];
            else if (col < 40)  v = g_vpt[((size_t)k * 12 + h) * 24 + (col - 16)];
            Bs[kk * 48 + col] = v;
        }
        __syncthreads();
#pragma unroll 8
        for (int kk = 0; kk < 64; kk++) {
            float4 a4 = *(const float4*)(As + kk * 64 + ty * 4);
            float b0 = Bs[kk * 48 + tx * 3 + 0];
            float b1 = Bs[kk * 48 + tx * 3 + 1];
            float b2 = Bs[kk * 48 + tx * 3 + 2];
            ffma2(acc[0][0], acc[1][0], a4.x, a4.y, b0, b0);
            ffma2(acc[2][0], acc[3][0], a4.z, a4.w, b0, b0);
            ffma2(acc[0][1], acc[1][1], a4.x, a4.y, b1, b1);
            ffma2(acc[2][1], acc[3][1], a4.z, a4.w, b1, b1);
            ffma2(acc[0][2], acc[1][2], a4.x, a4.y, b2, b2);
            ffma2(acc[2][2], acc[3][2], a4.z, a4.w, b2, b2);
        }
        __syncthreads();
    }
#pragma unroll
    for (int i = 0; i < 4; i++) {
        int q = q0 + ty * 4 + i;
#pragma unroll
        for (int j = 0; j < 3; j++) {
            int col = tx * 3 + j;
            if (col < 40) g_out6[((size_t)q * 12 + h) * 40 + col] = acc[i][j];
        }
    }
}

// ---------------- K6: inverse rigid, norms, feature assembly ----------------
__global__ void k_post(const float* __restrict__ rot, const float* __restrict__ trans) {
    int q = blockIdx.x;
    int t = threadIdx.x;   // 288
    float* f = g_feat + (size_t)q * 2112;
    const float* o6 = g_out6 + (size_t)q * 12 * 40;
    if (t < 96) {
        int h = t >> 3, p = t & 7;
        const float* g = o6 + h * 40 + 16 + p * 3;
        float g0 = g[0] - trans[q * 3 + 0];
        float g1 = g[1] - trans[q * 3 + 1];
        float g2 = g[2] - trans[q * 3 + 2];
        const float* R = rot + q * 9;
        float l0 = R[0] * g0 + R[3] * g1 + R[6] * g2;
        float l1 = R[1] * g0 + R[4] * g1 + R[7] * g2;
        float l2 = R[2] * g0 + R[5] * g1 + R[8] * g2;
        int idx = h * 8 + p;
        f[192 + idx] = l0;
        f[288 + idx] = l1;
        f[384 + idx] = l2;
        f[480 + idx] = sqrtf(fmaxf(l0 * l0 + l1 * l1 + l2 * l2, 1e-16f));
    } else if (t < 288) {
        int idx = t - 96;           // 0..191
        int h = idx >> 4, s = idx & 15;
        f[idx] = o6[h * 40 + s];
    }
}

// ---------------- K7: output GEMM 1024x384x2112 (32x64 tiles) ----------------
__global__ __launch_bounds__(256) void k_out(const float* __restrict__ wout,
                                             const float* __restrict__ bout,
                                             float* __restrict__ out) {
    __shared__ __align__(16) float As[16 * 32];
    __shared__ __align__(16) float Bs[16 * 64];
    int n0 = blockIdx.x * 64, m0 = blockIdx.y * 32;
    int t = threadIdx.x;
    int tx = t & 15, ty = t >> 4;
    float acc[2][4] = {};
    for (int kc = 0; kc < FEATD; kc += 16) {
#pragma unroll
        for (int r = 0; r < 2; r++) {
            int idx = t + r * 256;
            As[(idx & 15) * 32 + (idx >> 4)] =
                g_feat[(size_t)(m0 + (idx >> 4)) * FEATD + kc + (idx & 15)];
        }
#pragma unroll
        for (int r = 0; r < 4; r++) {
            int idx = t + r * 256;
            Bs[(idx >> 6) * 64 + (idx & 63)] =
                wout[(size_t)(kc + (idx >> 6)) * NCHd + n0 + (idx & 63)];
        }
        __syncthreads();
#pragma unroll
        for (int kk = 0; kk < 16; kk++) {
            float2 a2 = *(const float2*)(As + kk * 32 + ty * 2);
            float4 b4 = *(const float4*)(Bs + kk * 64 + tx * 4);
            ffma2(acc[0][0], acc[0][1], a2.x, a2.x, b4.x, b4.y);
            ffma2(acc[0][2], acc[0][3], a2.x, a2.x, b4.z, b4.w);
            ffma2(acc[1][0], acc[1][1], a2.y, a2.y, b4.x, b4.y);
            ffma2(acc[1][2], acc[1][3], a2.y, a2.y, b4.z, b4.w);
        }
        __syncthreads();
    }
#pragma unroll
    for (int i = 0; i < 2; i++) {
        int m = m0 + ty * 2 + i;
#pragma unroll
        for (int j = 0; j < 4; j++) {
            int n = n0 + tx * 4 + j;
            out[(size_t)m * NCHd + n] = acc[i][j] + bout[n];
        }
    }
}

// ---------------- launch ----------------
extern "C" void kernel_launch(void* const* d_in, const int* in_sizes, int n_in,
                              void* d_out, int out_size) {
    const float* inputs_1d = (const float*)d_in[0];
    const float* inputs_2d = (const float*)d_in[1];
    const float* mask      = (const float*)d_in[2];
    const float* rot       = (const float*)d_in[3];
    const float* trans     = (const float*)d_in[4];
    const float* rawpw     = (const float*)d_in[5];
    const float* wq_point  = (const float*)d_in[6];
    const float* bq_point  = (const float*)d_in[7];
    const float* wk_point  = (const float*)d_in[8];
    const float* bk_point  = (const float*)d_in[9];
    const float* wv_point  = (const float*)d_in[10];
    const float* bv_point  = (const float*)d_in[11];
    const float* wq_scalar = (const float*)d_in[12];
    const float* wk_scalar = (const float*)d_in[13];
    const float* wv_scalar = (const float*)d_in[14];
    const float* w2d       = (const float*)d_in[15];
    const float* b2d       = (const float*)d_in[16];
    const float* wout      = (const float*)d_in[17];
    const float* bout      = (const float*)d_in[18];
    float* out = (float*)d_out;

    const int smem_attn2d = (20480 + 192) * 4;   // 82688 B
    cudaFuncSetAttribute(k_attn2d, cudaFuncAttributeMaxDynamicSharedMemorySize, smem_attn2d);

    k_proj<<<dim3(PW / 64, Nn / 64), 256>>>(inputs_1d, wq_point, wk_point, wv_point,
                                            wq_scalar, wk_scalar, wv_scalar,
                                            bq_point, bk_point, bv_point);
    k_rotate<<<Nn, 256>>>(rot, trans);
    k_cheap<<<dim3(16, 16, 12), 256>>>(b2d, rawpw);
    k_attn2d<<<Nn, 256, smem_attn2d>>>(inputs_2d, w2d, mask);
    k_av<<<dim3(16, 12), 256>>>();
    k_post<<<Nn, 288>>>(rot, trans);
    k_out<<<dim3(NCHd / 64, Nn / 32), 256>>>(wout, bout, out);
}

// round 15
// speedup vs baseline: 1.7002x; 1.0538x over previous
#include <cuda_runtime.h>
#include <math.h>

#define Nn 1024
#define C1 384
#define C2 128
#define Hh 12
#define FEATD 2112
#define NCHd 384
#define PW 1152
#define APLANE 1052   // swizzled attn plane stride (floats)

// ---------------- scratch (device globals; no runtime allocation) ----------------
static __device__ float g_P[Nn * PW];               // projections (1024x1152)
static __device__ float g_qpt[Nn * Hh * 12];        // global q points (n,h,p*3+i)
static __device__ float g_kpt[Nn * Hh * 12];
static __device__ float g_vcat[Nn * Hh * 40];       // packed V: [k][h][40] = scalar16|point24
static __device__ float g_qn[Nn * Hh];              // |q_pts|^2 per (n,h)
static __device__ float g_kn[Nn * Hh];
static __device__ float g_bufA[(size_t)Hh * Nn * Nn]; // (h,q,k): cheap logits, then attn
static __device__ float g_out6[Nn * Hh * 40];       // [v_scalar(16) | point(24)] per (q,h)
static __device__ float g_feat[Nn * FEATD];         // assembled feature rows

// packed fp32x2 FMA: d0 += a0*b0 ; d1 += a1*b1
__device__ __forceinline__ void ffma2(float& d0, float& d1, float a0, float a1,
                                      float b0, float b1) {
    asm("{\n\t"
        ".reg .b64 ra, rb, rc;\n\t"
        "mov.b64 ra, {%2, %3};\n\t"
        "mov.b64 rb, {%4, %5};\n\t"
        "mov.b64 rc, {%0, %1};\n\t"
        "fma.rn.f32x2 rc, ra, rb, rc;\n\t"
        "mov.b64 {%0, %1}, rc;\n\t"
        "}"
        : "+f"(d0), "+f"(d1)
        : "f"(a0), "f"(a1), "f"(b0), "f"(b1));
}

__device__ __forceinline__ int asw(int k) { return k + 4 * (k >> 7); }   // attn plane swizzle

// source of the assembled projection matrix column `col`, row `c`
__device__ __forceinline__ float wsrc(const float* __restrict__ wqp, const float* __restrict__ wkp,
                                      const float* __restrict__ wvp, const float* __restrict__ wqs,
                                      const float* __restrict__ wks, const float* __restrict__ wvs,
                                      int c, int col) {
    if (col < 144)  return wqp[c * 144 + col];
    if (col < 288)  return wkp[c * 144 + col - 144];
    if (col < 576)  return wvp[c * 288 + col - 288];
    if (col < 768)  return wqs[c * 192 + col - 576];
    if (col < 960)  return wks[c * 192 + col - 768];
    return wvs[c * 192 + col - 960];
}

// ---------------- K1: projection GEMM 1024x1152x384 ----------------
__global__ __launch_bounds__(256) void k_proj(const float* __restrict__ A,
                                              const float* __restrict__ wqp, const float* __restrict__ wkp,
                                              const float* __restrict__ wvp, const float* __restrict__ wqs,
                                              const float* __restrict__ wks, const float* __restrict__ wvs,
                                              const float* __restrict__ bqp, const float* __restrict__ bkp,
                                              const float* __restrict__ bvp) {
    __shared__ __align__(16) float As[16 * 64];
    __shared__ __align__(16) float Bs[16 * 64];
    int n0 = blockIdx.x * 64, m0 = blockIdx.y * 64;
    int t = threadIdx.x;
    int tx = t & 15, ty = t >> 4;
    float acc[4][4] = {};
    for (int kc = 0; kc < C1; kc += 16) {
#pragma unroll
        for (int r = 0; r < 4; r++) {
            int idx = t + r * 256;
            As[(idx & 15) * 64 + (idx >> 4)] = A[(m0 + (idx >> 4)) * C1 + kc + (idx & 15)];
            Bs[(idx >> 6) * 64 + (idx & 63)] =
                wsrc(wqp, wkp, wvp, wqs, wks, wvs, kc + (idx >> 6), n0 + (idx & 63));
        }
        __syncthreads();
#pragma unroll
        for (int kk = 0; kk < 16; kk++) {
            float4 a4 = *(const float4*)(As + kk * 64 + ty * 4);
            float4 b4 = *(const float4*)(Bs + kk * 64 + tx * 4);
            ffma2(acc[0][0], acc[0][1], a4.x, a4.x, b4.x, b4.y);
            ffma2(acc[0][2], acc[0][3], a4.x, a4.x, b4.z, b4.w);
            ffma2(acc[1][0], acc[1][1], a4.y, a4.y, b4.x, b4.y);
            ffma2(acc[1][2], acc[1][3], a4.y, a4.y, b4.z, b4.w);
            ffma2(acc[2][0], acc[2][1], a4.z, a4.z, b4.x, b4.y);
            ffma2(acc[2][2], acc[2][3], a4.z, a4.z, b4.z, b4.w);
            ffma2(acc[3][0], acc[3][1], a4.w, a4.w, b4.x, b4.y);
            ffma2(acc[3][2], acc[3][3], a4.w, a4.w, b4.z, b4.w);
        }
        __syncthreads();
    }
#pragma unroll
    for (int i = 0; i < 4; i++) {
        int m = m0 + ty * 4 + i;
#pragma unroll
        for (int j = 0; j < 4; j++) {
            int n = n0 + tx * 4 + j;
            float b = 0.f;
            if (n < 144)      b = bqp[n];
            else if (n < 288) b = bkp[n - 144];
            else if (n < 576) b = bvp[n - 288];
            float s = (n >= 576 && n < 768) ? 0.25f : 1.f;   // q_scalar * sqrt(1/16)
            g_P[m * PW + n] = acc[i][j] * s + b;
        }
    }
}

// ---------------- K2: rigid transform + point norms + packed V ----------------
__global__ void k_rotate(const float* __restrict__ rot, const float* __restrict__ trans) {
    int n = blockIdx.x;
    int t = threadIdx.x;
    __shared__ float R[9], T[3];
    if (t < 9) R[t] = rot[n * 9 + t];
    if (t < 3) T[t] = trans[n * 3 + t];
    __syncthreads();
    if (t < 192) {
        float l0, l1, l2;
        float* dst;
        if (t < 48) {
            int h = t >> 2, p = t & 3;
            const float* src = &g_P[n * PW + h * 12];
            l0 = src[p]; l1 = src[4 + p]; l2 = src[8 + p];
            dst = &g_qpt[(n * 12 + h) * 12 + p * 3];
        } else if (t < 96) {
            int u = t - 48; int h = u >> 2, p = u & 3;
            const float* src = &g_P[n * PW + 144 + h * 12];
            l0 = src[p]; l1 = src[4 + p]; l2 = src[8 + p];
            dst = &g_kpt[(n * 12 + h) * 12 + p * 3];
        } else {
            int u = t - 96; int h = u >> 3, p = u & 7;
            const float* src = &g_P[n * PW + 288 + h * 24];
            l0 = src[p]; l1 = src[8 + p]; l2 = src[16 + p];
            dst = &g_vcat[(size_t)n * 480 + h * 40 + 16 + p * 3];
        }
        dst[0] = R[0] * l0 + R[1] * l1 + R[2] * l2 + T[0];
        dst[1] = R[3] * l0 + R[4] * l1 + R[5] * l2 + T[1];
        dst[2] = R[6] * l0 + R[7] * l1 + R[8] * l2 + T[2];
    }
    // pack v_scalar into g_vcat
    if (t < 192) {
        int h = t >> 4, s = t & 15;
        g_vcat[(size_t)n * 480 + h * 40 + s] = g_P[n * PW + 960 + h * 16 + s];
    }
    __syncthreads();
    if (t < 24) {
        int h = t % 12;
        const float* p = (t < 12) ? &g_qpt[(n * 12 + h) * 12] : &g_kpt[(n * 12 + h) * 12];
        float s = 0.f;
#pragma unroll
        for (int d = 0; d < 12; d++) s += p[d] * p[d];
        if (t < 12) g_qn[n * 12 + h] = s;
        else        g_kn[n * 12 + h] = s;
    }
}

// ---------------- K3: cheap logits -> (h,q,k), 64x64 tiles ----------------
__global__ __launch_bounds__(256) void k_cheap(const float* __restrict__ b2d,
                                               const float* __restrict__ rawpw) {
    int k0 = blockIdx.x * 64, q0 = blockIdx.y * 64, h = blockIdx.z;
    __shared__ __align__(16) float qf[28 * 64];   // [c][r]
    __shared__ __align__(16) float kf[28 * 64];
    __shared__ float qn_[64], kn_[64];
    int t = threadIdx.x;
    float x = rawpw[h];
    float sp = (x > 20.f) ? x : log1pf(expf(x));
    float pw = sqrtf(1.f / 18.f) * sp;             // point_var = 4*9/2 = 18
    for (int u = t; u < 512; u += 256) {
        int r = u >> 3, g = u & 7;
        if (g < 4) {
            float4 v = *(const float4*)(&g_P[(size_t)(q0 + r) * PW + 576 + h * 16 + g * 4]);
            qf[(g * 4 + 0) * 64 + r] = v.x; qf[(g * 4 + 1) * 64 + r] = v.y;
            qf[(g * 4 + 2) * 64 + r] = v.z; qf[(g * 4 + 3) * 64 + r] = v.w;
            float4 w = *(const float4*)(&g_P[(size_t)(k0 + r) * PW + 768 + h * 16 + g * 4]);
            kf[(g * 4 + 0) * 64 + r] = w.x; kf[(g * 4 + 1) * 64 + r] = w.y;
            kf[(g * 4 + 2) * 64 + r] = w.z; kf[(g * 4 + 3) * 64 + r] = w.w;
        } else if (g < 7) {
            int pc = 16 + (g - 4) * 4;
            float4 v = *(const float4*)(&g_qpt[(((size_t)(q0 + r)) * 12 + h) * 12 + (g - 4) * 4]);
            qf[(pc + 0) * 64 + r] = v.x; qf[(pc + 1) * 64 + r] = v.y;
            qf[(pc + 2) * 64 + r] = v.z; qf[(pc + 3) * 64 + r] = v.w;
            float4 w = *(const float4*)(&g_kpt[(((size_t)(k0 + r)) * 12 + h) * 12 + (g - 4) * 4]);
            kf[(pc + 0) * 64 + r] = pw * w.x; kf[(pc + 1) * 64 + r] = pw * w.y;
            kf[(pc + 2) * 64 + r] = pw * w.z; kf[(pc + 3) * 64 + r] = pw * w.w;
        }
    }
    if (t < 64)            qn_[t] = 0.5f * pw * g_qn[(q0 + t) * 12 + h];
    else if (t < 128)      kn_[t - 64] = 0.5f * pw * g_kn[(k0 + t - 64) * 12 + h];
    __syncthreads();
    int tx = t & 15, ty = t >> 4;
    float acc[4][4] = {};
#pragma unroll
    for (int c = 0; c < 28; c++) {
        float4 a4 = *(const float4*)(qf + c * 64 + ty * 4);
        float4 b4 = *(const float4*)(kf + c * 64 + tx * 4);
        ffma2(acc[0][0], acc[0][1], a4.x, a4.x, b4.x, b4.y);
        ffma2(acc[0][2], acc[0][3], a4.x, a4.x, b4.z, b4.w);
        ffma2(acc[1][0], acc[1][1], a4.y, a4.y, b4.x, b4.y);
        ffma2(acc[1][2], acc[1][3], a4.y, a4.y, b4.z, b4.w);
        ffma2(acc[2][0], acc[2][1], a4.z, a4.z, b4.x, b4.y);
        ffma2(acc[2][2], acc[2][3], a4.z, a4.z, b4.z, b4.w);
        ffma2(acc[3][0], acc[3][1], a4.w, a4.w, b4.x, b4.y);
        ffma2(acc[3][2], acc[3][3], a4.w, a4.w, b4.z, b4.w);
    }
    float bb = b2d[h];
#pragma unroll
    for (int i = 0; i < 4; i++) {
        int q = q0 + ty * 4 + i;
#pragma unroll
        for (int j = 0; j < 4; j++) {
            int k = k0 + tx * 4 + j;
            g_bufA[((size_t)h << 20) + (size_t)q * 1024 + k] =
                acc[i][j] - qn_[ty * 4 + i] - kn_[tx * 4 + j] + bb;
        }
    }
}

// ---------------- K4: fused in2d projection + cheap + softmax + res_2d ----------------
__global__ __launch_bounds__(256, 2) void k_attn2d(const float* __restrict__ in2d,
                                                   const float* __restrict__ w2d,
                                                   const float* __restrict__ mask) {
    extern __shared__ float dsm[];
    float* s2d = dsm;                 // pass1: 20480-float staging; pass2: attn planes [12][APLANE]
    float* ws  = dsm + 20480;         // 192 floats (w2d chunk); reused as red[96]
    int q = blockIdx.x, t = threadIdx.x;
    float acc[4][12];
#pragma unroll
    for (int s = 0; s < 4; s++)
#pragma unroll
        for (int h = 0; h < 12; h++) acc[s][h] = 0.f;
    int kb[4];
#pragma unroll
    for (int s = 0; s < 4; s++) {
        int k = t + s * 256;
        kb[s] = 40 * (k >> 1) + 4 * (k & 1);
    }
    const float* inrow = in2d + (size_t)q * 131072;
    for (int c0 = 0; c0 < 128; c0 += 16) {
        if (t < 192) ws[t] = w2d[c0 * 12 + t];
#pragma unroll
        for (int it = 0; it < 16; it++) {
            int idx = t + it * 256;
            int row = idx >> 2, cq = idx & 3;
            float4 v = *(const float4*)(inrow + row * 128 + c0 + cq * 4);
            *(float4*)(s2d + 40 * (row >> 1) + 4 * (row & 1) + 8 * cq) = v;
        }
        __syncthreads();
#pragma unroll
        for (int c4 = 0; c4 < 4; c4++) {
            float4 a[4];
#pragma unroll
            for (int s = 0; s < 4; s++)
                a[s] = *(const float4*)(s2d + kb[s] + 8 * c4);
#pragma unroll
            for (int cc = 0; cc < 4; cc++) {
                const float* wb = ws + (c4 * 4 + cc) * 12;
                float4 b0 = *(const float4*)(wb);
                float4 b1 = *(const float4*)(wb + 4);
                float4 b2 = *(const float4*)(wb + 8);
#pragma unroll
                for (int s = 0; s < 4; s++) {
                    float av = (cc == 0) ? a[s].x : (cc == 1) ? a[s].y
                             : (cc == 2) ? a[s].z : a[s].w;
                    ffma2(acc[s][0],  acc[s][1],  av, av, b0.x, b0.y);
                    ffma2(acc[s][2],  acc[s][3],  av, av, b0.z, b0.w);
                    ffma2(acc[s][4],  acc[s][5],  av, av, b1.x, b1.y);
                    ffma2(acc[s][6],  acc[s][7],  av, av, b1.z, b1.w);
                    ffma2(acc[s][8],  acc[s][9],  av, av, b2.x, b2.y);
                    ffma2(acc[s][10], acc[s][11], av, av, b2.z, b2.w);
                }
            }
        }
        __syncthreads();
    }
    // ---- epilogue: add cheap, mask, scale ----
    float* red = ws;
    const float scale = 0.57735026918962576f;
    float mq = mask[q];
    float pen[4];
#pragma unroll
    for (int s = 0; s < 4; s++) pen[s] = -1e5f * (1.f - mq * mask[t + s * 256]);
#pragma unroll
    for (int h = 0; h < 12; h++) {
        size_t off = ((size_t)h << 20) + ((size_t)q << 10) + t;
#pragma unroll
        for (int s = 0; s < 4; s++) {
            float ch = g_bufA[off + s * 256];
            acc[s][h] = (acc[s][h] + ch + pen[s]) * scale;
        }
    }
    // ---- softmax over k (block-wide per h) ----
    int w = t >> 5, lane = t & 31;
#pragma unroll
    for (int h = 0; h < 12; h++) {
        float m = fmaxf(fmaxf(acc[0][h], acc[1][h]), fmaxf(acc[2][h], acc[3][h]));
#pragma unroll
        for (int s = 16; s; s >>= 1) m = fmaxf(m, __shfl_xor_sync(0xffffffffu, m, s));
        if (lane == 0) red[w * 12 + h] = m;
    }
    __syncthreads();
    float hm[12];
#pragma unroll
    for (int h = 0; h < 12; h++) {
        float m = red[h];
#pragma unroll
        for (int w2 = 1; w2 < 8; w2++) m = fmaxf(m, red[w2 * 12 + h]);
        hm[h] = m;
    }
    __syncthreads();
#pragma unroll
    for (int h = 0; h < 12; h++) {
        float s0 = 0.f;
#pragma unroll
        for (int s = 0; s < 4; s++) {
            acc[s][h] = __expf(acc[s][h] - hm[h]);
            s0 += acc[s][h];
        }
#pragma unroll
        for (int s = 16; s; s >>= 1) s0 += __shfl_xor_sync(0xffffffffu, s0, s);
        if (lane == 0) red[w * 12 + h] = s0;
    }
    __syncthreads();
    // normalize; write attn to g_bufA (for AV kernel) and to swizzled smem planes
#pragma unroll
    for (int h = 0; h < 12; h++) {
        float tot = red[h];
#pragma unroll
        for (int w2 = 1; w2 < 8; w2++) tot += red[w2 * 12 + h];
        float inv = 1.f / tot;
        size_t off = ((size_t)h << 20) + ((size_t)q << 10) + t;
#pragma unroll
        for (int s = 0; s < 4; s++) {
            float a = acc[s][h] * inv;
            int k = t + s * 256;
            g_bufA[off + s * 256] = a;
            s2d[h * APLANE + asw(k)] = a;
        }
    }
    __syncthreads();
    // ---- pass 2: res_2d, thread = (col group of 4) x (k slice of 128), shuffle reduce ----
    {
        int g  = w * 4 + (lane & 3);       // 0..31 -> cols [4g, 4g+4)
        int sl = lane >> 2;                // 0..7  -> k in [128*sl, 128*sl+128)
        float rX[4][6], rY[4][6];          // [col][h-pair] packed f32x2 halves
        float r2[4][12];
#pragma unroll
        for (int c = 0; c < 4; c++)
#pragma unroll
            for (int u = 0; u < 12; u++) r2[c][u] = 0.f;
        const float* base = inrow + g * 4;
        int kbase = sl * 128;
        for (int kt = 0; kt < 32; kt++) {
            int k0 = kbase + kt * 4;
            float4 d0 = *(const float4*)(base + (size_t)(k0 + 0) * 128);
            float4 d1 = *(const float4*)(base + (size_t)(k0 + 1) * 128);
            float4 d2 = *(const float4*)(base + (size_t)(k0 + 2) * 128);
            float4 d3 = *(const float4*)(base + (size_t)(k0 + 3) * 128);
            int sk = asw(k0);
#pragma unroll
            for (int hp = 0; hp < 6; hp++) {
                float4 a0 = *(const float4*)(s2d + (2 * hp) * APLANE + sk);
                float4 a1 = *(const float4*)(s2d + (2 * hp + 1) * APLANE + sk);
                ffma2(r2[0][2*hp], r2[0][2*hp+1], a0.x, a1.x, d0.x, d0.x);
                ffma2(r2[1][2*hp], r2[1][2*hp+1], a0.x, a1.x, d0.y, d0.y);
                ffma2(r2[2][2*hp], r2[2][2*hp+1], a0.x, a1.x, d0.z, d0.z);
                ffma2(r2[3][2*hp], r2[3][2*hp+1], a0.x, a1.x, d0.w, d0.w);
                ffma2(r2[0][2*hp], r2[0][2*hp+1], a0.y, a1.y, d1.x, d1.x);
                ffma2(r2[1][2*hp], r2[1][2*hp+1], a0.y, a1.y, d1.y, d1.y);
                ffma2(r2[2][2*hp], r2[2][2*hp+1], a0.y, a1.y, d1.z, d1.z);
                ffma2(r2[3][2*hp], r2[3][2*hp+1], a0.y, a1.y, d1.w, d1.w);
                ffma2(r2[0][2*hp], r2[0][2*hp+1], a0.z, a1.z, d2.x, d2.x);
                ffma2(r2[1][2*hp], r2[1][2*hp+1], a0.z, a1.z, d2.y, d2.y);
                ffma2(r2[2][2*hp], r2[2][2*hp+1], a0.z, a1.z, d2.z, d2.z);
                ffma2(r2[3][2*hp], r2[3][2*hp+1], a0.z, a1.z, d2.w, d2.w);
                ffma2(r2[0][2*hp], r2[0][2*hp+1], a0.w, a1.w, d3.x, d3.x);
                ffma2(r2[1][2*hp], r2[1][2*hp+1], a0.w, a1.w, d3.y, d3.y);
                ffma2(r2[2][2*hp], r2[2][2*hp+1], a0.w, a1.w, d3.z, d3.z);
                ffma2(r2[3][2*hp], r2[3][2*hp+1], a0.w, a1.w, d3.w, d3.w);
            }
        }
        // reduce over the 8 k-slices (lane bits 2..4)
#pragma unroll
        for (int c = 0; c < 4; c++)
#pragma unroll
            for (int u = 0; u < 12; u++) {
                float v = r2[c][u];
                v += __shfl_xor_sync(0xffffffffu, v, 4);
                v += __shfl_xor_sync(0xffffffffu, v, 8);
                v += __shfl_xor_sync(0xffffffffu, v, 16);
                r2[c][u] = v;
            }
        if (sl == 0) {
            float* f = g_feat + (size_t)q * 2112 + 576;
#pragma unroll
            for (int h = 0; h < 12; h++) {
                float4 v = make_float4(r2[0][h], r2[1][h], r2[2][h], r2[3][h]);
                *(float4*)(f + h * 128 + g * 4) = v;
            }
        }
        (void)rX; (void)rY;
    }
}

// ---------------- K5: AV (scalar + point values), per-head GEMM ----------------
__global__ __launch_bounds__(256) void k_av() {
    __shared__ __align__(16) float As[64 * 64];   // [kk][r]
    __shared__ __align__(16) float Bs[64 * 40 + 16];
    int h = blockIdx.y;
    int q0 = blockIdx.x * 64;
    int t = threadIdx.x;
    int tx = t & 15, ty = t >> 4;
    float acc[4][3] = {};
    for (int k0 = 0; k0 < 1024; k0 += 64) {
        const float* ab = g_bufA + ((size_t)h << 20) + (size_t)q0 * 1024 + k0;
        for (int idx = t; idx < 1024; idx += 256) {
            int r = idx >> 4, c4 = (idx & 15) * 4;
            float4 v = *(const float4*)(ab + (size_t)r * 1024 + c4);
            As[(c4 + 0) * 64 + r] = v.x; As[(c4 + 1) * 64 + r] = v.y;
            As[(c4 + 2) * 64 + r] = v.z; As[(c4 + 3) * 64 + r] = v.w;
        }
        for (int idx = t; idx < 640; idx += 256) {
            int kk = idx / 10, c4 = idx - kk * 10;
            *(float4*)(Bs + kk * 40 + c4 * 4) =
                *(const float4*)(g_vcat + (size_t)(k0 + kk) * 480 + h * 40 + c4 * 4);
        }
        __syncthreads();
#pragma unroll 8
        for (int kk = 0; kk < 64; kk++) {
            float4 a4 = *(const float4*)(As + kk * 64 + ty * 4);
            int cb = tx * 3;
            float b0 = Bs[kk * 40 + ((cb + 0 < 40) ? cb + 0 : 39)];
            float b1 = Bs[kk * 40 + ((cb + 1 < 40) ? cb + 1 : 39)];
            float b2 = Bs[kk * 40 + ((cb + 2 < 40) ? cb + 2 : 39)];
            ffma2(acc[0][0], acc[1][0], a4.x, a4.y, b0, b0);
            ffma2(acc[2][0], acc[3][0], a4.z, a4.w, b0, b0);
            ffma2(acc[0][1], acc[1][1], a4.x, a4.y, b1, b1);
            ffma2(acc[2][1], acc[3][1], a4.z, a4.w, b1, b1);
            ffma2(acc[0][2], acc[1][2], a4.x, a4.y, b2, b2);
            ffma2(acc[2][2], acc[3][2], a4.z, a4.w, b2, b2);
        }
        __syncthreads();
    }
#pragma unroll
    for (int i = 0; i < 4; i++) {
        int q = q0 + ty * 4 + i;
#pragma unroll
        for (int j = 0; j < 3; j++) {
            int col = tx * 3 + j;
            if (col < 40) g_out6[((size_t)q * 12 + h) * 40 + col] = acc[i][j];
        }
    }
}

// ---------------- K6: inverse rigid, norms, feature assembly ----------------
__global__ void k_post(const float* __restrict__ rot, const float* __restrict__ trans) {
    int q = blockIdx.x;
    int t = threadIdx.x;   // 288
    float* f = g_feat + (size_t)q * 2112;
    const float* o6 = g_out6 + (size_t)q * 12 * 40;
    if (t < 96) {
        int h = t >> 3, p = t & 7;
        const float* g = o6 + h * 40 + 16 + p * 3;
        float g0 = g[0] - trans[q * 3 + 0];
        float g1 = g[1] - trans[q * 3 + 1];
        float g2 = g[2] - trans[q * 3 + 2];
        const float* R = rot + q * 9;
        float l0 = R[0] * g0 + R[3] * g1 + R[6] * g2;
        float l1 = R[1] * g0 + R[4] * g1 + R[7] * g2;
        float l2 = R[2] * g0 + R[5] * g1 + R[8] * g2;
        int idx = h * 8 + p;
        f[192 + idx] = l0;
        f[288 + idx] = l1;
        f[384 + idx] = l2;
        f[480 + idx] = sqrtf(fmaxf(l0 * l0 + l1 * l1 + l2 * l2, 1e-16f));
    } else if (t < 288) {
        int idx = t - 96;           // 0..191
        int h = idx >> 4, s = idx & 15;
        f[idx] = o6[h * 40 + s];
    }
}

// ---------------- K7: output GEMM 1024x384x2112 (32x64 tiles) ----------------
__global__ __launch_bounds__(256) void k_out(const float* __restrict__ wout,
                                             const float* __restrict__ bout,
                                             float* __restrict__ out) {
    __shared__ __align__(16) float As[16 * 32];
    __shared__ __align__(16) float Bs[16 * 64];
    int n0 = blockIdx.x * 64, m0 = blockIdx.y * 32;
    int t = threadIdx.x;
    int tx = t & 15, ty = t >> 4;
    float acc[2][4] = {};
    for (int kc = 0; kc < FEATD; kc += 16) {
#pragma unroll
        for (int r = 0; r < 2; r++) {
            int idx = t + r * 256;
            As[(idx & 15) * 32 + (idx >> 4)] =
                g_feat[(size_t)(m0 + (idx >> 4)) * FEATD + kc + (idx & 15)];
        }
#pragma unroll
        for (int r = 0; r < 4; r++) {
            int idx = t + r * 256;
            Bs[(idx >> 6) * 64 + (idx & 63)] =
                wout[(size_t)(kc + (idx >> 6)) * NCHd + n0 + (idx & 63)];
        }
        __syncthreads();
#pragma unroll
        for (int kk = 0; kk < 16; kk++) {
            float2 a2 = *(const float2*)(As + kk * 32 + ty * 2);
            float4 b4 = *(const float4*)(Bs + kk * 64 + tx * 4);
            ffma2(acc[0][0], acc[0][1], a2.x, a2.x, b4.x, b4.y);
            ffma2(acc[0][2], acc[0][3], a2.x, a2.x, b4.z, b4.w);
            ffma2(acc[1][0], acc[1][1], a2.y, a2.y, b4.x, b4.y);
            ffma2(acc[1][2], acc[1][3], a2.y, a2.y, b4.z, b4.w);
        }
        __syncthreads();
    }
#pragma unroll
    for (int i = 0; i < 2; i++) {
        int m = m0 + ty * 2 + i;
#pragma unroll
        for (int j = 0; j < 4; j++) {
            int n = n0 + tx * 4 + j;
            out[(size_t)m * NCHd + n] = acc[i][j] + bout[n];
        }
    }
}

// ---------------- launch ----------------
extern "C" void kernel_launch(void* const* d_in, const int* in_sizes, int n_in,
                              void* d_out, int out_size) {
    const float* inputs_1d = (const float*)d_in[0];
    const float* inputs_2d = (const float*)d_in[1];
    const float* mask      = (const float*)d_in[2];
    const float* rot       = (const float*)d_in[3];
    const float* trans     = (const float*)d_in[4];
    const float* rawpw     = (const float*)d_in[5];
    const float* wq_point  = (const float*)d_in[6];
    const float* bq_point  = (const float*)d_in[7];
    const float* wk_point  = (const float*)d_in[8];
    const float* bk_point  = (const float*)d_in[9];
    const float* wv_point  = (const float*)d_in[10];
    const float* bv_point  = (const float*)d_in[11];
    const float* wq_scalar = (const float*)d_in[12];
    const float* wk_scalar = (const float*)d_in[13];
    const float* wv_scalar = (const float*)d_in[14];
    const float* w2d       = (const float*)d_in[15];
    const float* b2d       = (const float*)d_in[16];
    const float* wout      = (const float*)d_in[17];
    const float* bout      = (const float*)d_in[18];
    float* out = (float*)d_out;

    const int smem_attn2d = (20480 + 192) * 4;   // 82688 B
    cudaFuncSetAttribute(k_attn2d, cudaFuncAttributeMaxDynamicSharedMemorySize, smem_attn2d);

    k_proj<<<dim3(PW / 64, Nn / 64), 256>>>(inputs_1d, wq_point, wk_point, wv_point,
                                            wq_scalar, wk_scalar, wv_scalar,
                                            bq_point, bk_point, bv_point);
    k_rotate<<<Nn, 256>>>(rot, trans);
    k_cheap<<<dim3(16, 16, 12), 256>>>(b2d, rawpw);
    k_attn2d<<<Nn, 256, smem_attn2d>>>(inputs_2d, w2d, mask);
    k_av<<<dim3(16, 12), 256>>>();
    k_post<<<Nn, 288>>>(rot, trans);
    k_out<<<dim3(NCHd / 64, Nn / 32), 256>>>(wout, bout, out);
}

// round 16
// speedup vs baseline: 1.8277x; 1.0750x over previous
#include <cuda_runtime.h>
#include <math.h>

#define Nn 1024
#define C1 384
#define C2 128
#define Hh 12
#define FEATD 2112
#define NCHd 384
#define PW 1152
#define PL2 2112   // pass-2 attn plane stride (floats), h-pair interleaved

typedef unsigned long long u64;

// ---------------- scratch (device globals; no runtime allocation) ----------------
static __device__ float g_P[Nn * PW];               // projections (1024x1152)
static __device__ float g_qpt[Nn * Hh * 12];        // global q points (n,h,p*3+i)
static __device__ float g_kpt[Nn * Hh * 12];
static __device__ float g_vcat[Nn * Hh * 40];       // packed V: [k][h][40] = scalar16|point24
static __device__ float g_qn[Nn * Hh];              // |q_pts|^2 per (n,h)
static __device__ float g_kn[Nn * Hh];
static __device__ float g_bufA[(size_t)Hh * Nn * Nn]; // (h,q,k): cheap logits, then attn
static __device__ float g_out6[Nn * Hh * 40];       // [v_scalar(16) | point(24)] per (q,h)
static __device__ float g_feat[Nn * FEATD];         // assembled feature rows

// bare packed fp32x2 FMA: acc stays in a 64-bit register pair across calls
__device__ __forceinline__ void ffma2u(u64& d, u64 a, u64 b) {
    asm("fma.rn.f32x2 %0, %1, %2, %0;" : "+l"(d) : "l"(a), "l"(b));
}
__device__ __forceinline__ u64 dup2(float x) {
    u64 r; asm("mov.b64 %0, {%1, %1};" : "=l"(r) : "f"(x)); return r;
}
__device__ __forceinline__ u64 pk2(float x, float y) {
    u64 r; asm("mov.b64 %0, {%1, %2};" : "=l"(r) : "f"(x), "f"(y)); return r;
}
__device__ __forceinline__ float2 up2(u64 v) {
    float2 f; asm("mov.b64 {%0, %1}, %2;" : "=f"(f.x), "=f"(f.y) : "l"(v)); return f;
}

// source of the assembled projection matrix column `col`, row `c`
__device__ __forceinline__ float wsrc(const float* __restrict__ wqp, const float* __restrict__ wkp,
                                      const float* __restrict__ wvp, const float* __restrict__ wqs,
                                      const float* __restrict__ wks, const float* __restrict__ wvs,
                                      int c, int col) {
    if (col < 144)  return wqp[c * 144 + col];
    if (col < 288)  return wkp[c * 144 + col - 144];
    if (col < 576)  return wvp[c * 288 + col - 288];
    if (col < 768)  return wqs[c * 192 + col - 576];
    if (col < 960)  return wks[c * 192 + col - 768];
    return wvs[c * 192 + col - 960];
}

// ---------------- K1: projection GEMM 1024x1152x384 ----------------
__global__ __launch_bounds__(256) void k_proj(const float* __restrict__ A,
                                              const float* __restrict__ wqp, const float* __restrict__ wkp,
                                              const float* __restrict__ wvp, const float* __restrict__ wqs,
                                              const float* __restrict__ wks, const float* __restrict__ wvs,
                                              const float* __restrict__ bqp, const float* __restrict__ bkp,
                                              const float* __restrict__ bvp) {
    __shared__ __align__(16) float As[16 * 64];
    __shared__ __align__(16) float Bs[16 * 64];
    int n0 = blockIdx.x * 64, m0 = blockIdx.y * 64;
    int t = threadIdx.x;
    int tx = t & 15, ty = t >> 4;
    u64 acc64[4][2] = {};
    for (int kc = 0; kc < C1; kc += 16) {
#pragma unroll
        for (int r = 0; r < 4; r++) {
            int idx = t + r * 256;
            As[(idx & 15) * 64 + (idx >> 4)] = A[(m0 + (idx >> 4)) * C1 + kc + (idx & 15)];
            Bs[(idx >> 6) * 64 + (idx & 63)] =
                wsrc(wqp, wkp, wvp, wqs, wks, wvs, kc + (idx >> 6), n0 + (idx & 63));
        }
        __syncthreads();
#pragma unroll
        for (int kk = 0; kk < 16; kk++) {
            float4 a4 = *(const float4*)(As + kk * 64 + ty * 4);
            float4 b4 = *(const float4*)(Bs + kk * 64 + tx * 4);
            u64 b01 = pk2(b4.x, b4.y), b23 = pk2(b4.z, b4.w);
            u64 a0 = dup2(a4.x), a1 = dup2(a4.y), a2 = dup2(a4.z), a3 = dup2(a4.w);
            ffma2u(acc64[0][0], a0, b01); ffma2u(acc64[0][1], a0, b23);
            ffma2u(acc64[1][0], a1, b01); ffma2u(acc64[1][1], a1, b23);
            ffma2u(acc64[2][0], a2, b01); ffma2u(acc64[2][1], a2, b23);
            ffma2u(acc64[3][0], a3, b01); ffma2u(acc64[3][1], a3, b23);
        }
        __syncthreads();
    }
#pragma unroll
    for (int i = 0; i < 4; i++) {
        int m = m0 + ty * 4 + i;
        float2 f0 = up2(acc64[i][0]), f1 = up2(acc64[i][1]);
        float av[4] = {f0.x, f0.y, f1.x, f1.y};
#pragma unroll
        for (int j = 0; j < 4; j++) {
            int n = n0 + tx * 4 + j;
            float b = 0.f;
            if (n < 144)      b = bqp[n];
            else if (n < 288) b = bkp[n - 144];
            else if (n < 576) b = bvp[n - 288];
            float s = (n >= 576 && n < 768) ? 0.25f : 1.f;   // q_scalar * sqrt(1/16)
            g_P[m * PW + n] = av[j] * s + b;
        }
    }
}

// ---------------- K2: rigid transform + point norms + packed V ----------------
__global__ void k_rotate(const float* __restrict__ rot, const float* __restrict__ trans) {
    int n = blockIdx.x;
    int t = threadIdx.x;
    __shared__ float R[9], T[3];
    if (t < 9) R[t] = rot[n * 9 + t];
    if (t < 3) T[t] = trans[n * 3 + t];
    __syncthreads();
    if (t < 192) {
        float l0, l1, l2;
        float* dst;
        if (t < 48) {
            int h = t >> 2, p = t & 3;
            const float* src = &g_P[n * PW + h * 12];
            l0 = src[p]; l1 = src[4 + p]; l2 = src[8 + p];
            dst = &g_qpt[(n * 12 + h) * 12 + p * 3];
        } else if (t < 96) {
            int u = t - 48; int h = u >> 2, p = u & 3;
            const float* src = &g_P[n * PW + 144 + h * 12];
            l0 = src[p]; l1 = src[4 + p]; l2 = src[8 + p];
            dst = &g_kpt[(n * 12 + h) * 12 + p * 3];
        } else {
            int u = t - 96; int h = u >> 3, p = u & 7;
            const float* src = &g_P[n * PW + 288 + h * 24];
            l0 = src[p]; l1 = src[8 + p]; l2 = src[16 + p];
            dst = &g_vcat[(size_t)n * 480 + h * 40 + 16 + p * 3];
        }
        dst[0] = R[0] * l0 + R[1] * l1 + R[2] * l2 + T[0];
        dst[1] = R[3] * l0 + R[4] * l1 + R[5] * l2 + T[1];
        dst[2] = R[6] * l0 + R[7] * l1 + R[8] * l2 + T[2];
    }
    if (t < 192) {
        int h = t >> 4, s = t & 15;
        g_vcat[(size_t)n * 480 + h * 40 + s] = g_P[n * PW + 960 + h * 16 + s];
    }
    __syncthreads();
    if (t < 24) {
        int h = t % 12;
        const float* p = (t < 12) ? &g_qpt[(n * 12 + h) * 12] : &g_kpt[(n * 12 + h) * 12];
        float s = 0.f;
#pragma unroll
        for (int d = 0; d < 12; d++) s += p[d] * p[d];
        if (t < 12) g_qn[n * 12 + h] = s;
        else        g_kn[n * 12 + h] = s;
    }
}

// ---------------- K3: cheap logits -> (h,q,k), 64x64 tiles ----------------
__global__ __launch_bounds__(256) void k_cheap(const float* __restrict__ b2d,
                                               const float* __restrict__ rawpw) {
    int k0 = blockIdx.x * 64, q0 = blockIdx.y * 64, h = blockIdx.z;
    __shared__ __align__(16) float qf[28 * 64];   // [c][r]
    __shared__ __align__(16) float kf[28 * 64];
    __shared__ float qn_[64], kn_[64];
    int t = threadIdx.x;
    float x = rawpw[h];
    float sp = (x > 20.f) ? x : log1pf(expf(x));
    float pw = sqrtf(1.f / 18.f) * sp;             // point_var = 4*9/2 = 18
    for (int u = t; u < 512; u += 256) {
        int r = u >> 3, g = u & 7;
        if (g < 4) {
            float4 v = *(const float4*)(&g_P[(size_t)(q0 + r) * PW + 576 + h * 16 + g * 4]);
            qf[(g * 4 + 0) * 64 + r] = v.x; qf[(g * 4 + 1) * 64 + r] = v.y;
            qf[(g * 4 + 2) * 64 + r] = v.z; qf[(g * 4 + 3) * 64 + r] = v.w;
            float4 w = *(const float4*)(&g_P[(size_t)(k0 + r) * PW + 768 + h * 16 + g * 4]);
            kf[(g * 4 + 0) * 64 + r] = w.x; kf[(g * 4 + 1) * 64 + r] = w.y;
            kf[(g * 4 + 2) * 64 + r] = w.z; kf[(g * 4 + 3) * 64 + r] = w.w;
        } else if (g < 7) {
            int pc = 16 + (g - 4) * 4;
            float4 v = *(const float4*)(&g_qpt[(((size_t)(q0 + r)) * 12 + h) * 12 + (g - 4) * 4]);
            qf[(pc + 0) * 64 + r] = v.x; qf[(pc + 1) * 64 + r] = v.y;
            qf[(pc + 2) * 64 + r] = v.z; qf[(pc + 3) * 64 + r] = v.w;
            float4 w = *(const float4*)(&g_kpt[(((size_t)(k0 + r)) * 12 + h) * 12 + (g - 4) * 4]);
            kf[(pc + 0) * 64 + r] = pw * w.x; kf[(pc + 1) * 64 + r] = pw * w.y;
            kf[(pc + 2) * 64 + r] = pw * w.z; kf[(pc + 3) * 64 + r] = pw * w.w;
        }
    }
    if (t < 64)            qn_[t] = 0.5f * pw * g_qn[(q0 + t) * 12 + h];
    else if (t < 128)      kn_[t - 64] = 0.5f * pw * g_kn[(k0 + t - 64) * 12 + h];
    __syncthreads();
    int tx = t & 15, ty = t >> 4;
    u64 acc64[4][2] = {};
#pragma unroll
    for (int c = 0; c < 28; c++) {
        float4 a4 = *(const float4*)(qf + c * 64 + ty * 4);
        float4 b4 = *(const float4*)(kf + c * 64 + tx * 4);
        u64 b01 = pk2(b4.x, b4.y), b23 = pk2(b4.z, b4.w);
        u64 a0 = dup2(a4.x), a1 = dup2(a4.y), a2 = dup2(a4.z), a3 = dup2(a4.w);
        ffma2u(acc64[0][0], a0, b01); ffma2u(acc64[0][1], a0, b23);
        ffma2u(acc64[1][0], a1, b01); ffma2u(acc64[1][1], a1, b23);
        ffma2u(acc64[2][0], a2, b01); ffma2u(acc64[2][1], a2, b23);
        ffma2u(acc64[3][0], a3, b01); ffma2u(acc64[3][1], a3, b23);
    }
    float bb = b2d[h];
#pragma unroll
    for (int i = 0; i < 4; i++) {
        int q = q0 + ty * 4 + i;
        float2 f0 = up2(acc64[i][0]), f1 = up2(acc64[i][1]);
        float av[4] = {f0.x, f0.y, f1.x, f1.y};
#pragma unroll
        for (int j = 0; j < 4; j++) {
            int k = k0 + tx * 4 + j;
            g_bufA[((size_t)h << 20) + (size_t)q * 1024 + k] =
                av[j] - qn_[ty * 4 + i] - kn_[tx * 4 + j] + bb;
        }
    }
}

// ---------------- K4: fused in2d projection + cheap + softmax + res_2d ----------------
__global__ __launch_bounds__(256, 2) void k_attn2d(const float* __restrict__ in2d,
                                                   const float* __restrict__ w2d,
                                                   const float* __restrict__ mask) {
    extern __shared__ float dsm[];
    float* s2d = dsm;                 // pass1: 20480-float staging; pass2: 6 h-pair planes [PL2]
    float* ws  = dsm + 20480;         // 192 floats (w2d chunk); reused as red[96]
    int q = blockIdx.x, t = threadIdx.x;
    u64 acc64[4][6] = {};
    int kb[4];
#pragma unroll
    for (int s = 0; s < 4; s++) {
        int k = t + s * 256;
        kb[s] = 40 * (k >> 1) + 4 * (k & 1);
    }
    const float* inrow = in2d + (size_t)q * 131072;
    for (int c0 = 0; c0 < 128; c0 += 16) {
        if (t < 192) ws[t] = w2d[c0 * 12 + t];
#pragma unroll
        for (int it = 0; it < 16; it++) {
            int idx = t + it * 256;
            int row = idx >> 2, cq = idx & 3;
            float4 v = *(const float4*)(inrow + row * 128 + c0 + cq * 4);
            *(float4*)(s2d + 40 * (row >> 1) + 4 * (row & 1) + 8 * cq) = v;
        }
        __syncthreads();
#pragma unroll
        for (int c4 = 0; c4 < 4; c4++) {
            float4 a[4];
#pragma unroll
            for (int s = 0; s < 4; s++)
                a[s] = *(const float4*)(s2d + kb[s] + 8 * c4);
#pragma unroll
            for (int cc = 0; cc < 4; cc++) {
                const ulonglong2* wp = (const ulonglong2*)(ws + (c4 * 4 + cc) * 12);
                ulonglong2 w01 = wp[0];
                ulonglong2 w23 = wp[1];
                ulonglong2 w45 = wp[2];
#pragma unroll
                for (int s = 0; s < 4; s++) {
                    float av = (cc == 0) ? a[s].x : (cc == 1) ? a[s].y
                             : (cc == 2) ? a[s].z : a[s].w;
                    u64 a2 = dup2(av);
                    ffma2u(acc64[s][0], a2, w01.x);
                    ffma2u(acc64[s][1], a2, w01.y);
                    ffma2u(acc64[s][2], a2, w23.x);
                    ffma2u(acc64[s][3], a2, w23.y);
                    ffma2u(acc64[s][4], a2, w45.x);
                    ffma2u(acc64[s][5], a2, w45.y);
                }
            }
        }
        __syncthreads();
    }
    // ---- unpack, add cheap, mask, scale ----
    float acc[4][12];
#pragma unroll
    for (int s = 0; s < 4; s++)
#pragma unroll
        for (int u = 0; u < 6; u++) {
            float2 f = up2(acc64[s][u]);
            acc[s][2 * u] = f.x; acc[s][2 * u + 1] = f.y;
        }
    float* red = ws;
    const float scale = 0.57735026918962576f;
    float mq = mask[q];
    float pen[4];
#pragma unroll
    for (int s = 0; s < 4; s++) pen[s] = -1e5f * (1.f - mq * mask[t + s * 256]);
#pragma unroll
    for (int h = 0; h < 12; h++) {
        size_t off = ((size_t)h << 20) + ((size_t)q << 10) + t;
#pragma unroll
        for (int s = 0; s < 4; s++) {
            float ch = g_bufA[off + s * 256];
            acc[s][h] = (acc[s][h] + ch + pen[s]) * scale;
        }
    }
    // ---- softmax over k (block-wide per h) ----
    int w = t >> 5, lane = t & 31;
#pragma unroll
    for (int h = 0; h < 12; h++) {
        float m = fmaxf(fmaxf(acc[0][h], acc[1][h]), fmaxf(acc[2][h], acc[3][h]));
#pragma unroll
        for (int s = 16; s; s >>= 1) m = fmaxf(m, __shfl_xor_sync(0xffffffffu, m, s));
        if (lane == 0) red[w * 12 + h] = m;
    }
    __syncthreads();
    float hm[12];
#pragma unroll
    for (int h = 0; h < 12; h++) {
        float m = red[h];
#pragma unroll
        for (int w2 = 1; w2 < 8; w2++) m = fmaxf(m, red[w2 * 12 + h]);
        hm[h] = m;
    }
    __syncthreads();
#pragma unroll
    for (int h = 0; h < 12; h++) {
        float s0 = 0.f;
#pragma unroll
        for (int s = 0; s < 4; s++) {
            acc[s][h] = __expf(acc[s][h] - hm[h]);
            s0 += acc[s][h];
        }
#pragma unroll
        for (int s = 16; s; s >>= 1) s0 += __shfl_xor_sync(0xffffffffu, s0, s);
        if (lane == 0) red[w * 12 + h] = s0;
    }
    __syncthreads();
    // normalize; write attn to g_bufA and to h-pair interleaved smem planes
#pragma unroll
    for (int h = 0; h < 12; h++) {
        float tot = red[h];
#pragma unroll
        for (int w2 = 1; w2 < 8; w2++) tot += red[w2 * 12 + h];
        float inv = 1.f / tot;
        size_t off = ((size_t)h << 20) + ((size_t)q << 10) + t;
#pragma unroll
        for (int s = 0; s < 4; s++) {
            acc[s][h] *= inv;
            g_bufA[off + s * 256] = acc[s][h];
        }
    }
#pragma unroll
    for (int s = 0; s < 4; s++) {
        int k = t + s * 256;
        int base = 2 * k + 8 * (k >> 7);
#pragma unroll
        for (int hp = 0; hp < 6; hp++)
            *(float2*)(s2d + hp * PL2 + base) = make_float2(acc[s][2 * hp], acc[s][2 * hp + 1]);
    }
    __syncthreads();
    // ---- pass 2: res_2d, thread = (col group of 4) x (k slice of 128), shuffle reduce ----
    {
        int g  = w * 4 + (lane & 3);       // 0..31 -> cols [4g, 4g+4)
        int sl = lane >> 2;                // 0..7  -> k in [128*sl, 128*sl+128)
        u64 r64[4][6] = {};
        const float* base = inrow + g * 4;
        for (int kt = 0; kt < 32; kt++) {
            int k0 = sl * 128 + kt * 4;
            float4 d0 = *(const float4*)(base + (size_t)(k0 + 0) * 128);
            float4 d1 = *(const float4*)(base + (size_t)(k0 + 1) * 128);
            float4 d2 = *(const float4*)(base + (size_t)(k0 + 2) * 128);
            float4 d3 = *(const float4*)(base + (size_t)(k0 + 3) * 128);
            u64 dd0x = dup2(d0.x), dd0y = dup2(d0.y), dd0z = dup2(d0.z), dd0w = dup2(d0.w);
            u64 dd1x = dup2(d1.x), dd1y = dup2(d1.y), dd1z = dup2(d1.z), dd1w = dup2(d1.w);
            u64 dd2x = dup2(d2.x), dd2y = dup2(d2.y), dd2z = dup2(d2.z), dd2w = dup2(d2.w);
            u64 dd3x = dup2(d3.x), dd3y = dup2(d3.y), dd3z = dup2(d3.z), dd3w = dup2(d3.w);
            int so = 264 * sl + 8 * kt;
#pragma unroll
            for (int hp = 0; hp < 6; hp++) {
                const ulonglong2* ap = (const ulonglong2*)(s2d + hp * PL2 + so);
                ulonglong2 p01 = ap[0];   // attn pairs for k0, k0+1
                ulonglong2 p23 = ap[1];   // k0+2, k0+3
                ffma2u(r64[0][hp], p01.x, dd0x); ffma2u(r64[1][hp], p01.x, dd0y);
                ffma2u(r64[2][hp], p01.x, dd0z); ffma2u(r64[3][hp], p01.x, dd0w);
                ffma2u(r64[0][hp], p01.y, dd1x); ffma2u(r64[1][hp], p01.y, dd1y);
                ffma2u(r64[2][hp], p01.y, dd1z); ffma2u(r64[3][hp], p01.y, dd1w);
                ffma2u(r64[0][hp], p23.x, dd2x); ffma2u(r64[1][hp], p23.x, dd2y);
                ffma2u(r64[2][hp], p23.x, dd2z); ffma2u(r64[3][hp], p23.x, dd2w);
                ffma2u(r64[0][hp], p23.y, dd3x); ffma2u(r64[1][hp], p23.y, dd3y);
                ffma2u(r64[2][hp], p23.y, dd3z); ffma2u(r64[3][hp], p23.y, dd3w);
            }
        }
        float r2[4][12];
#pragma unroll
        for (int c = 0; c < 4; c++)
#pragma unroll
            for (int hp = 0; hp < 6; hp++) {
                float2 f = up2(r64[c][hp]);
                r2[c][2 * hp] = f.x; r2[c][2 * hp + 1] = f.y;
            }
        // reduce over the 8 k-slices (lane bits 2..4)
#pragma unroll
        for (int c = 0; c < 4; c++)
#pragma unroll
            for (int u = 0; u < 12; u++) {
                float v = r2[c][u];
                v += __shfl_xor_sync(0xffffffffu, v, 4);
                v += __shfl_xor_sync(0xffffffffu, v, 8);
                v += __shfl_xor_sync(0xffffffffu, v, 16);
                r2[c][u] = v;
            }
        if (sl == 0) {
            float* f = g_feat + (size_t)q * 2112 + 576;
#pragma unroll
            for (int h = 0; h < 12; h++) {
                float4 v = make_float4(r2[0][h], r2[1][h], r2[2][h], r2[3][h]);
                *(float4*)(f + h * 128 + g * 4) = v;
            }
        }
    }
}

// ---------------- K5: AV (scalar + point values), per-head GEMM ----------------
__global__ __launch_bounds__(256) void k_av() {
    __shared__ __align__(16) float As[64 * 64];   // [kk][r]
    __shared__ __align__(16) float Bs[64 * 40 + 16];
    int h = blockIdx.y;
    int q0 = blockIdx.x * 64;
    int t = threadIdx.x;
    int tx = t & 15, ty = t >> 4;
    u64 acc64[2][3] = {};
    for (int k0 = 0; k0 < 1024; k0 += 64) {
        const float* ab = g_bufA + ((size_t)h << 20) + (size_t)q0 * 1024 + k0;
        for (int idx = t; idx < 1024; idx += 256) {
            int r = idx >> 4, c4 = (idx & 15) * 4;
            float4 v = *(const float4*)(ab + (size_t)r * 1024 + c4);
            As[(c4 + 0) * 64 + r] = v.x; As[(c4 + 1) * 64 + r] = v.y;
            As[(c4 + 2) * 64 + r] = v.z; As[(c4 + 3) * 64 + r] = v.w;
        }
        for (int idx = t; idx < 640; idx += 256) {
            int kk = idx / 10, c4 = idx - kk * 10;
            *(float4*)(Bs + kk * 40 + c4 * 4) =
                *(const float4*)(g_vcat + (size_t)(k0 + kk) * 480 + h * 40 + c4 * 4);
        }
        __syncthreads();
#pragma unroll 8
        for (int kk = 0; kk < 64; kk++) {
            float4 a4 = *(const float4*)(As + kk * 64 + ty * 4);
            u64 a01 = pk2(a4.x, a4.y), a23 = pk2(a4.z, a4.w);
            int cb = tx * 3;
            u64 bd0 = dup2(Bs[kk * 40 + ((cb + 0 < 40) ? cb + 0 : 39)]);
            u64 bd1 = dup2(Bs[kk * 40 + ((cb + 1 < 40) ? cb + 1 : 39)]);
            u64 bd2 = dup2(Bs[kk * 40 + ((cb + 2 < 40) ? cb + 2 : 39)]);
            ffma2u(acc64[0][0], a01, bd0); ffma2u(acc64[1][0], a23, bd0);
            ffma2u(acc64[0][1], a01, bd1); ffma2u(acc64[1][1], a23, bd1);
            ffma2u(acc64[0][2], a01, bd2); ffma2u(acc64[1][2], a23, bd2);
        }
        __syncthreads();
    }
#pragma unroll
    for (int j = 0; j < 3; j++) {
        int col = tx * 3 + j;
        float2 f0 = up2(acc64[0][j]), f1 = up2(acc64[1][j]);
        float av[4] = {f0.x, f0.y, f1.x, f1.y};
        if (col < 40) {
#pragma unroll
            for (int i = 0; i < 4; i++) {
                int q = q0 + ty * 4 + i;
                g_out6[((size_t)q * 12 + h) * 40 + col] = av[i];
            }
        }
    }
}

// ---------------- K6: inverse rigid, norms, feature assembly ----------------
__global__ void k_post(const float* __restrict__ rot, const float* __restrict__ trans) {
    int q = blockIdx.x;
    int t = threadIdx.x;   // 288
    float* f = g_feat + (size_t)q * 2112;
    const float* o6 = g_out6 + (size_t)q * 12 * 40;
    if (t < 96) {
        int h = t >> 3, p = t & 7;
        const float* g = o6 + h * 40 + 16 + p * 3;
        float g0 = g[0] - trans[q * 3 + 0];
        float g1 = g[1] - trans[q * 3 + 1];
        float g2 = g[2] - trans[q * 3 + 2];
        const float* R = rot + q * 9;
        float l0 = R[0] * g0 + R[3] * g1 + R[6] * g2;
        float l1 = R[1] * g0 + R[4] * g1 + R[7] * g2;
        float l2 = R[2] * g0 + R[5] * g1 + R[8] * g2;
        int idx = h * 8 + p;
        f[192 + idx] = l0;
        f[288 + idx] = l1;
        f[384 + idx] = l2;
        f[480 + idx] = sqrtf(fmaxf(l0 * l0 + l1 * l1 + l2 * l2, 1e-16f));
    } else if (t < 288) {
        int idx = t - 96;           // 0..191
        int h = idx >> 4, s = idx & 15;
        f[idx] = o6[h * 40 + s];
    }
}

// ---------------- K7: output GEMM 1024x384x2112 (32x64 tiles) ----------------
__global__ __launch_bounds__(256) void k_out(const float* __restrict__ wout,
                                             const float* __restrict__ bout,
                                             float* __restrict__ out) {
    __shared__ __align__(16) float As[16 * 32];
    __shared__ __align__(16) float Bs[16 * 64];
    int n0 = blockIdx.x * 64, m0 = blockIdx.y * 32;
    int t = threadIdx.x;
    int tx = t & 15, ty = t >> 4;
    u64 acc64[2][2] = {};
    for (int kc = 0; kc < FEATD; kc += 16) {
#pragma unroll
        for (int r = 0; r < 2; r++) {
            int idx = t + r * 256;
            As[(idx & 15) * 32 + (idx >> 4)] =
                g_feat[(size_t)(m0 + (idx >> 4)) * FEATD + kc + (idx & 15)];
        }
#pragma unroll
        for (int r = 0; r < 4; r++) {
            int idx = t + r * 256;
            Bs[(idx >> 6) * 64 + (idx & 63)] =
                wout[(size_t)(kc + (idx >> 6)) * NCHd + n0 + (idx & 63)];
        }
        __syncthreads();
#pragma unroll
        for (int kk = 0; kk < 16; kk++) {
            float2 a2 = *(const float2*)(As + kk * 32 + ty * 2);
            float4 b4 = *(const float4*)(Bs + kk * 64 + tx * 4);
            u64 b01 = pk2(b4.x, b4.y), b23 = pk2(b4.z, b4.w);
            u64 ad0 = dup2(a2.x), ad1 = dup2(a2.y);
            ffma2u(acc64[0][0], ad0, b01); ffma2u(acc64[0][1], ad0, b23);
            ffma2u(acc64[1][0], ad1, b01); ffma2u(acc64[1][1], ad1, b23);
        }
        __syncthreads();
    }
#pragma unroll
    for (int i = 0; i < 2; i++) {
        int m = m0 + ty * 2 + i;
        float2 f0 = up2(acc64[i][0]), f1 = up2(acc64[i][1]);
        float av[4] = {f0.x, f0.y, f1.x, f1.y};
#pragma unroll
        for (int j = 0; j < 4; j++) {
            int n = n0 + tx * 4 + j;
            out[(size_t)m * NCHd + n] = av[j] + bout[n];
        }
    }
}

// ---------------- launch ----------------
extern "C" void kernel_launch(void* const* d_in, const int* in_sizes, int n_in,
                              void* d_out, int out_size) {
    const float* inputs_1d = (const float*)d_in[0];
    const float* inputs_2d = (const float*)d_in[1];
    const float* mask      = (const float*)d_in[2];
    const float* rot       = (const float*)d_in[3];
    const float* trans     = (const float*)d_in[4];
    const float* rawpw     = (const float*)d_in[5];
    const float* wq_point  = (const float*)d_in[6];
    const float* bq_point  = (const float*)d_in[7];
    const float* wk_point  = (const float*)d_in[8];
    const float* bk_point  = (const float*)d_in[9];
    const float* wv_point  = (const float*)d_in[10];
    const float* bv_point  = (const float*)d_in[11];
    const float* wq_scalar = (const float*)d_in[12];
    const float* wk_scalar = (const float*)d_in[13];
    const float* wv_scalar = (const float*)d_in[14];
    const float* w2d       = (const float*)d_in[15];
    const float* b2d       = (const float*)d_in[16];
    const float* wout      = (const float*)d_in[17];
    const float* bout      = (const float*)d_in[18];
    float* out = (float*)d_out;

    const int smem_attn2d = (20480 + 192) * 4;   // 82688 B
    cudaFuncSetAttribute(k_attn2d, cudaFuncAttributeMaxDynamicSharedMemorySize, smem_attn2d);

    k_proj<<<dim3(PW / 64, Nn / 64), 256>>>(inputs_1d, wq_point, wk_point, wv_point,
                                            wq_scalar, wk_scalar, wv_scalar,
                                            bq_point, bk_point, bv_point);
    k_rotate<<<Nn, 256>>>(rot, trans);
    k_cheap<<<dim3(16, 16, 12), 256>>>(b2d, rawpw);
    k_attn2d<<<Nn, 256, smem_attn2d>>>(inputs_2d, w2d, mask);
    k_av<<<dim3(16, 12), 256>>>();
    k_post<<<Nn, 288>>>(rot, trans);
    k_out<<<dim3(NCHd / 64, Nn / 32), 256>>>(wout, bout, out);
}

// round 17
// speedup vs baseline: 1.9415x; 1.0623x over previous
#include <cuda_runtime.h>
#include <math.h>

#define Nn 1024
#define C1 384
#define C2 128
#define Hh 12
#define FEATD 2112
#define NCHd 384
#define PW 1152
#define PL2 2112   // pass-2 attn plane stride (floats), h-pair interleaved

typedef unsigned long long u64;

// ---------------- scratch (device globals; no runtime allocation) ----------------
static __device__ float g_P[Nn * PW];               // projections (1024x1152)
static __device__ float g_qpt[Nn * Hh * 12];        // global q points (n,h,p*3+i)
static __device__ float g_kpt[Nn * Hh * 12];
static __device__ float g_vcat[Nn * Hh * 40];       // packed V: [k][h][40] = scalar16|point24
static __device__ float g_qn[Nn * Hh];              // |q_pts|^2 per (n,h)
static __device__ float g_kn[Nn * Hh];
static __device__ float g_bufA[(size_t)Hh * Nn * Nn]; // (h,q,k): cheap logits, then attn
static __device__ float g_out6[Nn * Hh * 40];       // [v_scalar(16) | point(24)] per (q,h)
static __device__ float g_feat[Nn * FEATD];         // assembled feature rows

// bare packed fp32x2 FMA: acc stays in a 64-bit register pair across calls
__device__ __forceinline__ void ffma2u(u64& d, u64 a, u64 b) {
    asm("fma.rn.f32x2 %0, %1, %2, %0;" : "+l"(d) : "l"(a), "l"(b));
}
__device__ __forceinline__ u64 dup2(float x) {
    u64 r; asm("mov.b64 %0, {%1, %1};" : "=l"(r) : "f"(x)); return r;
}
__device__ __forceinline__ u64 pk2(float x, float y) {
    u64 r; asm("mov.b64 %0, {%1, %2};" : "=l"(r) : "f"(x), "f"(y)); return r;
}
__device__ __forceinline__ float2 up2(u64 v) {
    float2 f; asm("mov.b64 {%0, %1}, %2;" : "=f"(f.x), "=f"(f.y) : "l"(v)); return f;
}

// source of the assembled projection matrix column `col`, row `c`
__device__ __forceinline__ float wsrc(const float* __restrict__ wqp, const float* __restrict__ wkp,
                                      const float* __restrict__ wvp, const float* __restrict__ wqs,
                                      const float* __restrict__ wks, const float* __restrict__ wvs,
                                      int c, int col) {
    if (col < 144)  return wqp[c * 144 + col];
    if (col < 288)  return wkp[c * 144 + col - 144];
    if (col < 576)  return wvp[c * 288 + col - 288];
    if (col < 768)  return wqs[c * 192 + col - 576];
    if (col < 960)  return wks[c * 192 + col - 768];
    return wvs[c * 192 + col - 960];
}

// ---------------- K1: projection GEMM 1024x1152x384 ----------------
__global__ __launch_bounds__(256) void k_proj(const float* __restrict__ A,
                                              const float* __restrict__ wqp, const float* __restrict__ wkp,
                                              const float* __restrict__ wvp, const float* __restrict__ wqs,
                                              const float* __restrict__ wks, const float* __restrict__ wvs,
                                              const float* __restrict__ bqp, const float* __restrict__ bkp,
                                              const float* __restrict__ bvp) {
    __shared__ __align__(16) float As[16 * 68];   // [k][m], padded stride 68
    __shared__ __align__(16) float Bs[16 * 64];
    int n0 = blockIdx.x * 64, m0 = blockIdx.y * 64;
    int t = threadIdx.x;
    int tx = t & 15, ty = t >> 4;
    u64 acc64[4][2] = {};
    for (int kc = 0; kc < C1; kc += 16) {
#pragma unroll
        for (int r = 0; r < 4; r++) {
            int idx = t + r * 256;
            As[(idx & 15) * 68 + (idx >> 4)] = A[(m0 + (idx >> 4)) * C1 + kc + (idx & 15)];
            Bs[(idx >> 6) * 64 + (idx & 63)] =
                wsrc(wqp, wkp, wvp, wqs, wks, wvs, kc + (idx >> 6), n0 + (idx & 63));
        }
        __syncthreads();
#pragma unroll
        for (int kk = 0; kk < 16; kk++) {
            float4 a4 = *(const float4*)(As + kk * 68 + ty * 4);
            float4 b4 = *(const float4*)(Bs + kk * 64 + tx * 4);
            u64 b01 = pk2(b4.x, b4.y), b23 = pk2(b4.z, b4.w);
            u64 a0 = dup2(a4.x), a1 = dup2(a4.y), a2 = dup2(a4.z), a3 = dup2(a4.w);
            ffma2u(acc64[0][0], a0, b01); ffma2u(acc64[0][1], a0, b23);
            ffma2u(acc64[1][0], a1, b01); ffma2u(acc64[1][1], a1, b23);
            ffma2u(acc64[2][0], a2, b01); ffma2u(acc64[2][1], a2, b23);
            ffma2u(acc64[3][0], a3, b01); ffma2u(acc64[3][1], a3, b23);
        }
        __syncthreads();
    }
#pragma unroll
    for (int i = 0; i < 4; i++) {
        int m = m0 + ty * 4 + i;
        float2 f0 = up2(acc64[i][0]), f1 = up2(acc64[i][1]);
        float av[4] = {f0.x, f0.y, f1.x, f1.y};
#pragma unroll
        for (int j = 0; j < 4; j++) {
            int n = n0 + tx * 4 + j;
            float b = 0.f;
            if (n < 144)      b = bqp[n];
            else if (n < 288) b = bkp[n - 144];
            else if (n < 576) b = bvp[n - 288];
            float s = (n >= 576 && n < 768) ? 0.25f : 1.f;   // q_scalar * sqrt(1/16)
            g_P[m * PW + n] = av[j] * s + b;
        }
    }
}

// ---------------- K2: rigid transform + point norms + packed V ----------------
__global__ void k_rotate(const float* __restrict__ rot, const float* __restrict__ trans) {
    int n = blockIdx.x;
    int t = threadIdx.x;
    __shared__ float R[9], T[3];
    if (t < 9) R[t] = rot[n * 9 + t];
    if (t < 3) T[t] = trans[n * 3 + t];
    __syncthreads();
    if (t < 192) {
        float l0, l1, l2;
        float* dst;
        if (t < 48) {
            int h = t >> 2, p = t & 3;
            const float* src = &g_P[n * PW + h * 12];
            l0 = src[p]; l1 = src[4 + p]; l2 = src[8 + p];
            dst = &g_qpt[(n * 12 + h) * 12 + p * 3];
        } else if (t < 96) {
            int u = t - 48; int h = u >> 2, p = u & 3;
            const float* src = &g_P[n * PW + 144 + h * 12];
            l0 = src[p]; l1 = src[4 + p]; l2 = src[8 + p];
            dst = &g_kpt[(n * 12 + h) * 12 + p * 3];
        } else {
            int u = t - 96; int h = u >> 3, p = u & 7;
            const float* src = &g_P[n * PW + 288 + h * 24];
            l0 = src[p]; l1 = src[8 + p]; l2 = src[16 + p];
            dst = &g_vcat[(size_t)n * 480 + h * 40 + 16 + p * 3];
        }
        dst[0] = R[0] * l0 + R[1] * l1 + R[2] * l2 + T[0];
        dst[1] = R[3] * l0 + R[4] * l1 + R[5] * l2 + T[1];
        dst[2] = R[6] * l0 + R[7] * l1 + R[8] * l2 + T[2];
    }
    if (t < 192) {
        int h = t >> 4, s = t & 15;
        g_vcat[(size_t)n * 480 + h * 40 + s] = g_P[n * PW + 960 + h * 16 + s];
    }
    __syncthreads();
    if (t < 24) {
        int h = t % 12;
        const float* p = (t < 12) ? &g_qpt[(n * 12 + h) * 12] : &g_kpt[(n * 12 + h) * 12];
        float s = 0.f;
#pragma unroll
        for (int d = 0; d < 12; d++) s += p[d] * p[d];
        if (t < 12) g_qn[n * 12 + h] = s;
        else        g_kn[n * 12 + h] = s;
    }
}

// ---------------- K3: cheap logits -> (h,q,k), 64x64 tiles ----------------
__global__ __launch_bounds__(256) void k_cheap(const float* __restrict__ b2d,
                                               const float* __restrict__ rawpw) {
    int k0 = blockIdx.x * 64, q0 = blockIdx.y * 64, h = blockIdx.z;
    __shared__ __align__(16) float qf[28 * 68];   // [c][r], padded stride 68
    __shared__ __align__(16) float kf[28 * 68];
    __shared__ float qn_[64], kn_[64];
    int t = threadIdx.x;
    float x = rawpw[h];
    float sp = (x > 20.f) ? x : log1pf(expf(x));
    float pw = sqrtf(1.f / 18.f) * sp;             // point_var = 4*9/2 = 18
    for (int u = t; u < 512; u += 256) {
        int r = u >> 3, g = u & 7;
        if (g < 4) {
            float4 v = *(const float4*)(&g_P[(size_t)(q0 + r) * PW + 576 + h * 16 + g * 4]);
            qf[(g * 4 + 0) * 68 + r] = v.x; qf[(g * 4 + 1) * 68 + r] = v.y;
            qf[(g * 4 + 2) * 68 + r] = v.z; qf[(g * 4 + 3) * 68 + r] = v.w;
            float4 w = *(const float4*)(&g_P[(size_t)(k0 + r) * PW + 768 + h * 16 + g * 4]);
            kf[(g * 4 + 0) * 68 + r] = w.x; kf[(g * 4 + 1) * 68 + r] = w.y;
            kf[(g * 4 + 2) * 68 + r] = w.z; kf[(g * 4 + 3) * 68 + r] = w.w;
        } else if (g < 7) {
            int pc = 16 + (g - 4) * 4;
            float4 v = *(const float4*)(&g_qpt[(((size_t)(q0 + r)) * 12 + h) * 12 + (g - 4) * 4]);
            qf[(pc + 0) * 68 + r] = v.x; qf[(pc + 1) * 68 + r] = v.y;
            qf[(pc + 2) * 68 + r] = v.z; qf[(pc + 3) * 68 + r] = v.w;
            float4 w = *(const float4*)(&g_kpt[(((size_t)(k0 + r)) * 12 + h) * 12 + (g - 4) * 4]);
            kf[(pc + 0) * 68 + r] = pw * w.x; kf[(pc + 1) * 68 + r] = pw * w.y;
            kf[(pc + 2) * 68 + r] = pw * w.z; kf[(pc + 3) * 68 + r] = pw * w.w;
        }
    }
    if (t < 64)            qn_[t] = 0.5f * pw * g_qn[(q0 + t) * 12 + h];
    else if (t < 128)      kn_[t - 64] = 0.5f * pw * g_kn[(k0 + t - 64) * 12 + h];
    __syncthreads();
    int tx = t & 15, ty = t >> 4;
    u64 acc64[4][2] = {};
#pragma unroll
    for (int c = 0; c < 28; c++) {
        float4 a4 = *(const float4*)(qf + c * 68 + ty * 4);
        float4 b4 = *(const float4*)(kf + c * 68 + tx * 4);
        u64 b01 = pk2(b4.x, b4.y), b23 = pk2(b4.z, b4.w);
        u64 a0 = dup2(a4.x), a1 = dup2(a4.y), a2 = dup2(a4.z), a3 = dup2(a4.w);
        ffma2u(acc64[0][0], a0, b01); ffma2u(acc64[0][1], a0, b23);
        ffma2u(acc64[1][0], a1, b01); ffma2u(acc64[1][1], a1, b23);
        ffma2u(acc64[2][0], a2, b01); ffma2u(acc64[2][1], a2, b23);
        ffma2u(acc64[3][0], a3, b01); ffma2u(acc64[3][1], a3, b23);
    }
    float bb = b2d[h];
#pragma unroll
    for (int i = 0; i < 4; i++) {
        int q = q0 + ty * 4 + i;
        float2 f0 = up2(acc64[i][0]), f1 = up2(acc64[i][1]);
        float av[4] = {f0.x, f0.y, f1.x, f1.y};
#pragma unroll
        for (int j = 0; j < 4; j++) {
            int k = k0 + tx * 4 + j;
            g_bufA[((size_t)h << 20) + (size_t)q * 1024 + k] =
                av[j] - qn_[ty * 4 + i] - kn_[tx * 4 + j] + bb;
        }
    }
}

// ---------------- K4: fused in2d projection + cheap + softmax + res_2d ----------------
__global__ __launch_bounds__(256, 2) void k_attn2d(const float* __restrict__ in2d,
                                                   const float* __restrict__ w2d,
                                                   const float* __restrict__ mask) {
    extern __shared__ float dsm[];
    float* s2d = dsm;                 // pass1: 20480-float staging; pass2: 6 h-pair planes [PL2]
    float* ws  = dsm + 20480;         // 192 floats (w2d chunk); reused as red[96]
    int q = blockIdx.x, t = threadIdx.x;
    u64 acc64[4][6] = {};
    int kb[4];
#pragma unroll
    for (int s = 0; s < 4; s++) {
        int k = t + s * 256;
        kb[s] = 40 * (k >> 1) + 4 * (k & 1);
    }
    const float* inrow = in2d + (size_t)q * 131072;
    for (int c0 = 0; c0 < 128; c0 += 16) {
        if (t < 192) ws[t] = w2d[c0 * 12 + t];
#pragma unroll
        for (int it = 0; it < 16; it++) {
            int idx = t + it * 256;
            int row = idx >> 2, cq = idx & 3;
            float4 v = *(const float4*)(inrow + row * 128 + c0 + cq * 4);
            *(float4*)(s2d + 40 * (row >> 1) + 4 * (row & 1) + 8 * cq) = v;
        }
        __syncthreads();
#pragma unroll
        for (int c4 = 0; c4 < 4; c4++) {
            float4 a[4];
#pragma unroll
            for (int s = 0; s < 4; s++)
                a[s] = *(const float4*)(s2d + kb[s] + 8 * c4);
#pragma unroll
            for (int cc = 0; cc < 4; cc++) {
                const ulonglong2* wp = (const ulonglong2*)(ws + (c4 * 4 + cc) * 12);
                ulonglong2 w01 = wp[0];
                ulonglong2 w23 = wp[1];
                ulonglong2 w45 = wp[2];
#pragma unroll
                for (int s = 0; s < 4; s++) {
                    float av = (cc == 0) ? a[s].x : (cc == 1) ? a[s].y
                             : (cc == 2) ? a[s].z : a[s].w;
                    u64 a2 = dup2(av);
                    ffma2u(acc64[s][0], a2, w01.x);
                    ffma2u(acc64[s][1], a2, w01.y);
                    ffma2u(acc64[s][2], a2, w23.x);
                    ffma2u(acc64[s][3], a2, w23.y);
                    ffma2u(acc64[s][4], a2, w45.x);
                    ffma2u(acc64[s][5], a2, w45.y);
                }
            }
        }
        __syncthreads();
    }
    // ---- unpack, add cheap, mask, scale ----
    float acc[4][12];
#pragma unroll
    for (int s = 0; s < 4; s++)
#pragma unroll
        for (int u = 0; u < 6; u++) {
            float2 f = up2(acc64[s][u]);
            acc[s][2 * u] = f.x; acc[s][2 * u + 1] = f.y;
        }
    float* red = ws;
    const float scale = 0.57735026918962576f;
    float mq = mask[q];
    float pen[4];
#pragma unroll
    for (int s = 0; s < 4; s++) pen[s] = -1e5f * (1.f - mq * mask[t + s * 256]);
#pragma unroll
    for (int h = 0; h < 12; h++) {
        size_t off = ((size_t)h << 20) + ((size_t)q << 10) + t;
#pragma unroll
        for (int s = 0; s < 4; s++) {
            float ch = g_bufA[off + s * 256];
            acc[s][h] = (acc[s][h] + ch + pen[s]) * scale;
        }
    }
    // ---- softmax over k (block-wide per h) ----
    int w = t >> 5, lane = t & 31;
#pragma unroll
    for (int h = 0; h < 12; h++) {
        float m = fmaxf(fmaxf(acc[0][h], acc[1][h]), fmaxf(acc[2][h], acc[3][h]));
#pragma unroll
        for (int s = 16; s; s >>= 1) m = fmaxf(m, __shfl_xor_sync(0xffffffffu, m, s));
        if (lane == 0) red[w * 12 + h] = m;
    }
    __syncthreads();
    float hm[12];
#pragma unroll
    for (int h = 0; h < 12; h++) {
        float m = red[h];
#pragma unroll
        for (int w2 = 1; w2 < 8; w2++) m = fmaxf(m, red[w2 * 12 + h]);
        hm[h] = m;
    }
    __syncthreads();
#pragma unroll
    for (int h = 0; h < 12; h++) {
        float s0 = 0.f;
#pragma unroll
        for (int s = 0; s < 4; s++) {
            acc[s][h] = __expf(acc[s][h] - hm[h]);
            s0 += acc[s][h];
        }
#pragma unroll
        for (int s = 16; s; s >>= 1) s0 += __shfl_xor_sync(0xffffffffu, s0, s);
        if (lane == 0) red[w * 12 + h] = s0;
    }
    __syncthreads();
    // normalize; write attn to g_bufA and to h-pair interleaved smem planes
#pragma unroll
    for (int h = 0; h < 12; h++) {
        float tot = red[h];
#pragma unroll
        for (int w2 = 1; w2 < 8; w2++) tot += red[w2 * 12 + h];
        float inv = 1.f / tot;
        size_t off = ((size_t)h << 20) + ((size_t)q << 10) + t;
#pragma unroll
        for (int s = 0; s < 4; s++) {
            acc[s][h] *= inv;
            g_bufA[off + s * 256] = acc[s][h];
        }
    }
#pragma unroll
    for (int s = 0; s < 4; s++) {
        int k = t + s * 256;
        int base = 2 * k + 8 * (k >> 7);
#pragma unroll
        for (int hp = 0; hp < 6; hp++)
            *(float2*)(s2d + hp * PL2 + base) = make_float2(acc[s][2 * hp], acc[s][2 * hp + 1]);
    }
    __syncthreads();
    // ---- pass 2: res_2d, thread = (col group of 4) x (k slice of 128), shuffle reduce ----
    {
        int g  = w * 4 + (lane & 3);       // 0..31 -> cols [4g, 4g+4)
        int sl = lane >> 2;                // 0..7  -> k in [128*sl, 128*sl+128)
        u64 r64[4][6] = {};
        const float* base = inrow + g * 4;
        for (int kt = 0; kt < 32; kt++) {
            int k0 = sl * 128 + kt * 4;
            float4 d0 = *(const float4*)(base + (size_t)(k0 + 0) * 128);
            float4 d1 = *(const float4*)(base + (size_t)(k0 + 1) * 128);
            float4 d2 = *(const float4*)(base + (size_t)(k0 + 2) * 128);
            float4 d3 = *(const float4*)(base + (size_t)(k0 + 3) * 128);
            u64 dd0x = dup2(d0.x), dd0y = dup2(d0.y), dd0z = dup2(d0.z), dd0w = dup2(d0.w);
            u64 dd1x = dup2(d1.x), dd1y = dup2(d1.y), dd1z = dup2(d1.z), dd1w = dup2(d1.w);
            u64 dd2x = dup2(d2.x), dd2y = dup2(d2.y), dd2z = dup2(d2.z), dd2w = dup2(d2.w);
            u64 dd3x = dup2(d3.x), dd3y = dup2(d3.y), dd3z = dup2(d3.z), dd3w = dup2(d3.w);
            int so = 264 * sl + 8 * kt;
#pragma unroll
            for (int hp = 0; hp < 6; hp++) {
                const ulonglong2* ap = (const ulonglong2*)(s2d + hp * PL2 + so);
                ulonglong2 p01 = ap[0];   // attn pairs for k0, k0+1
                ulonglong2 p23 = ap[1];   // k0+2, k0+3
                ffma2u(r64[0][hp], p01.x, dd0x); ffma2u(r64[1][hp], p01.x, dd0y);
                ffma2u(r64[2][hp], p01.x, dd0z); ffma2u(r64[3][hp], p01.x, dd0w);
                ffma2u(r64[0][hp], p01.y, dd1x); ffma2u(r64[1][hp], p01.y, dd1y);
                ffma2u(r64[2][hp], p01.y, dd1z); ffma2u(r64[3][hp], p01.y, dd1w);
                ffma2u(r64[0][hp], p23.x, dd2x); ffma2u(r64[1][hp], p23.x, dd2y);
                ffma2u(r64[2][hp], p23.x, dd2z); ffma2u(r64[3][hp], p23.x, dd2w);
                ffma2u(r64[0][hp], p23.y, dd3x); ffma2u(r64[1][hp], p23.y, dd3y);
                ffma2u(r64[2][hp], p23.y, dd3z); ffma2u(r64[3][hp], p23.y, dd3w);
            }
        }
        float r2[4][12];
#pragma unroll
        for (int c = 0; c < 4; c++)
#pragma unroll
            for (int hp = 0; hp < 6; hp++) {
                float2 f = up2(r64[c][hp]);
                r2[c][2 * hp] = f.x; r2[c][2 * hp + 1] = f.y;
            }
        // reduce over the 8 k-slices (lane bits 2..4)
#pragma unroll
        for (int c = 0; c < 4; c++)
#pragma unroll
            for (int u = 0; u < 12; u++) {
                float v = r2[c][u];
                v += __shfl_xor_sync(0xffffffffu, v, 4);
                v += __shfl_xor_sync(0xffffffffu, v, 8);
                v += __shfl_xor_sync(0xffffffffu, v, 16);
                r2[c][u] = v;
            }
        if (sl == 0) {
            float* f = g_feat + (size_t)q * 2112 + 576;
#pragma unroll
            for (int h = 0; h < 12; h++) {
                float4 v = make_float4(r2[0][h], r2[1][h], r2[2][h], r2[3][h]);
                *(float4*)(f + h * 128 + g * 4) = v;
            }
        }
    }
}

// ---------------- K5: AV (scalar + point values), per-head GEMM ----------------
__global__ __launch_bounds__(256) void k_av() {
    __shared__ __align__(16) float As[64 * 68];   // [r][kk], padded stride 68 (no transpose)
    __shared__ __align__(16) float Bs[64 * 40 + 16];
    int h = blockIdx.y;
    int q0 = blockIdx.x * 64;
    int t = threadIdx.x;
    int tx = t & 15, ty = t >> 4;
    u64 acc64[2][3] = {};
    for (int k0 = 0; k0 < 1024; k0 += 64) {
        const float* ab = g_bufA + ((size_t)h << 20) + (size_t)q0 * 1024 + k0;
        for (int idx = t; idx < 1024; idx += 256) {
            int r = idx >> 4, c4 = (idx & 15) * 4;
            *(float4*)(As + r * 68 + c4) = *(const float4*)(ab + (size_t)r * 1024 + c4);
        }
        for (int idx = t; idx < 640; idx += 256) {
            int kk = idx / 10, c4 = idx - kk * 10;
            *(float4*)(Bs + kk * 40 + c4 * 4) =
                *(const float4*)(g_vcat + (size_t)(k0 + kk) * 480 + h * 40 + c4 * 4);
        }
        __syncthreads();
#pragma unroll 8
        for (int kk = 0; kk < 64; kk++) {
            float a0 = As[(ty * 4 + 0) * 68 + kk];
            float a1 = As[(ty * 4 + 1) * 68 + kk];
            float a2 = As[(ty * 4 + 2) * 68 + kk];
            float a3 = As[(ty * 4 + 3) * 68 + kk];
            u64 a01 = pk2(a0, a1), a23 = pk2(a2, a3);
            int cb = tx * 3;
            u64 bd0 = dup2(Bs[kk * 40 + ((cb + 0 < 40) ? cb + 0 : 39)]);
            u64 bd1 = dup2(Bs[kk * 40 + ((cb + 1 < 40) ? cb + 1 : 39)]);
            u64 bd2 = dup2(Bs[kk * 40 + ((cb + 2 < 40) ? cb + 2 : 39)]);
            ffma2u(acc64[0][0], a01, bd0); ffma2u(acc64[1][0], a23, bd0);
            ffma2u(acc64[0][1], a01, bd1); ffma2u(acc64[1][1], a23, bd1);
            ffma2u(acc64[0][2], a01, bd2); ffma2u(acc64[1][2], a23, bd2);
        }
        __syncthreads();
    }
#pragma unroll
    for (int j = 0; j < 3; j++) {
        int col = tx * 3 + j;
        float2 f0 = up2(acc64[0][j]), f1 = up2(acc64[1][j]);
        float av[4] = {f0.x, f0.y, f1.x, f1.y};
        if (col < 40) {
#pragma unroll
            for (int i = 0; i < 4; i++) {
                int q = q0 + ty * 4 + i;
                g_out6[((size_t)q * 12 + h) * 40 + col] = av[i];
            }
        }
    }
}

// ---------------- K6: inverse rigid, norms, feature assembly ----------------
__global__ void k_post(const float* __restrict__ rot, const float* __restrict__ trans) {
    int q = blockIdx.x;
    int t = threadIdx.x;   // 288
    float* f = g_feat + (size_t)q * 2112;
    const float* o6 = g_out6 + (size_t)q * 12 * 40;
    if (t < 96) {
        int h = t >> 3, p = t & 7;
        const float* g = o6 + h * 40 + 16 + p * 3;
        float g0 = g[0] - trans[q * 3 + 0];
        float g1 = g[1] - trans[q * 3 + 1];
        float g2 = g[2] - trans[q * 3 + 2];
        const float* R = rot + q * 9;
        float l0 = R[0] * g0 + R[3] * g1 + R[6] * g2;
        float l1 = R[1] * g0 + R[4] * g1 + R[7] * g2;
        float l2 = R[2] * g0 + R[5] * g1 + R[8] * g2;
        int idx = h * 8 + p;
        f[192 + idx] = l0;
        f[288 + idx] = l1;
        f[384 + idx] = l2;
        f[480 + idx] = sqrtf(fmaxf(l0 * l0 + l1 * l1 + l2 * l2, 1e-16f));
    } else if (t < 288) {
        int idx = t - 96;           // 0..191
        int h = idx >> 4, s = idx & 15;
        f[idx] = o6[h * 40 + s];
    }
}

// ---------------- K7: output GEMM 1024x384x2112 (32x64 tiles) ----------------
__global__ __launch_bounds__(256) void k_out(const float* __restrict__ wout,
                                             const float* __restrict__ bout,
                                             float* __restrict__ out) {
    __shared__ __align__(16) float As[16 * 36];   // [k][m], padded stride 36
    __shared__ __align__(16) float Bs[16 * 64];
    int n0 = blockIdx.x * 64, m0 = blockIdx.y * 32;
    int t = threadIdx.x;
    int tx = t & 15, ty = t >> 4;
    u64 acc64[2][2] = {};
    for (int kc = 0; kc < FEATD; kc += 16) {
#pragma unroll
        for (int r = 0; r < 2; r++) {
            int idx = t + r * 256;
            As[(idx & 15) * 36 + (idx >> 4)] =
                g_feat[(size_t)(m0 + (idx >> 4)) * FEATD + kc + (idx & 15)];
        }
#pragma unroll
        for (int r = 0; r < 4; r++) {
            int idx = t + r * 256;
            Bs[(idx >> 6) * 64 + (idx & 63)] =
                wout[(size_t)(kc + (idx >> 6)) * NCHd + n0 + (idx & 63)];
        }
        __syncthreads();
#pragma unroll
        for (int kk = 0; kk < 16; kk++) {
            float2 a2 = *(const float2*)(As + kk * 36 + ty * 2);
            float4 b4 = *(const float4*)(Bs + kk * 64 + tx * 4);
            u64 b01 = pk2(b4.x, b4.y), b23 = pk2(b4.z, b4.w);
            u64 ad0 = dup2(a2.x), ad1 = dup2(a2.y);
            ffma2u(acc64[0][0], ad0, b01); ffma2u(acc64[0][1], ad0, b23);
            ffma2u(acc64[1][0], ad1, b01); ffma2u(acc64[1][1], ad1, b23);
        }
        __syncthreads();
    }
#pragma unroll
    for (int i = 0; i < 2; i++) {
        int m = m0 + ty * 2 + i;
        float2 f0 = up2(acc64[i][0]), f1 = up2(acc64[i][1]);
        float av[4] = {f0.x, f0.y, f1.x, f1.y};
#pragma unroll
        for (int j = 0; j < 4; j++) {
            int n = n0 + tx * 4 + j;
            out[(size_t)m * NCHd + n] = av[j] + bout[n];
        }
    }
}

// ---------------- launch ----------------
extern "C" void kernel_launch(void* const* d_in, const int* in_sizes, int n_in,
                              void* d_out, int out_size) {
    const float* inputs_1d = (const float*)d_in[0];
    const float* inputs_2d = (const float*)d_in[1];
    const float* mask      = (const float*)d_in[2];
    const float* rot       = (const float*)d_in[3];
    const float* trans     = (const float*)d_in[4];
    const float* rawpw     = (const float*)d_in[5];
    const float* wq_point  = (const float*)d_in[6];
    const float* bq_point  = (const float*)d_in[7];
    const float* wk_point  = (const float*)d_in[8];
    const float* bk_point  = (const float*)d_in[9];
    const float* wv_point  = (const float*)d_in[10];
    const float* bv_point  = (const float*)d_in[11];
    const float* wq_scalar = (const float*)d_in[12];
    const float* wk_scalar = (const float*)d_in[13];
    const float* wv_scalar = (const float*)d_in[14];
    const float* w2d       = (const float*)d_in[15];
    const float* b2d       = (const float*)d_in[16];
    const float* wout      = (const float*)d_in[17];
    const float* bout      = (const float*)d_in[18];
    float* out = (float*)d_out;

    const int smem_attn2d = (20480 + 192) * 4;   // 82688 B
    cudaFuncSetAttribute(k_attn2d, cudaFuncAttributeMaxDynamicSharedMemorySize, smem_attn2d);

    k_proj<<<dim3(PW / 64, Nn / 64), 256>>>(inputs_1d, wq_point, wk_point, wv_point,
                                            wq_scalar, wk_scalar, wv_scalar,
                                            bq_point, bk_point, bv_point);
    k_rotate<<<Nn, 256>>>(rot, trans);
    k_cheap<<<dim3(16, 16, 12), 256>>>(b2d, rawpw);
    k_attn2d<<<Nn, 256, smem_attn2d>>>(inputs_2d, w2d, mask);
    k_av<<<dim3(16, 12), 256>>>();
    k_post<<<Nn, 288>>>(rot, trans);
    k_out<<<dim3(NCHd / 64, Nn / 32), 256>>>(wout, bout, out);
}